// round 1
// baseline (speedup 1.0000x reference)
#include <cuda_runtime.h>
#include <math.h>

// ---------------- problem constants ----------------
#define L_SEQ   4096
#define DMODEL  1024
#define DINNER  2048
#define EDIM    (2*DINNER)   // 4096
#define BATCH   2
#define NFFT    8192
#define NHALF   (NFFT/2)     // 4096
#define LOG2N   13

// ---------------- scratch (device globals; allocation-free launch) ----------------
__device__ float  g_xz[(unsigned long long)BATCH * EDIM * L_SEQ];     // [b][e][l], 134MB
__device__ float  g_y [(unsigned long long)BATCH * DINNER * L_SEQ];   // [b][h][l],  67MB
__device__ float2 g_Hf[(unsigned long long)DINNER * NFFT];            // kernel spectra, 134MB
__device__ float2 g_tw[NHALF];                                        // exp(-2*pi*i*k/N)

// ---------------- twiddle table ----------------
__global__ void twiddle_kernel() {
    int k = blockIdx.x * blockDim.x + threadIdx.x;
    if (k < NHALF) {
        float s, c;
        sincospif(2.0f * (float)k / (float)NFFT, &s, &c); // angle = 2*pi*k/N
        g_tw[k] = make_float2(c, -s);
    }
}

// ---------------- FFT core: Stockham radix-2, 512 threads, N=8192 ----------------
__device__ __forceinline__ float2 cmul(float2 a, float2 b) {
    return make_float2(fmaf(a.x, b.x, -a.y * b.y), fmaf(a.x, b.y, a.y * b.x));
}

// data starts in src buffer; returns pointer holding the result (natural order).
// sgn = +1 forward, -1 inverse (unscaled).
__device__ float2* fft8192(float2* srcb, float2* dstb, const float2* __restrict__ tw,
                           float sgn, int tid)
{
    float2* src = srcb;
    float2* dst = dstb;
    int s = 1;
    #pragma unroll 1
    for (int st = 0; st < LOG2N; ++st) {
        int sm1 = s - 1;
        #pragma unroll
        for (int r = 0; r < NHALF / 512; ++r) {
            int i = tid + r * 512;
            int q = i & sm1;
            float2 a = src[i];
            float2 b = src[i + NHALF];
            float2 w = tw[i - q];          // index = p*s = i & ~(s-1)
            w.y *= sgn;
            float2 sum = make_float2(a.x + b.x, a.y + b.y);
            float2 dif = make_float2(a.x - b.x, a.y - b.y);
            int o = 2 * i - q;             // q + s*(2p)
            dst[o]     = sum;
            dst[o + s] = cmul(dif, w);
        }
        __syncthreads();
        float2* t = src; src = dst; dst = t;
        s <<= 1;
    }
    return src;
}

// ---------------- kernel spectrum: Hf[h] = FFT(pad(k_ssm[h])) ----------------
#define SMEM_FFTK (2 * NFFT * (int)sizeof(float2) + NHALF * (int)sizeof(float2))
__global__ void __launch_bounds__(512) fftk_kernel(const float* __restrict__ k_ssm)
{
    extern __shared__ float smem_raw[];
    float2* buf0 = (float2*)smem_raw;
    float2* buf1 = buf0 + NFFT;
    float2* tws  = buf1 + NFFT;
    const int h = blockIdx.x;
    const int tid = threadIdx.x;

    for (int i = tid; i < NHALF; i += 512) tws[i] = g_tw[i];
    const float* kr = k_ssm + (size_t)h * L_SEQ;
    for (int i = tid; i < L_SEQ; i += 512)      buf0[i] = make_float2(kr[i], 0.f);
    for (int i = tid + L_SEQ; i < NFFT; i += 512) buf0[i] = make_float2(0.f, 0.f);
    __syncthreads();

    float2* res = fft8192(buf0, buf1, tws, 1.0f, tid);
    float2* out = g_Hf + (size_t)h * NFFT;
    for (int i = tid; i < NFFT; i += 512) out[i] = res[i];
}

// ---------------- fused: conv4+SiLU -> FFT conv -> D_skip -> *SiLU(z) ----------------
#define SMEM_CONV (SMEM_FFTK + L_SEQ * (int)sizeof(float))
__global__ void __launch_bounds__(512) convfft_kernel(const float* __restrict__ conv_w,
                                                      const float* __restrict__ conv_b,
                                                      const float* __restrict__ D_skip)
{
    extern __shared__ float smem_raw[];
    float2* buf0 = (float2*)smem_raw;
    float2* buf1 = buf0 + NFFT;
    float2* tws  = buf1 + NFFT;
    float*  xs   = (float*)(tws + NHALF);

    const int bh = blockIdx.x;
    const int b  = bh >> 11;            // DINNER = 2048
    const int h  = bh & (DINNER - 1);
    const int tid = threadIdx.x;

    for (int i = tid; i < NHALF; i += 512) tws[i] = g_tw[i];

    const float w0 = conv_w[h * 4 + 0];
    const float w1 = conv_w[h * 4 + 1];
    const float w2 = conv_w[h * 4 + 2];
    const float w3 = conv_w[h * 4 + 3];
    const float cb = conv_b[h];

    const float* gx = g_xz + ((size_t)(b * EDIM) + h) * L_SEQ;
    for (int l = tid; l < L_SEQ; l += 512) {
        float acc = fmaf(w3, gx[l], cb);
        if (l >= 1) acc = fmaf(w2, gx[l - 1], acc);
        if (l >= 2) acc = fmaf(w1, gx[l - 2], acc);
        if (l >= 3) acc = fmaf(w0, gx[l - 3], acc);
        float v = acc / (1.0f + expf(-acc));   // silu
        xs[l] = v;
        buf0[l] = make_float2(v, 0.f);
    }
    for (int i = tid + L_SEQ; i < NFFT; i += 512) buf0[i] = make_float2(0.f, 0.f);
    __syncthreads();

    float2* r1 = fft8192(buf0, buf1, tws, 1.0f, tid);   // lands in buf1

    const float2* __restrict__ Hrow = g_Hf + (size_t)h * NFFT;
    for (int i = tid; i < NFFT; i += 512) r1[i] = cmul(r1[i], Hrow[i]);
    __syncthreads();

    float2* other = (r1 == buf0) ? buf1 : buf0;
    float2* r2 = fft8192(r1, other, tws, -1.0f, tid);   // lands in buf0

    const float dsk = D_skip[h];
    const float* gz = g_xz + ((size_t)(b * EDIM) + DINNER + h) * L_SEQ;
    float*       gy = g_y  + ((size_t)(b * DINNER) + h) * L_SEQ;
    const float invn = 1.0f / (float)NFFT;
    for (int l = tid; l < L_SEQ; l += 512) {
        float yv = fmaf(r2[l].x, invn, dsk * xs[l]);
        float zv = gz[l];
        float sz = zv / (1.0f + expf(-zv));
        gy[l] = yv * sz;
    }
}

// ---------------- GEMM1: xz[b][e][l] = sum_d W_in[e][d] * hs[b][l][d] ----------------
// NT sgemm: A = W_in (4096x1024, K-contig), B = hs_b (4096x1024, K-contig), C row-major.
__global__ void __launch_bounds__(256) gemm1_kernel(const float* __restrict__ hs,
                                                    const float* __restrict__ Win)
{
    __shared__ float As[16][128];
    __shared__ float Bs[16][128];
    const int b  = blockIdx.z;
    const int m0 = blockIdx.y * 128;   // e
    const int n0 = blockIdx.x * 128;   // l
    const int tid = threadIdx.x;
    const int tx = tid & 15, ty = tid >> 4;

    const float* A = Win;
    const float* B = hs + (size_t)b * L_SEQ * DMODEL;

    float acc[8][8];
    #pragma unroll
    for (int i = 0; i < 8; ++i)
        #pragma unroll
        for (int j = 0; j < 8; ++j) acc[i][j] = 0.f;

    const int lrow = tid >> 2;          // 0..63
    const int lkg  = (tid & 3) << 2;    // 0,4,8,12

    for (int k0 = 0; k0 < DMODEL; k0 += 16) {
        #pragma unroll
        for (int t = 0; t < 2; ++t) {
            int row = lrow + t * 64;
            float4 va = *(const float4*)(A + (size_t)(m0 + row) * DMODEL + k0 + lkg);
            As[lkg + 0][row] = va.x; As[lkg + 1][row] = va.y;
            As[lkg + 2][row] = va.z; As[lkg + 3][row] = va.w;
            float4 vb = *(const float4*)(B + (size_t)(n0 + row) * DMODEL + k0 + lkg);
            Bs[lkg + 0][row] = vb.x; Bs[lkg + 1][row] = vb.y;
            Bs[lkg + 2][row] = vb.z; Bs[lkg + 3][row] = vb.w;
        }
        __syncthreads();
        #pragma unroll
        for (int k = 0; k < 16; ++k) {
            float a[8], bb[8];
            *(float4*)&a[0]  = *(const float4*)&As[k][ty * 8];
            *(float4*)&a[4]  = *(const float4*)&As[k][ty * 8 + 4];
            *(float4*)&bb[0] = *(const float4*)&Bs[k][tx * 8];
            *(float4*)&bb[4] = *(const float4*)&Bs[k][tx * 8 + 4];
            #pragma unroll
            for (int i = 0; i < 8; ++i)
                #pragma unroll
                for (int j = 0; j < 8; ++j)
                    acc[i][j] = fmaf(a[i], bb[j], acc[i][j]);
        }
        __syncthreads();
    }

    float* C = g_xz + (size_t)b * EDIM * L_SEQ;
    #pragma unroll
    for (int i = 0; i < 8; ++i) {
        float* cp = C + (size_t)(m0 + ty * 8 + i) * L_SEQ + n0 + tx * 8;
        *(float4*)cp       = make_float4(acc[i][0], acc[i][1], acc[i][2], acc[i][3]);
        *(float4*)(cp + 4) = make_float4(acc[i][4], acc[i][5], acc[i][6], acc[i][7]);
    }
}

// ---------------- GEMM2: out[b][l][d] = sum_h y[b][h][l] * W_out[d][h] ----------------
__global__ void __launch_bounds__(256) gemm2_kernel(const float* __restrict__ Wout,
                                                    float* __restrict__ out)
{
    __shared__ float As[16][128];   // [h][l]
    __shared__ float Bs[16][128];   // [h][d]
    const int b  = blockIdx.z;
    const int m0 = blockIdx.y * 128;   // l
    const int n0 = blockIdx.x * 128;   // d
    const int tid = threadIdx.x;
    const int tx = tid & 15, ty = tid >> 4;

    const float* Y = g_y + (size_t)b * DINNER * L_SEQ;

    float acc[8][8];
    #pragma unroll
    for (int i = 0; i < 8; ++i)
        #pragma unroll
        for (int j = 0; j < 8; ++j) acc[i][j] = 0.f;

    for (int k0 = 0; k0 < DINNER; k0 += 16) {
        #pragma unroll
        for (int t = 0; t < 2; ++t) {
            int idx = tid + t * 256;            // 0..511
            int kk  = idx >> 5;                 // 0..15
            int mg  = (idx & 31) << 2;          // 0..124
            float4 v = *(const float4*)(Y + (size_t)(k0 + kk) * L_SEQ + m0 + mg);
            *(float4*)&As[kk][mg] = v;
            int row = idx >> 2;                 // d: 0..127
            int kg  = (idx & 3) << 2;           // 0,4,8,12
            float4 wv = *(const float4*)(Wout + (size_t)(n0 + row) * DINNER + k0 + kg);
            Bs[kg + 0][row] = wv.x; Bs[kg + 1][row] = wv.y;
            Bs[kg + 2][row] = wv.z; Bs[kg + 3][row] = wv.w;
        }
        __syncthreads();
        #pragma unroll
        for (int k = 0; k < 16; ++k) {
            float a[8], bb[8];
            *(float4*)&a[0]  = *(const float4*)&As[k][ty * 8];
            *(float4*)&a[4]  = *(const float4*)&As[k][ty * 8 + 4];
            *(float4*)&bb[0] = *(const float4*)&Bs[k][tx * 8];
            *(float4*)&bb[4] = *(const float4*)&Bs[k][tx * 8 + 4];
            #pragma unroll
            for (int i = 0; i < 8; ++i)
                #pragma unroll
                for (int j = 0; j < 8; ++j)
                    acc[i][j] = fmaf(a[i], bb[j], acc[i][j]);
        }
        __syncthreads();
    }

    float* C = out + (size_t)b * L_SEQ * DMODEL;
    #pragma unroll
    for (int i = 0; i < 8; ++i) {
        float* cp = C + (size_t)(m0 + ty * 8 + i) * DMODEL + n0 + tx * 8;
        *(float4*)cp       = make_float4(acc[i][0], acc[i][1], acc[i][2], acc[i][3]);
        *(float4*)(cp + 4) = make_float4(acc[i][4], acc[i][5], acc[i][6], acc[i][7]);
    }
}

// ---------------- launch ----------------
extern "C" void kernel_launch(void* const* d_in, const int* in_sizes, int n_in,
                              void* d_out, int out_size)
{
    (void)in_sizes; (void)n_in; (void)out_size;
    const float* hs     = (const float*)d_in[0];
    const float* W_in   = (const float*)d_in[1];
    const float* conv_w = (const float*)d_in[2];
    const float* conv_b = (const float*)d_in[3];
    const float* k_ssm  = (const float*)d_in[4];
    const float* D_skip = (const float*)d_in[5];
    const float* W_out  = (const float*)d_in[6];
    float* out = (float*)d_out;

    cudaFuncSetAttribute(fftk_kernel,    cudaFuncAttributeMaxDynamicSharedMemorySize, SMEM_FFTK);
    cudaFuncSetAttribute(convfft_kernel, cudaFuncAttributeMaxDynamicSharedMemorySize, SMEM_CONV);

    twiddle_kernel<<<NHALF / 512, 512>>>();
    gemm1_kernel<<<dim3(32, 32, 2), 256>>>(hs, W_in);
    fftk_kernel<<<DINNER, 512, SMEM_FFTK>>>(k_ssm);
    convfft_kernel<<<BATCH * DINNER, 512, SMEM_CONV>>>(conv_w, conv_b, D_skip);
    gemm2_kernel<<<dim3(DMODEL / 128, L_SEQ / 128, 2), 256>>>(W_out, out);
}

// round 2
// speedup vs baseline: 1.1321x; 1.1321x over previous
#include <cuda_runtime.h>
#include <math.h>

// ---------------- problem constants ----------------
#define L_SEQ   4096
#define DMODEL  1024
#define DINNER  2048
#define EDIM    (2*DINNER)   // 4096
#define BATCH   2
#define NFFT    8192
#define NQ      (NFFT/4)     // 2048
#define NHALF   (NFFT/2)     // 4096

// ---------------- scratch (device globals; allocation-free launch) ----------------
__device__ float  g_xz[(unsigned long long)BATCH * EDIM * L_SEQ];     // [b][e][l]
__device__ float  g_y [(unsigned long long)BATCH * DINNER * L_SEQ];   // [b][h][l]
__device__ float2 g_Hf[(unsigned long long)DINNER * NFFT];            // kernel spectra
__device__ float2 g_tw[NHALF];                                        // exp(-2*pi*i*k/N)

// ---------------- twiddle table ----------------
__global__ void twiddle_kernel() {
    int k = blockIdx.x * blockDim.x + threadIdx.x;
    if (k < NHALF) {
        float s, c;
        sincospif(2.0f * (float)k / (float)NFFT, &s, &c); // angle = 2*pi*k/N
        g_tw[k] = make_float2(c, -s);
    }
}

// ---------------- complex helpers ----------------
__device__ __forceinline__ float2 cmul(float2 a, float2 b) {
    return make_float2(fmaf(a.x, b.x, -a.y * b.y), fmaf(a.x, b.y, a.y * b.x));
}
__device__ __forceinline__ float2 cadd(float2 a, float2 b) { return make_float2(a.x + b.x, a.y + b.y); }
__device__ __forceinline__ float2 csub(float2 a, float2 b) { return make_float2(a.x - b.x, a.y - b.y); }

// ---------------- FFT core: Stockham, 6 radix-4 stages + 1 radix-2, 512 thr ----------
// sgn = +1 forward (W^-), -1 inverse (unscaled, W^+). Result in returned buffer,
// natural order.
__device__ float2* fft8192_r4(float2* src, float2* dst, const float2* __restrict__ tw,
                              float sgn, int tid)
{
    int s = 1;
    #pragma unroll 1
    for (int st = 0; st < 6; ++st) {
        int sm1 = s - 1;
        #pragma unroll
        for (int r = 0; r < NQ / 512; ++r) {        // 4 iters
            int i  = tid + r * 512;
            int q  = i & sm1;
            int ps = i - q;                          // s * p'
            float2 x0 = src[i];
            float2 x2 = src[i + NQ];
            float2 x1 = src[i + NHALF];
            float2 x3 = src[i + NQ + NHALF];
            float2 w1 = tw[ps];
            float2 w2 = tw[2 * ps];
            w1.y *= sgn; w2.y *= sgn;
            float2 w3 = cmul(w1, w2);
            float2 u0 = cadd(x0, x1);
            float2 d0 = csub(x0, x1);
            float2 u1 = cadd(x2, x3);
            float2 d1 = csub(x2, x3);
            // sd1 = (-i*sgn) * d1  : forward -i, inverse +i
            float2 sd1 = make_float2(sgn * d1.y, -sgn * d1.x);
            float2 y0 = cadd(u0, u1);
            float2 y2 = cmul(csub(u0, u1), w2);
            float2 y1 = cmul(cadd(d0, sd1), w1);
            float2 y3 = cmul(csub(d0, sd1), w3);
            int o = q + 4 * ps;                      // q + 4*s*p'
            dst[o]         = y0;
            dst[o + s]     = y1;
            dst[o + 2 * s] = y2;
            dst[o + 3 * s] = y3;
        }
        __syncthreads();
        float2* t = src; src = dst; dst = t;
        s <<= 2;
    }
    // final radix-2 stage, s = N/2: q = i, p = 0 -> twiddle-free
    #pragma unroll
    for (int r = 0; r < NHALF / 512; ++r) {          // 8 iters
        int i = tid + r * 512;
        float2 a = src[i];
        float2 b = src[i + NHALF];
        dst[i]         = cadd(a, b);
        dst[i + NHALF] = csub(a, b);
    }
    __syncthreads();
    return dst;
}

// ---------------- kernel spectrum: Hf[h] = FFT(pad(k_ssm[h])) ----------------
#define SMEM_FFTK ((2 * NFFT + NHALF) * (int)sizeof(float2))
__global__ void __launch_bounds__(512) fftk_kernel(const float* __restrict__ k_ssm)
{
    extern __shared__ float smem_raw[];
    float2* buf0 = (float2*)smem_raw;
    float2* buf1 = buf0 + NFFT;
    float2* tws  = buf1 + NFFT;
    const int h = blockIdx.x;
    const int tid = threadIdx.x;

    for (int i = tid; i < NHALF; i += 512) tws[i] = g_tw[i];
    const float* kr = k_ssm + (size_t)h * L_SEQ;
    for (int i = tid; i < L_SEQ; i += 512)        buf0[i] = make_float2(kr[i], 0.f);
    for (int i = tid + L_SEQ; i < NFFT; i += 512) buf0[i] = make_float2(0.f, 0.f);
    __syncthreads();

    float2* res = fft8192_r4(buf0, buf1, tws, 1.0f, tid);
    float2* out = g_Hf + (size_t)h * NFFT;
    for (int i = tid; i < NFFT; i += 512) out[i] = res[i];
}

// ------- fused: conv4+SiLU -> batch-packed FFT conv -> D_skip -> *SiLU(z) -------
// One CTA per channel h. Batches b=0,1 packed as Re/Im of one complex sequence:
// IFFT( FFT(x0 + i*x1) * H ) = conv(x0,k) + i*conv(x1,k)  (real kernel, linearity).
#define SMEM_CONV ((2 * NFFT + NHALF + L_SEQ) * (int)sizeof(float2))
__global__ void __launch_bounds__(512) convfft_kernel(const float* __restrict__ conv_w,
                                                      const float* __restrict__ conv_b,
                                                      const float* __restrict__ D_skip)
{
    extern __shared__ float smem_raw[];
    float2* buf0 = (float2*)smem_raw;
    float2* buf1 = buf0 + NFFT;
    float2* tws  = buf1 + NFFT;
    float2* xs   = tws + NHALF;          // conv+SiLU outputs (b0 in .x, b1 in .y)

    const int h   = blockIdx.x;
    const int tid = threadIdx.x;

    for (int i = tid; i < NHALF; i += 512) tws[i] = g_tw[i];

    const float w0 = conv_w[h * 4 + 0];
    const float w1 = conv_w[h * 4 + 1];
    const float w2 = conv_w[h * 4 + 2];
    const float w3 = conv_w[h * 4 + 3];
    const float cb = conv_b[h];

    const float* gx0 = g_xz + (size_t)h * L_SEQ;
    const float* gx1 = g_xz + ((size_t)EDIM + h) * L_SEQ;
    for (int l = tid; l < L_SEQ; l += 512) {
        float a0 = fmaf(w3, gx0[l], cb);
        float a1 = fmaf(w3, gx1[l], cb);
        if (l >= 1) { a0 = fmaf(w2, gx0[l - 1], a0); a1 = fmaf(w2, gx1[l - 1], a1); }
        if (l >= 2) { a0 = fmaf(w1, gx0[l - 2], a0); a1 = fmaf(w1, gx1[l - 2], a1); }
        if (l >= 3) { a0 = fmaf(w0, gx0[l - 3], a0); a1 = fmaf(w0, gx1[l - 3], a1); }
        float v0 = a0 / (1.0f + expf(-a0));
        float v1 = a1 / (1.0f + expf(-a1));
        float2 v = make_float2(v0, v1);
        xs[l]   = v;
        buf0[l] = v;
    }
    for (int i = tid + L_SEQ; i < NFFT; i += 512) buf0[i] = make_float2(0.f, 0.f);
    __syncthreads();

    float2* r1 = fft8192_r4(buf0, buf1, tws, 1.0f, tid);

    const float2* __restrict__ Hrow = g_Hf + (size_t)h * NFFT;
    for (int i = tid; i < NFFT; i += 512) r1[i] = cmul(r1[i], Hrow[i]);
    __syncthreads();

    float2* other = (r1 == buf0) ? buf1 : buf0;
    float2* r2 = fft8192_r4(r1, other, tws, -1.0f, tid);

    const float dsk = D_skip[h];
    const float* gz0 = g_xz + ((size_t)DINNER + h) * L_SEQ;
    const float* gz1 = g_xz + ((size_t)EDIM + DINNER + h) * L_SEQ;
    float*       gy0 = g_y  + (size_t)h * L_SEQ;
    float*       gy1 = g_y  + ((size_t)DINNER + h) * L_SEQ;
    const float invn = 1.0f / (float)NFFT;
    for (int l = tid; l < L_SEQ; l += 512) {
        float2 xv = xs[l];
        float y0 = fmaf(r2[l].x, invn, dsk * xv.x);
        float y1 = fmaf(r2[l].y, invn, dsk * xv.y);
        float z0 = gz0[l];
        float z1 = gz1[l];
        gy0[l] = y0 * (z0 / (1.0f + expf(-z0)));
        gy1[l] = y1 * (z1 / (1.0f + expf(-z1)));
    }
}

// ---------------- GEMM1: xz[b][e][l] = sum_d W_in[e][d] * hs[b][l][d] ----------------
__global__ void __launch_bounds__(256) gemm1_kernel(const float* __restrict__ hs,
                                                    const float* __restrict__ Win)
{
    __shared__ float As[16][128];
    __shared__ float Bs[16][128];
    const int b  = blockIdx.z;
    const int m0 = blockIdx.y * 128;   // e
    const int n0 = blockIdx.x * 128;   // l
    const int tid = threadIdx.x;
    const int tx = tid & 15, ty = tid >> 4;

    const float* A = Win;
    const float* B = hs + (size_t)b * L_SEQ * DMODEL;

    float acc[8][8];
    #pragma unroll
    for (int i = 0; i < 8; ++i)
        #pragma unroll
        for (int j = 0; j < 8; ++j) acc[i][j] = 0.f;

    const int lrow = tid >> 2;          // 0..63
    const int lkg  = (tid & 3) << 2;    // 0,4,8,12

    for (int k0 = 0; k0 < DMODEL; k0 += 16) {
        #pragma unroll
        for (int t = 0; t < 2; ++t) {
            int row = lrow + t * 64;
            float4 va = *(const float4*)(A + (size_t)(m0 + row) * DMODEL + k0 + lkg);
            As[lkg + 0][row] = va.x; As[lkg + 1][row] = va.y;
            As[lkg + 2][row] = va.z; As[lkg + 3][row] = va.w;
            float4 vb = *(const float4*)(B + (size_t)(n0 + row) * DMODEL + k0 + lkg);
            Bs[lkg + 0][row] = vb.x; Bs[lkg + 1][row] = vb.y;
            Bs[lkg + 2][row] = vb.z; Bs[lkg + 3][row] = vb.w;
        }
        __syncthreads();
        #pragma unroll
        for (int k = 0; k < 16; ++k) {
            float a[8], bb[8];
            *(float4*)&a[0]  = *(const float4*)&As[k][ty * 8];
            *(float4*)&a[4]  = *(const float4*)&As[k][ty * 8 + 4];
            *(float4*)&bb[0] = *(const float4*)&Bs[k][tx * 8];
            *(float4*)&bb[4] = *(const float4*)&Bs[k][tx * 8 + 4];
            #pragma unroll
            for (int i = 0; i < 8; ++i)
                #pragma unroll
                for (int j = 0; j < 8; ++j)
                    acc[i][j] = fmaf(a[i], bb[j], acc[i][j]);
        }
        __syncthreads();
    }

    float* C = g_xz + (size_t)b * EDIM * L_SEQ;
    #pragma unroll
    for (int i = 0; i < 8; ++i) {
        float* cp = C + (size_t)(m0 + ty * 8 + i) * L_SEQ + n0 + tx * 8;
        *(float4*)cp       = make_float4(acc[i][0], acc[i][1], acc[i][2], acc[i][3]);
        *(float4*)(cp + 4) = make_float4(acc[i][4], acc[i][5], acc[i][6], acc[i][7]);
    }
}

// ---------------- GEMM2: out[b][l][d] = sum_h y[b][h][l] * W_out[d][h] ----------------
__global__ void __launch_bounds__(256) gemm2_kernel(const float* __restrict__ Wout,
                                                    float* __restrict__ out)
{
    __shared__ float As[16][128];   // [h][l]
    __shared__ float Bs[16][128];   // [h][d]
    const int b  = blockIdx.z;
    const int m0 = blockIdx.y * 128;   // l
    const int n0 = blockIdx.x * 128;   // d
    const int tid = threadIdx.x;
    const int tx = tid & 15, ty = tid >> 4;

    const float* Y = g_y + (size_t)b * DINNER * L_SEQ;

    float acc[8][8];
    #pragma unroll
    for (int i = 0; i < 8; ++i)
        #pragma unroll
        for (int j = 0; j < 8; ++j) acc[i][j] = 0.f;

    for (int k0 = 0; k0 < DINNER; k0 += 16) {
        #pragma unroll
        for (int t = 0; t < 2; ++t) {
            int idx = tid + t * 256;            // 0..511
            int kk  = idx >> 5;                 // 0..15
            int mg  = (idx & 31) << 2;          // 0..124
            float4 v = *(const float4*)(Y + (size_t)(k0 + kk) * L_SEQ + m0 + mg);
            *(float4*)&As[kk][mg] = v;
            int row = idx >> 2;                 // d: 0..127
            int kg  = (idx & 3) << 2;           // 0,4,8,12
            float4 wv = *(const float4*)(Wout + (size_t)(n0 + row) * DINNER + k0 + kg);
            Bs[kg + 0][row] = wv.x; Bs[kg + 1][row] = wv.y;
            Bs[kg + 2][row] = wv.z; Bs[kg + 3][row] = wv.w;
        }
        __syncthreads();
        #pragma unroll
        for (int k = 0; k < 16; ++k) {
            float a[8], bb[8];
            *(float4*)&a[0]  = *(const float4*)&As[k][ty * 8];
            *(float4*)&a[4]  = *(const float4*)&As[k][ty * 8 + 4];
            *(float4*)&bb[0] = *(const float4*)&Bs[k][tx * 8];
            *(float4*)&bb[4] = *(const float4*)&Bs[k][tx * 8 + 4];
            #pragma unroll
            for (int i = 0; i < 8; ++i)
                #pragma unroll
                for (int j = 0; j < 8; ++j)
                    acc[i][j] = fmaf(a[i], bb[j], acc[i][j]);
        }
        __syncthreads();
    }

    float* C = out + (size_t)b * L_SEQ * DMODEL;
    #pragma unroll
    for (int i = 0; i < 8; ++i) {
        float* cp = C + (size_t)(m0 + ty * 8 + i) * DMODEL + n0 + tx * 8;
        *(float4*)cp       = make_float4(acc[i][0], acc[i][1], acc[i][2], acc[i][3]);
        *(float4*)(cp + 4) = make_float4(acc[i][4], acc[i][5], acc[i][6], acc[i][7]);
    }
}

// ---------------- launch ----------------
extern "C" void kernel_launch(void* const* d_in, const int* in_sizes, int n_in,
                              void* d_out, int out_size)
{
    (void)in_sizes; (void)n_in; (void)out_size;
    const float* hs     = (const float*)d_in[0];
    const float* W_in   = (const float*)d_in[1];
    const float* conv_w = (const float*)d_in[2];
    const float* conv_b = (const float*)d_in[3];
    const float* k_ssm  = (const float*)d_in[4];
    const float* D_skip = (const float*)d_in[5];
    const float* W_out  = (const float*)d_in[6];
    float* out = (float*)d_out;

    cudaFuncSetAttribute(fftk_kernel,    cudaFuncAttributeMaxDynamicSharedMemorySize, SMEM_FFTK);
    cudaFuncSetAttribute(convfft_kernel, cudaFuncAttributeMaxDynamicSharedMemorySize, SMEM_CONV);

    twiddle_kernel<<<NHALF / 512, 512>>>();
    gemm1_kernel<<<dim3(32, 32, 2), 256>>>(hs, W_in);
    fftk_kernel<<<DINNER, 512, SMEM_FFTK>>>(k_ssm);
    convfft_kernel<<<DINNER, 512, SMEM_CONV>>>(conv_w, conv_b, D_skip);
    gemm2_kernel<<<dim3(DMODEL / 128, L_SEQ / 128, 2), 256>>>(W_out, out);
}

// round 5
// speedup vs baseline: 2.4298x; 2.1463x over previous
#include <cuda_runtime.h>
#include <math.h>
#include <stdint.h>

// ---------------- problem constants ----------------
#define L_SEQ   4096
#define DMODEL  1024
#define DINNER  2048
#define EDIM    (2*DINNER)   // 4096
#define BATCH   2
#define NFFT    8192
#define NQ      (NFFT/4)     // 2048
#define NHALF   (NFFT/2)     // 4096

// single dynamic shared-memory declaration (consistent type across kernels)
extern __shared__ char s4_smem[];

// ---------------- scratch (device globals; allocation-free launch) ----------------
__device__ float  g_xz[(unsigned long long)BATCH * EDIM * L_SEQ];     // [b][e][l]
__device__ float  g_y [(unsigned long long)BATCH * DINNER * L_SEQ];   // [b][h][l]
__device__ float  g_yt[(unsigned long long)BATCH * L_SEQ * DINNER];   // [b][l][h]
__device__ float2 g_Hf[(unsigned long long)DINNER * NFFT];            // kernel spectra
__device__ float2 g_tw[NHALF];                                        // exp(-2*pi*i*k/N)

// ---------------- tf32 helpers ----------------
__device__ __forceinline__ float to_tf32(float x) {
    uint32_t u;
    asm("cvt.rna.tf32.f32 %0, %1;" : "=r"(u) : "f"(x));
    return __uint_as_float(u);
}
__device__ __forceinline__ void mma_tf32(float* d, const uint32_t* a, const uint32_t* b) {
    asm volatile(
        "mma.sync.aligned.m16n8k8.row.col.f32.tf32.tf32.f32 "
        "{%0,%1,%2,%3}, {%4,%5,%6,%7}, {%8,%9}, {%0,%1,%2,%3};"
        : "+f"(d[0]), "+f"(d[1]), "+f"(d[2]), "+f"(d[3])
        : "r"(a[0]), "r"(a[1]), "r"(a[2]), "r"(a[3]), "r"(b[0]), "r"(b[1]));
}

// ================= tf32 mma.sync GEMM =================
// C[m][n] = sum_k A[m*lda+k] * B[n*ldb+k]  (both K-contiguous, NT)
// CTA tile 128x128, 8 warps (2 M x 4 N), warp tile 64x32, mma m16n8k8.
__global__ void __launch_bounds__(256) gemm_mma(const float* __restrict__ A,
                                                const float* __restrict__ B,
                                                float* __restrict__ C,
                                                int lda, int ldb, int ldc, int K,
                                                long long aBatch, long long bBatch,
                                                long long cBatch)
{
    __shared__ float As[128][36];
    __shared__ float Bs[128][36];

    A += (size_t)blockIdx.z * aBatch;
    B += (size_t)blockIdx.z * bBatch;
    C += (size_t)blockIdx.z * cBatch;
    const int m0 = blockIdx.y * 128;
    const int n0 = blockIdx.x * 128;

    const int tid  = threadIdx.x;
    const int wid  = tid >> 5;
    const int lane = tid & 31;
    const int wm   = (wid >> 2) * 64;   // warp M offset
    const int wn   = (wid & 3) * 32;    // warp N offset
    const int g    = lane >> 2;         // group id 0..7
    const int t    = lane & 3;          // thread in group 0..3

    float acc[4][4][4];
    #pragma unroll
    for (int mi = 0; mi < 4; ++mi)
        #pragma unroll
        for (int ni = 0; ni < 4; ++ni)
            #pragma unroll
            for (int r = 0; r < 4; ++r) acc[mi][ni][r] = 0.f;

    const int nch = K >> 5;   // chunks of 32 k
    float4 pa[4], pb[4];

    // prefetch chunk 0
    #pragma unroll
    for (int p = 0; p < 4; ++p) {
        int lin = p * 256 + tid;
        int row = lin >> 3;
        int c4  = lin & 7;
        pa[p] = *(const float4*)(A + (size_t)(m0 + row) * lda + c4 * 4);
        pb[p] = *(const float4*)(B + (size_t)(n0 + row) * ldb + c4 * 4);
    }

    for (int c = 0; c < nch; ++c) {
        __syncthreads();   // prior compute done before overwriting smem
        #pragma unroll
        for (int p = 0; p < 4; ++p) {
            int lin = p * 256 + tid;
            int row = lin >> 3;
            int c4  = lin & 7;
            float4 va = pa[p], vb = pb[p];
            va.x = to_tf32(va.x); va.y = to_tf32(va.y);
            va.z = to_tf32(va.z); va.w = to_tf32(va.w);
            vb.x = to_tf32(vb.x); vb.y = to_tf32(vb.y);
            vb.z = to_tf32(vb.z); vb.w = to_tf32(vb.w);
            *(float4*)&As[row][c4 * 4] = va;
            *(float4*)&Bs[row][c4 * 4] = vb;
        }
        __syncthreads();

        if (c + 1 < nch) {
            const int k0 = (c + 1) << 5;
            #pragma unroll
            for (int p = 0; p < 4; ++p) {
                int lin = p * 256 + tid;
                int row = lin >> 3;
                int c4  = lin & 7;
                pa[p] = *(const float4*)(A + (size_t)(m0 + row) * lda + k0 + c4 * 4);
                pb[p] = *(const float4*)(B + (size_t)(n0 + row) * ldb + k0 + c4 * 4);
            }
        }

        #pragma unroll
        for (int ks = 0; ks < 4; ++ks) {
            const int kk = ks * 8;
            uint32_t af[4][4], bf[4][2];
            #pragma unroll
            for (int mi = 0; mi < 4; ++mi) {
                int r = wm + mi * 16 + g;
                af[mi][0] = __float_as_uint(As[r][kk + t]);
                af[mi][1] = __float_as_uint(As[r + 8][kk + t]);
                af[mi][2] = __float_as_uint(As[r][kk + t + 4]);
                af[mi][3] = __float_as_uint(As[r + 8][kk + t + 4]);
            }
            #pragma unroll
            for (int ni = 0; ni < 4; ++ni) {
                int cn = wn + ni * 8 + g;
                bf[ni][0] = __float_as_uint(Bs[cn][kk + t]);
                bf[ni][1] = __float_as_uint(Bs[cn][kk + t + 4]);
            }
            #pragma unroll
            for (int mi = 0; mi < 4; ++mi)
                #pragma unroll
                for (int ni = 0; ni < 4; ++ni)
                    mma_tf32(acc[mi][ni], af[mi], bf[ni]);
        }
    }

    // epilogue
    #pragma unroll
    for (int mi = 0; mi < 4; ++mi) {
        int r0 = m0 + wm + mi * 16 + g;
        #pragma unroll
        for (int ni = 0; ni < 4; ++ni) {
            int cc = n0 + wn + ni * 8 + t * 2;
            *(float2*)(C + (size_t)r0 * ldc + cc)       = make_float2(acc[mi][ni][0], acc[mi][ni][1]);
            *(float2*)(C + (size_t)(r0 + 8) * ldc + cc) = make_float2(acc[mi][ni][2], acc[mi][ni][3]);
        }
    }
}

// ================= transpose y[b][h][l] -> y_t[b][l][h] =================
__global__ void __launch_bounds__(256) transpose_kernel()
{
    __shared__ float tbuf[32][33];
    const int b  = blockIdx.z;
    const int l0 = blockIdx.x * 32;
    const int h0 = blockIdx.y * 32;
    const int tx = threadIdx.x, ty = threadIdx.y;   // (32, 8)

    const float* src = g_y + (size_t)b * DINNER * L_SEQ;
    float*       dst = g_yt + (size_t)b * L_SEQ * DINNER;
    #pragma unroll
    for (int i = 0; i < 4; ++i)
        tbuf[ty + i * 8][tx] = src[(size_t)(h0 + ty + i * 8) * L_SEQ + l0 + tx];
    __syncthreads();
    #pragma unroll
    for (int i = 0; i < 4; ++i)
        dst[(size_t)(l0 + ty + i * 8) * DINNER + h0 + tx] = tbuf[tx][ty + i * 8];
}

// ---------------- twiddle table ----------------
__global__ void twiddle_kernel() {
    int k = blockIdx.x * blockDim.x + threadIdx.x;
    if (k < NHALF) {
        float s, c;
        sincospif(2.0f * (float)k / (float)NFFT, &s, &c);
        g_tw[k] = make_float2(c, -s);
    }
}

// ---------------- complex helpers ----------------
__device__ __forceinline__ float2 cmul(float2 a, float2 b) {
    return make_float2(fmaf(a.x, b.x, -a.y * b.y), fmaf(a.x, b.y, a.y * b.x));
}
__device__ __forceinline__ float2 cadd(float2 a, float2 b) { return make_float2(a.x + b.x, a.y + b.y); }
__device__ __forceinline__ float2 csub(float2 a, float2 b) { return make_float2(a.x - b.x, a.y - b.y); }

// ---------------- FFT core: Stockham, 6 radix-4 stages + 1 radix-2, 512 thr ----------
__device__ float2* fft8192_r4(float2* src, float2* dst, const float2* __restrict__ tw,
                              float sgn, int tid)
{
    int s = 1;
    #pragma unroll 1
    for (int st = 0; st < 6; ++st) {
        int sm1 = s - 1;
        #pragma unroll
        for (int r = 0; r < NQ / 512; ++r) {
            int i  = tid + r * 512;
            int q  = i & sm1;
            int ps = i - q;
            float2 x0 = src[i];
            float2 x2 = src[i + NQ];
            float2 x1 = src[i + NHALF];
            float2 x3 = src[i + NQ + NHALF];
            float2 w1 = tw[ps];
            float2 w2 = tw[2 * ps];
            w1.y *= sgn; w2.y *= sgn;
            float2 w3 = cmul(w1, w2);
            float2 u0 = cadd(x0, x1);
            float2 d0 = csub(x0, x1);
            float2 u1 = cadd(x2, x3);
            float2 d1 = csub(x2, x3);
            float2 sd1 = make_float2(sgn * d1.y, -sgn * d1.x);
            float2 y0 = cadd(u0, u1);
            float2 y2 = cmul(csub(u0, u1), w2);
            float2 y1 = cmul(cadd(d0, sd1), w1);
            float2 y3 = cmul(csub(d0, sd1), w3);
            int o = q + 4 * ps;
            dst[o]         = y0;
            dst[o + s]     = y1;
            dst[o + 2 * s] = y2;
            dst[o + 3 * s] = y3;
        }
        __syncthreads();
        float2* t = src; src = dst; dst = t;
        s <<= 2;
    }
    #pragma unroll
    for (int r = 0; r < NHALF / 512; ++r) {
        int i = tid + r * 512;
        float2 a = src[i];
        float2 b = src[i + NHALF];
        dst[i]         = cadd(a, b);
        dst[i + NHALF] = csub(a, b);
    }
    __syncthreads();
    return dst;
}

// ---------------- kernel spectrum: Hf[h] = FFT(pad(k_ssm[h])) ----------------
#define SMEM_FFTK ((2 * NFFT + NHALF) * (int)sizeof(float2))
__global__ void __launch_bounds__(512) fftk_kernel(const float* __restrict__ k_ssm)
{
    float2* buf0 = (float2*)s4_smem;
    float2* buf1 = buf0 + NFFT;
    float2* tws  = buf1 + NFFT;
    const int h = blockIdx.x;
    const int tid = threadIdx.x;

    for (int i = tid; i < NHALF; i += 512) tws[i] = g_tw[i];
    const float* kr = k_ssm + (size_t)h * L_SEQ;
    for (int i = tid; i < L_SEQ; i += 512)        buf0[i] = make_float2(kr[i], 0.f);
    for (int i = tid + L_SEQ; i < NFFT; i += 512) buf0[i] = make_float2(0.f, 0.f);
    __syncthreads();

    float2* res = fft8192_r4(buf0, buf1, tws, 1.0f, tid);
    float2* out = g_Hf + (size_t)h * NFFT;
    for (int i = tid; i < NFFT; i += 512) out[i] = res[i];
}

// ------- fused: conv4+SiLU -> batch-packed FFT conv -> D_skip -> *SiLU(z) -------
#define SMEM_CONV ((2 * NFFT + NHALF + L_SEQ) * (int)sizeof(float2))
__global__ void __launch_bounds__(512) convfft_kernel(const float* __restrict__ conv_w,
                                                      const float* __restrict__ conv_b,
                                                      const float* __restrict__ D_skip)
{
    float2* buf0 = (float2*)s4_smem;
    float2* buf1 = buf0 + NFFT;
    float2* tws  = buf1 + NFFT;
    float2* xs   = tws + NHALF;

    const int h   = blockIdx.x;
    const int tid = threadIdx.x;

    for (int i = tid; i < NHALF; i += 512) tws[i] = g_tw[i];

    const float w0 = conv_w[h * 4 + 0];
    const float w1 = conv_w[h * 4 + 1];
    const float w2 = conv_w[h * 4 + 2];
    const float w3 = conv_w[h * 4 + 3];
    const float cb = conv_b[h];

    const float* gx0 = g_xz + (size_t)h * L_SEQ;
    const float* gx1 = g_xz + ((size_t)EDIM + h) * L_SEQ;
    for (int l = tid; l < L_SEQ; l += 512) {
        float a0 = fmaf(w3, gx0[l], cb);
        float a1 = fmaf(w3, gx1[l], cb);
        if (l >= 1) { a0 = fmaf(w2, gx0[l - 1], a0); a1 = fmaf(w2, gx1[l - 1], a1); }
        if (l >= 2) { a0 = fmaf(w1, gx0[l - 2], a0); a1 = fmaf(w1, gx1[l - 2], a1); }
        if (l >= 3) { a0 = fmaf(w0, gx0[l - 3], a0); a1 = fmaf(w0, gx1[l - 3], a1); }
        float v0 = a0 / (1.0f + expf(-a0));
        float v1 = a1 / (1.0f + expf(-a1));
        float2 v = make_float2(v0, v1);
        xs[l]   = v;
        buf0[l] = v;
    }
    for (int i = tid + L_SEQ; i < NFFT; i += 512) buf0[i] = make_float2(0.f, 0.f);
    __syncthreads();

    float2* r1 = fft8192_r4(buf0, buf1, tws, 1.0f, tid);

    const float2* __restrict__ Hrow = g_Hf + (size_t)h * NFFT;
    for (int i = tid; i < NFFT; i += 512) r1[i] = cmul(r1[i], Hrow[i]);
    __syncthreads();

    float2* other = (r1 == buf0) ? buf1 : buf0;
    float2* r2 = fft8192_r4(r1, other, tws, -1.0f, tid);

    const float dsk = D_skip[h];
    const float* gz0 = g_xz + ((size_t)DINNER + h) * L_SEQ;
    const float* gz1 = g_xz + ((size_t)EDIM + DINNER + h) * L_SEQ;
    float*       gy0 = g_y  + (size_t)h * L_SEQ;
    float*       gy1 = g_y  + ((size_t)DINNER + h) * L_SEQ;
    const float invn = 1.0f / (float)NFFT;
    for (int l = tid; l < L_SEQ; l += 512) {
        float2 xv = xs[l];
        float y0 = fmaf(r2[l].x, invn, dsk * xv.x);
        float y1 = fmaf(r2[l].y, invn, dsk * xv.y);
        float z0 = gz0[l];
        float z1 = gz1[l];
        gy0[l] = y0 * (z0 / (1.0f + expf(-z0)));
        gy1[l] = y1 * (z1 / (1.0f + expf(-z1)));
    }
}

// ---------------- launch ----------------
extern "C" void kernel_launch(void* const* d_in, const int* in_sizes, int n_in,
                              void* d_out, int out_size)
{
    (void)in_sizes; (void)n_in; (void)out_size;
    const float* hs     = (const float*)d_in[0];
    const float* W_in   = (const float*)d_in[1];
    const float* conv_w = (const float*)d_in[2];
    const float* conv_b = (const float*)d_in[3];
    const float* k_ssm  = (const float*)d_in[4];
    const float* D_skip = (const float*)d_in[5];
    const float* W_out  = (const float*)d_in[6];
    float* out = (float*)d_out;

    cudaFuncSetAttribute(fftk_kernel,    cudaFuncAttributeMaxDynamicSharedMemorySize, SMEM_FFTK);
    cudaFuncSetAttribute(convfft_kernel, cudaFuncAttributeMaxDynamicSharedMemorySize, SMEM_CONV);

    float* xz = nullptr; cudaGetSymbolAddress((void**)&xz, g_xz);
    float* yt = nullptr; cudaGetSymbolAddress((void**)&yt, g_yt);

    twiddle_kernel<<<NHALF / 512, 512>>>();

    // GEMM1: xz[b][e][l] = sum_d W_in[e][d] * hs[b][l][d]
    gemm_mma<<<dim3(L_SEQ / 128, EDIM / 128, BATCH), 256>>>(
        W_in, hs, xz, DMODEL, DMODEL, L_SEQ, DMODEL,
        0LL, (long long)L_SEQ * DMODEL, (long long)EDIM * L_SEQ);

    fftk_kernel<<<DINNER, 512, SMEM_FFTK>>>(k_ssm);
    convfft_kernel<<<DINNER, 512, SMEM_CONV>>>(conv_w, conv_b, D_skip);

    transpose_kernel<<<dim3(L_SEQ / 32, DINNER / 32, BATCH), dim3(32, 8)>>>();

    // GEMM2: out[b][l][d] = sum_h y_t[b][l][h] * W_out[d][h]
    gemm_mma<<<dim3(DMODEL / 128, L_SEQ / 128, BATCH), 256>>>(
        yt, W_out, out, DINNER, DINNER, DMODEL, DINNER,
        (long long)L_SEQ * DINNER, 0LL, (long long)L_SEQ * DMODEL);
}

// round 6
// speedup vs baseline: 2.7398x; 1.1276x over previous
#include <cuda_runtime.h>
#include <math.h>
#include <stdint.h>

// ---------------- problem constants ----------------
#define L_SEQ   4096
#define DMODEL  1024
#define DINNER  2048
#define EDIM    (2*DINNER)   // 4096
#define BATCH   2
#define NFFT    8192
#define NHALF   (NFFT/2)     // 4096

// skewed smem addressing for FFT buffers: linear conflict-free, strided <=2-way
#define SKW(i)  ((i) + ((i) >> 4))
#define SKWN    (NFFT + NFFT/16)     // 8704 float2 per buffer

// single dynamic shared-memory declaration (consistent type across kernels)
extern __shared__ char s4_smem[];

// ---------------- scratch (device globals; allocation-free launch) ----------------
__device__ float  g_xz[(unsigned long long)BATCH * EDIM * L_SEQ];     // [b][e][l]
__device__ float  g_y [(unsigned long long)BATCH * DINNER * L_SEQ];   // [b][h][l]
__device__ float  g_yt[(unsigned long long)BATCH * L_SEQ * DINNER];   // [b][l][h]
__device__ float2 g_Hf[(unsigned long long)DINNER * NFFT];            // kernel spectra
__device__ float2 g_tw[NHALF];                                        // exp(-2*pi*i*k/N)

// ---------------- tf32 helpers ----------------
__device__ __forceinline__ float to_tf32(float x) {
    uint32_t u;
    asm("cvt.rna.tf32.f32 %0, %1;" : "=r"(u) : "f"(x));
    return __uint_as_float(u);
}
__device__ __forceinline__ void mma_tf32(float* d, const uint32_t* a, const uint32_t* b) {
    asm volatile(
        "mma.sync.aligned.m16n8k8.row.col.f32.tf32.tf32.f32 "
        "{%0,%1,%2,%3}, {%4,%5,%6,%7}, {%8,%9}, {%0,%1,%2,%3};"
        : "+f"(d[0]), "+f"(d[1]), "+f"(d[2]), "+f"(d[3])
        : "r"(a[0]), "r"(a[1]), "r"(a[2]), "r"(a[3]), "r"(b[0]), "r"(b[1]));
}

// ================= tf32 mma.sync GEMM =================
// C[m][n] = sum_k A[m*lda+k] * B[n*ldb+k]  (both K-contiguous, NT)
__global__ void __launch_bounds__(256) gemm_mma(const float* __restrict__ A,
                                                const float* __restrict__ B,
                                                float* __restrict__ C,
                                                int lda, int ldb, int ldc, int K,
                                                long long aBatch, long long bBatch,
                                                long long cBatch)
{
    __shared__ float As[128][36];
    __shared__ float Bs[128][36];

    A += (size_t)blockIdx.z * aBatch;
    B += (size_t)blockIdx.z * bBatch;
    C += (size_t)blockIdx.z * cBatch;
    const int m0 = blockIdx.y * 128;
    const int n0 = blockIdx.x * 128;

    const int tid  = threadIdx.x;
    const int wid  = tid >> 5;
    const int lane = tid & 31;
    const int wm   = (wid >> 2) * 64;
    const int wn   = (wid & 3) * 32;
    const int g    = lane >> 2;
    const int t    = lane & 3;

    float acc[4][4][4];
    #pragma unroll
    for (int mi = 0; mi < 4; ++mi)
        #pragma unroll
        for (int ni = 0; ni < 4; ++ni)
            #pragma unroll
            for (int r = 0; r < 4; ++r) acc[mi][ni][r] = 0.f;

    const int nch = K >> 5;
    float4 pa[4], pb[4];

    #pragma unroll
    for (int p = 0; p < 4; ++p) {
        int lin = p * 256 + tid;
        int row = lin >> 3;
        int c4  = lin & 7;
        pa[p] = *(const float4*)(A + (size_t)(m0 + row) * lda + c4 * 4);
        pb[p] = *(const float4*)(B + (size_t)(n0 + row) * ldb + c4 * 4);
    }

    for (int c = 0; c < nch; ++c) {
        __syncthreads();
        #pragma unroll
        for (int p = 0; p < 4; ++p) {
            int lin = p * 256 + tid;
            int row = lin >> 3;
            int c4  = lin & 7;
            float4 va = pa[p], vb = pb[p];
            va.x = to_tf32(va.x); va.y = to_tf32(va.y);
            va.z = to_tf32(va.z); va.w = to_tf32(va.w);
            vb.x = to_tf32(vb.x); vb.y = to_tf32(vb.y);
            vb.z = to_tf32(vb.z); vb.w = to_tf32(vb.w);
            *(float4*)&As[row][c4 * 4] = va;
            *(float4*)&Bs[row][c4 * 4] = vb;
        }
        __syncthreads();

        if (c + 1 < nch) {
            const int k0 = (c + 1) << 5;
            #pragma unroll
            for (int p = 0; p < 4; ++p) {
                int lin = p * 256 + tid;
                int row = lin >> 3;
                int c4  = lin & 7;
                pa[p] = *(const float4*)(A + (size_t)(m0 + row) * lda + k0 + c4 * 4);
                pb[p] = *(const float4*)(B + (size_t)(n0 + row) * ldb + k0 + c4 * 4);
            }
        }

        #pragma unroll
        for (int ks = 0; ks < 4; ++ks) {
            const int kk = ks * 8;
            uint32_t af[4][4], bf[4][2];
            #pragma unroll
            for (int mi = 0; mi < 4; ++mi) {
                int r = wm + mi * 16 + g;
                af[mi][0] = __float_as_uint(As[r][kk + t]);
                af[mi][1] = __float_as_uint(As[r + 8][kk + t]);
                af[mi][2] = __float_as_uint(As[r][kk + t + 4]);
                af[mi][3] = __float_as_uint(As[r + 8][kk + t + 4]);
            }
            #pragma unroll
            for (int ni = 0; ni < 4; ++ni) {
                int cn = wn + ni * 8 + g;
                bf[ni][0] = __float_as_uint(Bs[cn][kk + t]);
                bf[ni][1] = __float_as_uint(Bs[cn][kk + t + 4]);
            }
            #pragma unroll
            for (int mi = 0; mi < 4; ++mi)
                #pragma unroll
                for (int ni = 0; ni < 4; ++ni)
                    mma_tf32(acc[mi][ni], af[mi], bf[ni]);
        }
    }

    #pragma unroll
    for (int mi = 0; mi < 4; ++mi) {
        int r0 = m0 + wm + mi * 16 + g;
        #pragma unroll
        for (int ni = 0; ni < 4; ++ni) {
            int cc = n0 + wn + ni * 8 + t * 2;
            *(float2*)(C + (size_t)r0 * ldc + cc)       = make_float2(acc[mi][ni][0], acc[mi][ni][1]);
            *(float2*)(C + (size_t)(r0 + 8) * ldc + cc) = make_float2(acc[mi][ni][2], acc[mi][ni][3]);
        }
    }
}

// ================= transpose y[b][h][l] -> y_t[b][l][h] =================
__global__ void __launch_bounds__(256) transpose_kernel()
{
    __shared__ float tbuf[32][33];
    const int b  = blockIdx.z;
    const int l0 = blockIdx.x * 32;
    const int h0 = blockIdx.y * 32;
    const int tx = threadIdx.x, ty = threadIdx.y;

    const float* src = g_y + (size_t)b * DINNER * L_SEQ;
    float*       dst = g_yt + (size_t)b * L_SEQ * DINNER;
    #pragma unroll
    for (int i = 0; i < 4; ++i)
        tbuf[ty + i * 8][tx] = src[(size_t)(h0 + ty + i * 8) * L_SEQ + l0 + tx];
    __syncthreads();
    #pragma unroll
    for (int i = 0; i < 4; ++i)
        dst[(size_t)(l0 + ty + i * 8) * DINNER + h0 + tx] = tbuf[tx][ty + i * 8];
}

// ---------------- twiddle table ----------------
__global__ void twiddle_kernel() {
    int k = blockIdx.x * blockDim.x + threadIdx.x;
    if (k < NHALF) {
        float s, c;
        sincospif(2.0f * (float)k / (float)NFFT, &s, &c);
        g_tw[k] = make_float2(c, -s);
    }
}

// ---------------- complex helpers ----------------
__device__ __forceinline__ float2 cmul(float2 a, float2 b) {
    return make_float2(fmaf(a.x, b.x, -a.y * b.y), fmaf(a.x, b.y, a.y * b.x));
}
__device__ __forceinline__ float2 cadd(float2 a, float2 b) { return make_float2(a.x + b.x, a.y + b.y); }
__device__ __forceinline__ float2 csub(float2 a, float2 b) { return make_float2(a.x - b.x, a.y - b.y); }

// ---------------- FFT core: Stockham radix-8 (4 stages) + radix-2, 512 thr ---------
// sgn = +1 forward, -1 inverse (unscaled). All buffer indices SKW-mapped.
// padded: input nonzero only in [0, NHALF) -> specialized first stage.
// halfOut: only outputs [0, NHALF) of the final stage are produced.
__device__ float2* fft8192_r8(float2* src, float2* dst, const float2* __restrict__ tw,
                              float sgn, int tid, bool padded, bool halfOut)
{
    const float RH = 0.70710678118654752f;   // sqrt(2)/2

    // ---- 4 radix-8 stages: s = 1, 8, 64, 512 ----
    int s = 1;
    #pragma unroll 1
    for (int st = 0; st < 4; ++st) {
        const int sm1 = s - 1;
        #pragma unroll
        for (int r = 0; r < 2; ++r) {              // N/8 = 1024 butterflies
            int i  = tid + r * 512;
            int q  = i & sm1;
            int ps = i - q;

            float2 a0 = src[SKW(i)];
            float2 a1 = src[SKW(i + 1024)];
            float2 a2 = src[SKW(i + 2048)];
            float2 a3 = src[SKW(i + 3072)];

            float2 E0, E1, E2, E3, O0, O1, O2, O3;
            if (padded && st == 0) {
                // a4..a7 == 0
                float2 m2 = make_float2(sgn * a2.y, -sgn * a2.x);
                float2 m3 = make_float2(sgn * a3.y, -sgn * a3.x);
                E0 = cadd(a0, a2); E2 = csub(a0, a2);
                E1 = cadd(a0, m2); E3 = csub(a0, m2);
                O0 = cadd(a1, a3); O2 = csub(a1, a3);
                O1 = cadd(a1, m3); O3 = csub(a1, m3);
            } else {
                float2 a4 = src[SKW(i + 4096)];
                float2 a5 = src[SKW(i + 5120)];
                float2 a6 = src[SKW(i + 6144)];
                float2 a7 = src[SKW(i + 7168)];
                // even DFT4 over (a0,a2,a4,a6)
                float2 t0 = cadd(a0, a4), t1 = csub(a0, a4);
                float2 t2 = cadd(a2, a6), t3 = csub(a2, a6);
                float2 m3e = make_float2(sgn * t3.y, -sgn * t3.x);
                E0 = cadd(t0, t2); E2 = csub(t0, t2);
                E1 = cadd(t1, m3e); E3 = csub(t1, m3e);
                // odd DFT4 over (a1,a3,a5,a7)
                float2 u0 = cadd(a1, a5), u1 = csub(a1, a5);
                float2 u2 = cadd(a3, a7), u3 = csub(a3, a7);
                float2 m3o = make_float2(sgn * u3.y, -sgn * u3.x);
                O0 = cadd(u0, u2); O2 = csub(u0, u2);
                O1 = cadd(u1, m3o); O3 = csub(u1, m3o);
            }

            // W8^k * O[k]
            float2 W1O = make_float2(RH * (O1.x + sgn * O1.y), RH * (O1.y - sgn * O1.x));
            float2 W2O = make_float2(sgn * O2.y, -sgn * O2.x);
            float2 W3O = make_float2(RH * (sgn * O3.y - O3.x), -RH * (O3.y + sgn * O3.x));

            float2 X0 = cadd(E0, O0),  X4 = csub(E0, O0);
            float2 X1 = cadd(E1, W1O), X5 = csub(E1, W1O);
            float2 X2 = cadd(E2, W2O), X6 = csub(E2, W2O);
            float2 X3 = cadd(E3, W3O), X7 = csub(E3, W3O);

            float2 w1 = tw[ps];     w1.y *= sgn;
            float2 w2 = tw[2 * ps]; w2.y *= sgn;
            float2 w4 = tw[4 * ps]; w4.y *= sgn;
            float2 w3 = cmul(w1, w2);
            float2 w5 = cmul(w1, w4);
            float2 w6 = cmul(w2, w4);
            float2 w7 = cmul(w3, w4);

            int o = q + 8 * ps;
            dst[SKW(o)]         = X0;
            dst[SKW(o + s)]     = cmul(X1, w1);
            dst[SKW(o + 2 * s)] = cmul(X2, w2);
            dst[SKW(o + 3 * s)] = cmul(X3, w3);
            dst[SKW(o + 4 * s)] = cmul(X4, w4);
            dst[SKW(o + 5 * s)] = cmul(X5, w5);
            dst[SKW(o + 6 * s)] = cmul(X6, w6);
            dst[SKW(o + 7 * s)] = cmul(X7, w7);
        }
        __syncthreads();
        float2* t = src; src = dst; dst = t;
        s <<= 3;
    }

    // ---- final radix-2, s = 4096, twiddle-free ----
    #pragma unroll
    for (int r = 0; r < 8; ++r) {
        int i = tid + r * 512;
        float2 a = src[SKW(i)];
        float2 b = src[SKW(i + NHALF)];
        dst[SKW(i)] = cadd(a, b);
        if (!halfOut) dst[SKW(i + NHALF)] = csub(a, b);
    }
    __syncthreads();
    return dst;
}

// ---------------- kernel spectra: two real channels per FFT (Re/Im packing) --------
// F = FFT(k[2b] + i*k[2b+1]); unpack via Hermitian symmetry.
#define SMEM_FFTK ((2 * SKWN + NHALF) * (int)sizeof(float2))
__global__ void __launch_bounds__(512) fftk_kernel(const float* __restrict__ k_ssm)
{
    float2* buf0 = (float2*)s4_smem;
    float2* buf1 = buf0 + SKWN;
    float2* tws  = buf1 + SKWN;
    const int h0 = blockIdx.x * 2;
    const int tid = threadIdx.x;

    for (int i = tid; i < NHALF; i += 512) tws[i] = g_tw[i];
    const float* k0 = k_ssm + (size_t)h0 * L_SEQ;
    const float* k1 = k0 + L_SEQ;
    for (int l = tid; l < L_SEQ; l += 512)
        buf0[SKW(l)] = make_float2(k0[l], k1[l]);
    __syncthreads();

    float2* F = fft8192_r8(buf0, buf1, tws, 1.0f, tid, true, false);

    float2* H0 = g_Hf + (size_t)h0 * NFFT;
    float2* H1 = H0 + NFFT;
    for (int k = tid; k < NFFT; k += 512) {
        float2 Fk = F[SKW(k)];
        float2 Fn = F[SKW((NFFT - k) & (NFFT - 1))];
        H0[k] = make_float2(0.5f * (Fk.x + Fn.x), 0.5f * (Fk.y - Fn.y));
        float2 Bd = make_float2(Fk.x - Fn.x, Fk.y + Fn.y);
        H1[k] = make_float2(0.5f * Bd.y, -0.5f * Bd.x);
    }
}

// ------- fused: conv4+SiLU -> batch-packed FFT conv -> D_skip -> *SiLU(z) -------
#define SMEM_CONV ((2 * SKWN + NHALF + L_SEQ) * (int)sizeof(float2))
__global__ void __launch_bounds__(512) convfft_kernel(const float* __restrict__ conv_w,
                                                      const float* __restrict__ conv_b,
                                                      const float* __restrict__ D_skip)
{
    float2* buf0 = (float2*)s4_smem;
    float2* buf1 = buf0 + SKWN;
    float2* tws  = buf1 + SKWN;
    float2* xs   = tws + NHALF;

    const int h   = blockIdx.x;
    const int tid = threadIdx.x;

    for (int i = tid; i < NHALF; i += 512) tws[i] = g_tw[i];

    const float w0 = conv_w[h * 4 + 0];
    const float w1 = conv_w[h * 4 + 1];
    const float w2 = conv_w[h * 4 + 2];
    const float w3 = conv_w[h * 4 + 3];
    const float cb = conv_b[h];

    const float* gx0 = g_xz + (size_t)h * L_SEQ;
    const float* gx1 = g_xz + ((size_t)EDIM + h) * L_SEQ;
    for (int l = tid; l < L_SEQ; l += 512) {
        float a0 = fmaf(w3, gx0[l], cb);
        float a1 = fmaf(w3, gx1[l], cb);
        if (l >= 1) { a0 = fmaf(w2, gx0[l - 1], a0); a1 = fmaf(w2, gx1[l - 1], a1); }
        if (l >= 2) { a0 = fmaf(w1, gx0[l - 2], a0); a1 = fmaf(w1, gx1[l - 2], a1); }
        if (l >= 3) { a0 = fmaf(w0, gx0[l - 3], a0); a1 = fmaf(w0, gx1[l - 3], a1); }
        float v0 = a0 / (1.0f + expf(-a0));
        float v1 = a1 / (1.0f + expf(-a1));
        float2 v = make_float2(v0, v1);
        xs[l]        = v;
        buf0[SKW(l)] = v;
    }
    __syncthreads();

    float2* r1 = fft8192_r8(buf0, buf1, tws, 1.0f, tid, true, false);

    const float2* __restrict__ Hrow = g_Hf + (size_t)h * NFFT;
    for (int i = tid; i < NFFT; i += 512) {
        float2 v = r1[SKW(i)];
        r1[SKW(i)] = cmul(v, Hrow[i]);
    }
    __syncthreads();

    float2* other = (r1 == buf0) ? buf1 : buf0;
    float2* r2 = fft8192_r8(r1, other, tws, -1.0f, tid, false, true);

    const float dsk = D_skip[h];
    const float* gz0 = g_xz + ((size_t)DINNER + h) * L_SEQ;
    const float* gz1 = g_xz + ((size_t)EDIM + DINNER + h) * L_SEQ;
    float*       gy0 = g_y  + (size_t)h * L_SEQ;
    float*       gy1 = g_y  + ((size_t)DINNER + h) * L_SEQ;
    const float invn = 1.0f / (float)NFFT;
    for (int l = tid; l < L_SEQ; l += 512) {
        float2 xv = xs[l];
        float2 rv = r2[SKW(l)];
        float y0 = fmaf(rv.x, invn, dsk * xv.x);
        float y1 = fmaf(rv.y, invn, dsk * xv.y);
        float z0 = gz0[l];
        float z1 = gz1[l];
        gy0[l] = y0 * (z0 / (1.0f + expf(-z0)));
        gy1[l] = y1 * (z1 / (1.0f + expf(-z1)));
    }
}

// ---------------- launch ----------------
extern "C" void kernel_launch(void* const* d_in, const int* in_sizes, int n_in,
                              void* d_out, int out_size)
{
    (void)in_sizes; (void)n_in; (void)out_size;
    const float* hs     = (const float*)d_in[0];
    const float* W_in   = (const float*)d_in[1];
    const float* conv_w = (const float*)d_in[2];
    const float* conv_b = (const float*)d_in[3];
    const float* k_ssm  = (const float*)d_in[4];
    const float* D_skip = (const float*)d_in[5];
    const float* W_out  = (const float*)d_in[6];
    float* out = (float*)d_out;

    cudaFuncSetAttribute(fftk_kernel,    cudaFuncAttributeMaxDynamicSharedMemorySize, SMEM_FFTK);
    cudaFuncSetAttribute(convfft_kernel, cudaFuncAttributeMaxDynamicSharedMemorySize, SMEM_CONV);

    float* xz = nullptr; cudaGetSymbolAddress((void**)&xz, g_xz);
    float* yt = nullptr; cudaGetSymbolAddress((void**)&yt, g_yt);

    twiddle_kernel<<<NHALF / 512, 512>>>();

    // GEMM1: xz[b][e][l] = sum_d W_in[e][d] * hs[b][l][d]
    gemm_mma<<<dim3(L_SEQ / 128, EDIM / 128, BATCH), 256>>>(
        W_in, hs, xz, DMODEL, DMODEL, L_SEQ, DMODEL,
        0LL, (long long)L_SEQ * DMODEL, (long long)EDIM * L_SEQ);

    fftk_kernel<<<DINNER / 2, 512, SMEM_FFTK>>>(k_ssm);
    convfft_kernel<<<DINNER, 512, SMEM_CONV>>>(conv_w, conv_b, D_skip);

    transpose_kernel<<<dim3(L_SEQ / 32, DINNER / 32, BATCH), dim3(32, 8)>>>();

    // GEMM2: out[b][l][d] = sum_h y_t[b][l][h] * W_out[d][h]
    gemm_mma<<<dim3(DMODEL / 128, L_SEQ / 128, BATCH), 256>>>(
        yt, W_out, out, DINNER, DINNER, DMODEL, DINNER,
        (long long)L_SEQ * DINNER, 0LL, (long long)L_SEQ * DMODEL);
}

// round 7
// speedup vs baseline: 3.0727x; 1.1215x over previous
#include <cuda_runtime.h>
#include <math.h>
#include <stdint.h>

// ---------------- problem constants ----------------
#define L_SEQ   4096
#define DMODEL  1024
#define DINNER  2048
#define EDIM    (2*DINNER)   // 4096
#define BATCH   2
#define NFFT    8192
#define NHALF   (NFFT/2)     // 4096
#define NTHR    1024         // FFT kernel block size

// skewed smem addressing for FFT buffers: linear conflict-free, strided <=2-way
#define SKW(i)  ((i) + ((i) >> 4))
#define SKWN    (NFFT + NFFT/16)     // 8704 float2 per buffer

// single dynamic shared-memory declaration (consistent type across kernels)
extern __shared__ char s4_smem[];

// ---------------- scratch (device globals; allocation-free launch) ----------------
__device__ float  g_xz[(unsigned long long)BATCH * EDIM * L_SEQ];     // [b][e][l]
__device__ float  g_y [(unsigned long long)BATCH * DINNER * L_SEQ];   // [b][h][l]
__device__ float  g_yt[(unsigned long long)BATCH * L_SEQ * DINNER];   // [b][l][h]
__device__ float2 g_Hf[(unsigned long long)DINNER * NFFT];            // kernel spectra
__device__ float2 g_tw[NHALF];                                        // exp(-2*pi*i*k/N)

// ---------------- tf32 helpers ----------------
__device__ __forceinline__ float to_tf32(float x) {
    uint32_t u;
    asm("cvt.rna.tf32.f32 %0, %1;" : "=r"(u) : "f"(x));
    return __uint_as_float(u);
}
__device__ __forceinline__ void mma_tf32(float* d, const uint32_t* a, const uint32_t* b) {
    asm volatile(
        "mma.sync.aligned.m16n8k8.row.col.f32.tf32.tf32.f32 "
        "{%0,%1,%2,%3}, {%4,%5,%6,%7}, {%8,%9}, {%0,%1,%2,%3};"
        : "+f"(d[0]), "+f"(d[1]), "+f"(d[2]), "+f"(d[3])
        : "r"(a[0]), "r"(a[1]), "r"(a[2]), "r"(a[3]), "r"(b[0]), "r"(b[1]));
}

// ================= tf32 mma.sync GEMM =================
// C[m][n] = sum_k A[m*lda+k] * B[n*ldb+k]  (both K-contiguous, NT)
__global__ void __launch_bounds__(256) gemm_mma(const float* __restrict__ A,
                                                const float* __restrict__ B,
                                                float* __restrict__ C,
                                                int lda, int ldb, int ldc, int K,
                                                long long aBatch, long long bBatch,
                                                long long cBatch)
{
    __shared__ float As[128][36];
    __shared__ float Bs[128][36];

    A += (size_t)blockIdx.z * aBatch;
    B += (size_t)blockIdx.z * bBatch;
    C += (size_t)blockIdx.z * cBatch;
    const int m0 = blockIdx.y * 128;
    const int n0 = blockIdx.x * 128;

    const int tid  = threadIdx.x;
    const int wid  = tid >> 5;
    const int lane = tid & 31;
    const int wm   = (wid >> 2) * 64;
    const int wn   = (wid & 3) * 32;
    const int g    = lane >> 2;
    const int t    = lane & 3;

    float acc[4][4][4];
    #pragma unroll
    for (int mi = 0; mi < 4; ++mi)
        #pragma unroll
        for (int ni = 0; ni < 4; ++ni)
            #pragma unroll
            for (int r = 0; r < 4; ++r) acc[mi][ni][r] = 0.f;

    const int nch = K >> 5;
    float4 pa[4], pb[4];

    #pragma unroll
    for (int p = 0; p < 4; ++p) {
        int lin = p * 256 + tid;
        int row = lin >> 3;
        int c4  = lin & 7;
        pa[p] = *(const float4*)(A + (size_t)(m0 + row) * lda + c4 * 4);
        pb[p] = *(const float4*)(B + (size_t)(n0 + row) * ldb + c4 * 4);
    }

    for (int c = 0; c < nch; ++c) {
        __syncthreads();
        #pragma unroll
        for (int p = 0; p < 4; ++p) {
            int lin = p * 256 + tid;
            int row = lin >> 3;
            int c4  = lin & 7;
            float4 va = pa[p], vb = pb[p];
            va.x = to_tf32(va.x); va.y = to_tf32(va.y);
            va.z = to_tf32(va.z); va.w = to_tf32(va.w);
            vb.x = to_tf32(vb.x); vb.y = to_tf32(vb.y);
            vb.z = to_tf32(vb.z); vb.w = to_tf32(vb.w);
            *(float4*)&As[row][c4 * 4] = va;
            *(float4*)&Bs[row][c4 * 4] = vb;
        }
        __syncthreads();

        if (c + 1 < nch) {
            const int k0 = (c + 1) << 5;
            #pragma unroll
            for (int p = 0; p < 4; ++p) {
                int lin = p * 256 + tid;
                int row = lin >> 3;
                int c4  = lin & 7;
                pa[p] = *(const float4*)(A + (size_t)(m0 + row) * lda + k0 + c4 * 4);
                pb[p] = *(const float4*)(B + (size_t)(n0 + row) * ldb + k0 + c4 * 4);
            }
        }

        #pragma unroll
        for (int ks = 0; ks < 4; ++ks) {
            const int kk = ks * 8;
            uint32_t af[4][4], bf[4][2];
            #pragma unroll
            for (int mi = 0; mi < 4; ++mi) {
                int r = wm + mi * 16 + g;
                af[mi][0] = __float_as_uint(As[r][kk + t]);
                af[mi][1] = __float_as_uint(As[r + 8][kk + t]);
                af[mi][2] = __float_as_uint(As[r][kk + t + 4]);
                af[mi][3] = __float_as_uint(As[r + 8][kk + t + 4]);
            }
            #pragma unroll
            for (int ni = 0; ni < 4; ++ni) {
                int cn = wn + ni * 8 + g;
                bf[ni][0] = __float_as_uint(Bs[cn][kk + t]);
                bf[ni][1] = __float_as_uint(Bs[cn][kk + t + 4]);
            }
            #pragma unroll
            for (int mi = 0; mi < 4; ++mi)
                #pragma unroll
                for (int ni = 0; ni < 4; ++ni)
                    mma_tf32(acc[mi][ni], af[mi], bf[ni]);
        }
    }

    #pragma unroll
    for (int mi = 0; mi < 4; ++mi) {
        int r0 = m0 + wm + mi * 16 + g;
        #pragma unroll
        for (int ni = 0; ni < 4; ++ni) {
            int cc = n0 + wn + ni * 8 + t * 2;
            *(float2*)(C + (size_t)r0 * ldc + cc)       = make_float2(acc[mi][ni][0], acc[mi][ni][1]);
            *(float2*)(C + (size_t)(r0 + 8) * ldc + cc) = make_float2(acc[mi][ni][2], acc[mi][ni][3]);
        }
    }
}

// ================= transpose y[b][h][l] -> y_t[b][l][h] =================
__global__ void __launch_bounds__(256) transpose_kernel()
{
    __shared__ float tbuf[32][33];
    const int b  = blockIdx.z;
    const int l0 = blockIdx.x * 32;
    const int h0 = blockIdx.y * 32;
    const int tx = threadIdx.x, ty = threadIdx.y;

    const float* src = g_y + (size_t)b * DINNER * L_SEQ;
    float*       dst = g_yt + (size_t)b * L_SEQ * DINNER;
    #pragma unroll
    for (int i = 0; i < 4; ++i)
        tbuf[ty + i * 8][tx] = src[(size_t)(h0 + ty + i * 8) * L_SEQ + l0 + tx];
    __syncthreads();
    #pragma unroll
    for (int i = 0; i < 4; ++i)
        dst[(size_t)(l0 + ty + i * 8) * DINNER + h0 + tx] = tbuf[tx][ty + i * 8];
}

// ---------------- twiddle table ----------------
__global__ void twiddle_kernel() {
    int k = blockIdx.x * blockDim.x + threadIdx.x;
    if (k < NHALF) {
        float s, c;
        sincospif(2.0f * (float)k / (float)NFFT, &s, &c);
        g_tw[k] = make_float2(c, -s);
    }
}

// ---------------- complex helpers ----------------
__device__ __forceinline__ float2 cmul(float2 a, float2 b) {
    return make_float2(fmaf(a.x, b.x, -a.y * b.y), fmaf(a.x, b.y, a.y * b.x));
}
__device__ __forceinline__ float2 cadd(float2 a, float2 b) { return make_float2(a.x + b.x, a.y + b.y); }
__device__ __forceinline__ float2 csub(float2 a, float2 b) { return make_float2(a.x - b.x, a.y - b.y); }

// ---------------- FFT core: Stockham radix-8 (4 stages) + radix-2, 1024 thr --------
// sgn = +1 forward, -1 inverse (unscaled). All buffer indices SKW-mapped.
// padded: input nonzero only in [0, NHALF). halfOut: only outputs [0, NHALF).
__device__ float2* fft8192_r8(float2* src, float2* dst, const float2* __restrict__ tw,
                              float sgn, int tid, bool padded, bool halfOut)
{
    const float RH = 0.70710678118654752f;   // sqrt(2)/2

    // ---- 4 radix-8 stages: s = 1, 8, 64, 512; one butterfly per thread ----
    int s = 1;
    #pragma unroll 1
    for (int st = 0; st < 4; ++st) {
        const int sm1 = s - 1;
        {
            int i  = tid;                      // 0..1023 = N/8 butterflies
            int q  = i & sm1;
            int ps = i - q;

            float2 a0 = src[SKW(i)];
            float2 a1 = src[SKW(i + 1024)];
            float2 a2 = src[SKW(i + 2048)];
            float2 a3 = src[SKW(i + 3072)];

            float2 E0, E1, E2, E3, O0, O1, O2, O3;
            if (padded && st == 0) {
                float2 m2 = make_float2(sgn * a2.y, -sgn * a2.x);
                float2 m3 = make_float2(sgn * a3.y, -sgn * a3.x);
                E0 = cadd(a0, a2); E2 = csub(a0, a2);
                E1 = cadd(a0, m2); E3 = csub(a0, m2);
                O0 = cadd(a1, a3); O2 = csub(a1, a3);
                O1 = cadd(a1, m3); O3 = csub(a1, m3);
            } else {
                float2 a4 = src[SKW(i + 4096)];
                float2 a5 = src[SKW(i + 5120)];
                float2 a6 = src[SKW(i + 6144)];
                float2 a7 = src[SKW(i + 7168)];
                float2 t0 = cadd(a0, a4), t1 = csub(a0, a4);
                float2 t2 = cadd(a2, a6), t3 = csub(a2, a6);
                float2 m3e = make_float2(sgn * t3.y, -sgn * t3.x);
                E0 = cadd(t0, t2); E2 = csub(t0, t2);
                E1 = cadd(t1, m3e); E3 = csub(t1, m3e);
                float2 u0 = cadd(a1, a5), u1 = csub(a1, a5);
                float2 u2 = cadd(a3, a7), u3 = csub(a3, a7);
                float2 m3o = make_float2(sgn * u3.y, -sgn * u3.x);
                O0 = cadd(u0, u2); O2 = csub(u0, u2);
                O1 = cadd(u1, m3o); O3 = csub(u1, m3o);
            }

            float2 W1O = make_float2(RH * (O1.x + sgn * O1.y), RH * (O1.y - sgn * O1.x));
            float2 W2O = make_float2(sgn * O2.y, -sgn * O2.x);
            float2 W3O = make_float2(RH * (sgn * O3.y - O3.x), -RH * (O3.y + sgn * O3.x));

            float2 X0 = cadd(E0, O0),  X4 = csub(E0, O0);
            float2 X1 = cadd(E1, W1O), X5 = csub(E1, W1O);
            float2 X2 = cadd(E2, W2O), X6 = csub(E2, W2O);
            float2 X3 = cadd(E3, W3O), X7 = csub(E3, W3O);

            float2 w1 = tw[ps];     w1.y *= sgn;
            float2 w2 = tw[2 * ps]; w2.y *= sgn;
            float2 w4 = tw[4 * ps]; w4.y *= sgn;
            float2 w3 = cmul(w1, w2);
            float2 w5 = cmul(w1, w4);
            float2 w6 = cmul(w2, w4);
            float2 w7 = cmul(w3, w4);

            int o = q + 8 * ps;
            dst[SKW(o)]         = X0;
            dst[SKW(o + s)]     = cmul(X1, w1);
            dst[SKW(o + 2 * s)] = cmul(X2, w2);
            dst[SKW(o + 3 * s)] = cmul(X3, w3);
            dst[SKW(o + 4 * s)] = cmul(X4, w4);
            dst[SKW(o + 5 * s)] = cmul(X5, w5);
            dst[SKW(o + 6 * s)] = cmul(X6, w6);
            dst[SKW(o + 7 * s)] = cmul(X7, w7);
        }
        __syncthreads();
        float2* t = src; src = dst; dst = t;
        s <<= 3;
    }

    // ---- final radix-2, s = 4096, twiddle-free ----
    #pragma unroll
    for (int r = 0; r < 4; ++r) {
        int i = tid + r * NTHR;
        float2 a = src[SKW(i)];
        float2 b = src[SKW(i + NHALF)];
        dst[SKW(i)] = cadd(a, b);
        if (!halfOut) dst[SKW(i + NHALF)] = csub(a, b);
    }
    __syncthreads();
    return dst;
}

// ---------------- kernel spectra: two real channels per FFT (Re/Im packing) --------
#define SMEM_FFTK ((2 * SKWN + NHALF) * (int)sizeof(float2))
__global__ void __launch_bounds__(NTHR) fftk_kernel(const float* __restrict__ k_ssm)
{
    float2* buf0 = (float2*)s4_smem;
    float2* buf1 = buf0 + SKWN;
    float2* tws  = buf1 + SKWN;
    const int h0 = blockIdx.x * 2;
    const int tid = threadIdx.x;

    for (int i = tid; i < NHALF; i += NTHR) tws[i] = g_tw[i];
    const float* k0 = k_ssm + (size_t)h0 * L_SEQ;
    const float* k1 = k0 + L_SEQ;
    for (int l = tid; l < L_SEQ; l += NTHR)
        buf0[SKW(l)] = make_float2(k0[l], k1[l]);
    __syncthreads();

    float2* F = fft8192_r8(buf0, buf1, tws, 1.0f, tid, true, false);

    float2* H0 = g_Hf + (size_t)h0 * NFFT;
    float2* H1 = H0 + NFFT;
    for (int k = tid; k < NFFT; k += NTHR) {
        float2 Fk = F[SKW(k)];
        float2 Fn = F[SKW((NFFT - k) & (NFFT - 1))];
        H0[k] = make_float2(0.5f * (Fk.x + Fn.x), 0.5f * (Fk.y - Fn.y));
        float2 Bd = make_float2(Fk.x - Fn.x, Fk.y + Fn.y);
        H1[k] = make_float2(0.5f * Bd.y, -0.5f * Bd.x);
    }
}

// ------- fused: conv4+SiLU -> batch-packed FFT conv -> D_skip -> *SiLU(z) -------
#define SMEM_CONV ((2 * SKWN + NHALF + L_SEQ) * (int)sizeof(float2))
__global__ void __launch_bounds__(NTHR) convfft_kernel(const float* __restrict__ conv_w,
                                                       const float* __restrict__ conv_b,
                                                       const float* __restrict__ D_skip)
{
    float2* buf0 = (float2*)s4_smem;
    float2* buf1 = buf0 + SKWN;
    float2* tws  = buf1 + SKWN;
    float2* xs   = tws + NHALF;

    const int h   = blockIdx.x;
    const int tid = threadIdx.x;

    for (int i = tid; i < NHALF; i += NTHR) tws[i] = g_tw[i];

    const float w0 = conv_w[h * 4 + 0];
    const float w1 = conv_w[h * 4 + 1];
    const float w2 = conv_w[h * 4 + 2];
    const float w3 = conv_w[h * 4 + 3];
    const float cb = conv_b[h];

    const float* gx0 = g_xz + (size_t)h * L_SEQ;
    const float* gx1 = g_xz + ((size_t)EDIM + h) * L_SEQ;
    for (int l = tid; l < L_SEQ; l += NTHR) {
        float a0 = fmaf(w3, gx0[l], cb);
        float a1 = fmaf(w3, gx1[l], cb);
        if (l >= 1) { a0 = fmaf(w2, gx0[l - 1], a0); a1 = fmaf(w2, gx1[l - 1], a1); }
        if (l >= 2) { a0 = fmaf(w1, gx0[l - 2], a0); a1 = fmaf(w1, gx1[l - 2], a1); }
        if (l >= 3) { a0 = fmaf(w0, gx0[l - 3], a0); a1 = fmaf(w0, gx1[l - 3], a1); }
        float v0 = a0 / (1.0f + expf(-a0));
        float v1 = a1 / (1.0f + expf(-a1));
        float2 v = make_float2(v0, v1);
        xs[l]        = v;
        buf0[SKW(l)] = v;
    }
    __syncthreads();

    float2* r1 = fft8192_r8(buf0, buf1, tws, 1.0f, tid, true, false);

    const float2* __restrict__ Hrow = g_Hf + (size_t)h * NFFT;
    for (int i = tid; i < NFFT; i += NTHR) {
        float2 v = r1[SKW(i)];
        r1[SKW(i)] = cmul(v, Hrow[i]);
    }
    __syncthreads();

    float2* other = (r1 == buf0) ? buf1 : buf0;
    float2* r2 = fft8192_r8(r1, other, tws, -1.0f, tid, false, true);

    const float dsk = D_skip[h];
    const float* gz0 = g_xz + ((size_t)DINNER + h) * L_SEQ;
    const float* gz1 = g_xz + ((size_t)EDIM + DINNER + h) * L_SEQ;
    float*       gy0 = g_y  + (size_t)h * L_SEQ;
    float*       gy1 = g_y  + ((size_t)DINNER + h) * L_SEQ;
    const float invn = 1.0f / (float)NFFT;
    for (int l = tid; l < L_SEQ; l += NTHR) {
        float2 xv = xs[l];
        float2 rv = r2[SKW(l)];
        float y0 = fmaf(rv.x, invn, dsk * xv.x);
        float y1 = fmaf(rv.y, invn, dsk * xv.y);
        float z0 = gz0[l];
        float z1 = gz1[l];
        gy0[l] = y0 * (z0 / (1.0f + expf(-z0)));
        gy1[l] = y1 * (z1 / (1.0f + expf(-z1)));
    }
}

// ---------------- launch ----------------
extern "C" void kernel_launch(void* const* d_in, const int* in_sizes, int n_in,
                              void* d_out, int out_size)
{
    (void)in_sizes; (void)n_in; (void)out_size;
    const float* hs     = (const float*)d_in[0];
    const float* W_in   = (const float*)d_in[1];
    const float* conv_w = (const float*)d_in[2];
    const float* conv_b = (const float*)d_in[3];
    const float* k_ssm  = (const float*)d_in[4];
    const float* D_skip = (const float*)d_in[5];
    const float* W_out  = (const float*)d_in[6];
    float* out = (float*)d_out;

    cudaFuncSetAttribute(fftk_kernel,    cudaFuncAttributeMaxDynamicSharedMemorySize, SMEM_FFTK);
    cudaFuncSetAttribute(convfft_kernel, cudaFuncAttributeMaxDynamicSharedMemorySize, SMEM_CONV);

    float* xz = nullptr; cudaGetSymbolAddress((void**)&xz, g_xz);
    float* yt = nullptr; cudaGetSymbolAddress((void**)&yt, g_yt);

    twiddle_kernel<<<NHALF / 512, 512>>>();

    // GEMM1: xz[b][e][l] = sum_d W_in[e][d] * hs[b][l][d]
    gemm_mma<<<dim3(L_SEQ / 128, EDIM / 128, BATCH), 256>>>(
        W_in, hs, xz, DMODEL, DMODEL, L_SEQ, DMODEL,
        0LL, (long long)L_SEQ * DMODEL, (long long)EDIM * L_SEQ);

    fftk_kernel<<<DINNER / 2, NTHR, SMEM_FFTK>>>(k_ssm);
    convfft_kernel<<<DINNER, NTHR, SMEM_CONV>>>(conv_w, conv_b, D_skip);

    transpose_kernel<<<dim3(L_SEQ / 32, DINNER / 32, BATCH), dim3(32, 8)>>>();

    // GEMM2: out[b][l][d] = sum_h y_t[b][l][h] * W_out[d][h]
    gemm_mma<<<dim3(DMODEL / 128, L_SEQ / 128, BATCH), 256>>>(
        yt, W_out, out, DINNER, DINNER, DMODEL, DINNER,
        (long long)L_SEQ * DINNER, 0LL, (long long)L_SEQ * DMODEL);
}

// round 8
// speedup vs baseline: 3.2327x; 1.0521x over previous
#include <cuda_runtime.h>
#include <cuda_fp16.h>
#include <math.h>
#include <stdint.h>

// ---------------- problem constants ----------------
#define L_SEQ   4096
#define DMODEL  1024
#define DINNER  2048
#define EDIM    (2*DINNER)   // 4096
#define BATCH   2
#define NFFT    8192
#define NHALF   (NFFT/2)     // 4096
#define NTHR    1024         // FFT kernel block size

// skewed smem addressing for FFT buffers: linear conflict-free, strided <=2-way
#define SKW(i)  ((i) + ((i) >> 4))
#define SKWN    (NFFT + NFFT/16)     // 8704 float2 per buffer

// single dynamic shared-memory declaration (consistent type across kernels)
extern __shared__ char s4_smem[];

// ---------------- scratch (device globals; allocation-free launch) ----------------
__device__ float  g_xz[(unsigned long long)BATCH * EDIM * L_SEQ];     // [b][e][l]
__device__ float  g_y [(unsigned long long)BATCH * DINNER * L_SEQ];   // [b][h][l]
__device__ float  g_yt[(unsigned long long)BATCH * L_SEQ * DINNER];   // [b][l][h]
__device__ float2 g_Hf[(unsigned long long)DINNER * NFFT];            // kernel spectra
__device__ float2 g_tw[NHALF];                                        // exp(-2*pi*i*k/N)

// ---------------- fp16 mma helper ----------------
__device__ __forceinline__ void mma_f16(float* d, const uint32_t* a, const uint32_t* b) {
    asm volatile(
        "mma.sync.aligned.m16n8k16.row.col.f32.f16.f16.f32 "
        "{%0,%1,%2,%3}, {%4,%5,%6,%7}, {%8,%9}, {%0,%1,%2,%3};"
        : "+f"(d[0]), "+f"(d[1]), "+f"(d[2]), "+f"(d[3])
        : "r"(a[0]), "r"(a[1]), "r"(a[2]), "r"(a[3]), "r"(b[0]), "r"(b[1]));
}

// ================= fp16 mma.sync GEMM (fp32 accumulate) =================
// C[m][n] = sum_k A[m*lda+k] * B[n*ldb+k]  (both K-contiguous, NT)
// CTA tile 128x128, 8 warps (2 M x 4 N), warp tile 64x32, mma m16n8k16.
__global__ void __launch_bounds__(256) gemm_mma(const float* __restrict__ A,
                                                const float* __restrict__ B,
                                                float* __restrict__ C,
                                                int lda, int ldb, int ldc, int K,
                                                long long aBatch, long long bBatch,
                                                long long cBatch)
{
    __shared__ __half As[128][36];   // 32 k-halves + pad 4 (72B rows)
    __shared__ __half Bs[128][36];

    A += (size_t)blockIdx.z * aBatch;
    B += (size_t)blockIdx.z * bBatch;
    C += (size_t)blockIdx.z * cBatch;
    const int m0 = blockIdx.y * 128;
    const int n0 = blockIdx.x * 128;

    const int tid  = threadIdx.x;
    const int wid  = tid >> 5;
    const int lane = tid & 31;
    const int wm   = (wid >> 2) * 64;
    const int wn   = (wid & 3) * 32;
    const int g    = lane >> 2;      // 0..7
    const int t    = lane & 3;       // 0..3

    float acc[4][4][4];
    #pragma unroll
    for (int mi = 0; mi < 4; ++mi)
        #pragma unroll
        for (int ni = 0; ni < 4; ++ni)
            #pragma unroll
            for (int r = 0; r < 4; ++r) acc[mi][ni][r] = 0.f;

    const int nch = K >> 5;          // chunks of 32 k
    float4 pa[4], pb[4];

    #pragma unroll
    for (int p = 0; p < 4; ++p) {
        int lin = p * 256 + tid;
        int row = lin >> 3;
        int c4  = lin & 7;
        pa[p] = *(const float4*)(A + (size_t)(m0 + row) * lda + c4 * 4);
        pb[p] = *(const float4*)(B + (size_t)(n0 + row) * ldb + c4 * 4);
    }

    for (int c = 0; c < nch; ++c) {
        __syncthreads();
        #pragma unroll
        for (int p = 0; p < 4; ++p) {
            int lin = p * 256 + tid;
            int row = lin >> 3;
            int c4  = lin & 7;
            float4 va = pa[p], vb = pb[p];
            __half2 a01 = __floats2half2_rn(va.x, va.y);
            __half2 a23 = __floats2half2_rn(va.z, va.w);
            __half2 b01 = __floats2half2_rn(vb.x, vb.y);
            __half2 b23 = __floats2half2_rn(vb.z, vb.w);
            *(uint2*)&As[row][c4 * 4] =
                make_uint2(*(uint32_t*)&a01, *(uint32_t*)&a23);
            *(uint2*)&Bs[row][c4 * 4] =
                make_uint2(*(uint32_t*)&b01, *(uint32_t*)&b23);
        }
        __syncthreads();

        if (c + 1 < nch) {
            const int k0 = (c + 1) << 5;
            #pragma unroll
            for (int p = 0; p < 4; ++p) {
                int lin = p * 256 + tid;
                int row = lin >> 3;
                int c4  = lin & 7;
                pa[p] = *(const float4*)(A + (size_t)(m0 + row) * lda + k0 + c4 * 4);
                pb[p] = *(const float4*)(B + (size_t)(n0 + row) * ldb + k0 + c4 * 4);
            }
        }

        #pragma unroll
        for (int ks = 0; ks < 2; ++ks) {          // two k16 steps per 32-chunk
            const int kk = ks * 16;
            uint32_t af[4][4], bf[4][2];
            #pragma unroll
            for (int mi = 0; mi < 4; ++mi) {
                int r = wm + mi * 16 + g;
                af[mi][0] = *(const uint32_t*)&As[r][kk + 2 * t];
                af[mi][1] = *(const uint32_t*)&As[r + 8][kk + 2 * t];
                af[mi][2] = *(const uint32_t*)&As[r][kk + 2 * t + 8];
                af[mi][3] = *(const uint32_t*)&As[r + 8][kk + 2 * t + 8];
            }
            #pragma unroll
            for (int ni = 0; ni < 4; ++ni) {
                int cn = wn + ni * 8 + g;
                bf[ni][0] = *(const uint32_t*)&Bs[cn][kk + 2 * t];
                bf[ni][1] = *(const uint32_t*)&Bs[cn][kk + 2 * t + 8];
            }
            #pragma unroll
            for (int mi = 0; mi < 4; ++mi)
                #pragma unroll
                for (int ni = 0; ni < 4; ++ni)
                    mma_f16(acc[mi][ni], af[mi], bf[ni]);
        }
    }

    #pragma unroll
    for (int mi = 0; mi < 4; ++mi) {
        int r0 = m0 + wm + mi * 16 + g;
        #pragma unroll
        for (int ni = 0; ni < 4; ++ni) {
            int cc = n0 + wn + ni * 8 + t * 2;
            *(float2*)(C + (size_t)r0 * ldc + cc)       = make_float2(acc[mi][ni][0], acc[mi][ni][1]);
            *(float2*)(C + (size_t)(r0 + 8) * ldc + cc) = make_float2(acc[mi][ni][2], acc[mi][ni][3]);
        }
    }
}

// ================= transpose y[b][h][l] -> y_t[b][l][h] =================
__global__ void __launch_bounds__(256) transpose_kernel()
{
    __shared__ float tbuf[32][33];
    const int b  = blockIdx.z;
    const int l0 = blockIdx.x * 32;
    const int h0 = blockIdx.y * 32;
    const int tx = threadIdx.x, ty = threadIdx.y;

    const float* src = g_y + (size_t)b * DINNER * L_SEQ;
    float*       dst = g_yt + (size_t)b * L_SEQ * DINNER;
    #pragma unroll
    for (int i = 0; i < 4; ++i)
        tbuf[ty + i * 8][tx] = src[(size_t)(h0 + ty + i * 8) * L_SEQ + l0 + tx];
    __syncthreads();
    #pragma unroll
    for (int i = 0; i < 4; ++i)
        dst[(size_t)(l0 + ty + i * 8) * DINNER + h0 + tx] = tbuf[tx][ty + i * 8];
}

// ---------------- twiddle table ----------------
__global__ void twiddle_kernel() {
    int k = blockIdx.x * blockDim.x + threadIdx.x;
    if (k < NHALF) {
        float s, c;
        sincospif(2.0f * (float)k / (float)NFFT, &s, &c);
        g_tw[k] = make_float2(c, -s);
    }
}

// ---------------- complex helpers ----------------
__device__ __forceinline__ float2 cmul(float2 a, float2 b) {
    return make_float2(fmaf(a.x, b.x, -a.y * b.y), fmaf(a.x, b.y, a.y * b.x));
}
__device__ __forceinline__ float2 cadd(float2 a, float2 b) { return make_float2(a.x + b.x, a.y + b.y); }
__device__ __forceinline__ float2 csub(float2 a, float2 b) { return make_float2(a.x - b.x, a.y - b.y); }

// ---------------- FFT core: Stockham radix-8 (4 stages) + radix-2, 1024 thr --------
__device__ float2* fft8192_r8(float2* src, float2* dst, const float2* __restrict__ tw,
                              float sgn, int tid, bool padded, bool halfOut)
{
    const float RH = 0.70710678118654752f;

    int s = 1;
    #pragma unroll 1
    for (int st = 0; st < 4; ++st) {
        const int sm1 = s - 1;
        {
            int i  = tid;
            int q  = i & sm1;
            int ps = i - q;

            float2 a0 = src[SKW(i)];
            float2 a1 = src[SKW(i + 1024)];
            float2 a2 = src[SKW(i + 2048)];
            float2 a3 = src[SKW(i + 3072)];

            float2 E0, E1, E2, E3, O0, O1, O2, O3;
            if (padded && st == 0) {
                float2 m2 = make_float2(sgn * a2.y, -sgn * a2.x);
                float2 m3 = make_float2(sgn * a3.y, -sgn * a3.x);
                E0 = cadd(a0, a2); E2 = csub(a0, a2);
                E1 = cadd(a0, m2); E3 = csub(a0, m2);
                O0 = cadd(a1, a3); O2 = csub(a1, a3);
                O1 = cadd(a1, m3); O3 = csub(a1, m3);
            } else {
                float2 a4 = src[SKW(i + 4096)];
                float2 a5 = src[SKW(i + 5120)];
                float2 a6 = src[SKW(i + 6144)];
                float2 a7 = src[SKW(i + 7168)];
                float2 t0 = cadd(a0, a4), t1 = csub(a0, a4);
                float2 t2 = cadd(a2, a6), t3 = csub(a2, a6);
                float2 m3e = make_float2(sgn * t3.y, -sgn * t3.x);
                E0 = cadd(t0, t2); E2 = csub(t0, t2);
                E1 = cadd(t1, m3e); E3 = csub(t1, m3e);
                float2 u0 = cadd(a1, a5), u1 = csub(a1, a5);
                float2 u2 = cadd(a3, a7), u3 = csub(a3, a7);
                float2 m3o = make_float2(sgn * u3.y, -sgn * u3.x);
                O0 = cadd(u0, u2); O2 = csub(u0, u2);
                O1 = cadd(u1, m3o); O3 = csub(u1, m3o);
            }

            float2 W1O = make_float2(RH * (O1.x + sgn * O1.y), RH * (O1.y - sgn * O1.x));
            float2 W2O = make_float2(sgn * O2.y, -sgn * O2.x);
            float2 W3O = make_float2(RH * (sgn * O3.y - O3.x), -RH * (O3.y + sgn * O3.x));

            float2 X0 = cadd(E0, O0),  X4 = csub(E0, O0);
            float2 X1 = cadd(E1, W1O), X5 = csub(E1, W1O);
            float2 X2 = cadd(E2, W2O), X6 = csub(E2, W2O);
            float2 X3 = cadd(E3, W3O), X7 = csub(E3, W3O);

            float2 w1 = tw[ps];     w1.y *= sgn;
            float2 w2 = tw[2 * ps]; w2.y *= sgn;
            float2 w4 = tw[4 * ps]; w4.y *= sgn;
            float2 w3 = cmul(w1, w2);
            float2 w5 = cmul(w1, w4);
            float2 w6 = cmul(w2, w4);
            float2 w7 = cmul(w3, w4);

            int o = q + 8 * ps;
            dst[SKW(o)]         = X0;
            dst[SKW(o + s)]     = cmul(X1, w1);
            dst[SKW(o + 2 * s)] = cmul(X2, w2);
            dst[SKW(o + 3 * s)] = cmul(X3, w3);
            dst[SKW(o + 4 * s)] = cmul(X4, w4);
            dst[SKW(o + 5 * s)] = cmul(X5, w5);
            dst[SKW(o + 6 * s)] = cmul(X6, w6);
            dst[SKW(o + 7 * s)] = cmul(X7, w7);
        }
        __syncthreads();
        float2* t = src; src = dst; dst = t;
        s <<= 3;
    }

    #pragma unroll
    for (int r = 0; r < 4; ++r) {
        int i = tid + r * NTHR;
        float2 a = src[SKW(i)];
        float2 b = src[SKW(i + NHALF)];
        dst[SKW(i)] = cadd(a, b);
        if (!halfOut) dst[SKW(i + NHALF)] = csub(a, b);
    }
    __syncthreads();
    return dst;
}

// ---------------- kernel spectra: two real channels per FFT (Re/Im packing) --------
#define SMEM_FFTK ((2 * SKWN + NHALF) * (int)sizeof(float2))
__global__ void __launch_bounds__(NTHR) fftk_kernel(const float* __restrict__ k_ssm)
{
    float2* buf0 = (float2*)s4_smem;
    float2* buf1 = buf0 + SKWN;
    float2* tws  = buf1 + SKWN;
    const int h0 = blockIdx.x * 2;
    const int tid = threadIdx.x;

    for (int i = tid; i < NHALF; i += NTHR) tws[i] = g_tw[i];
    const float* k0 = k_ssm + (size_t)h0 * L_SEQ;
    const float* k1 = k0 + L_SEQ;
    for (int l = tid; l < L_SEQ; l += NTHR)
        buf0[SKW(l)] = make_float2(k0[l], k1[l]);
    __syncthreads();

    float2* F = fft8192_r8(buf0, buf1, tws, 1.0f, tid, true, false);

    float2* H0 = g_Hf + (size_t)h0 * NFFT;
    float2* H1 = H0 + NFFT;
    for (int k = tid; k < NFFT; k += NTHR) {
        float2 Fk = F[SKW(k)];
        float2 Fn = F[SKW((NFFT - k) & (NFFT - 1))];
        H0[k] = make_float2(0.5f * (Fk.x + Fn.x), 0.5f * (Fk.y - Fn.y));
        float2 Bd = make_float2(Fk.x - Fn.x, Fk.y + Fn.y);
        H1[k] = make_float2(0.5f * Bd.y, -0.5f * Bd.x);
    }
}

// ------- fused: conv4+SiLU -> batch-packed FFT conv -> D_skip -> *SiLU(z) -------
#define SMEM_CONV ((2 * SKWN + NHALF + L_SEQ) * (int)sizeof(float2))
__global__ void __launch_bounds__(NTHR) convfft_kernel(const float* __restrict__ conv_w,
                                                       const float* __restrict__ conv_b,
                                                       const float* __restrict__ D_skip)
{
    float2* buf0 = (float2*)s4_smem;
    float2* buf1 = buf0 + SKWN;
    float2* tws  = buf1 + SKWN;
    float2* xs   = tws + NHALF;

    const int h   = blockIdx.x;
    const int tid = threadIdx.x;

    for (int i = tid; i < NHALF; i += NTHR) tws[i] = g_tw[i];

    const float w0 = conv_w[h * 4 + 0];
    const float w1 = conv_w[h * 4 + 1];
    const float w2 = conv_w[h * 4 + 2];
    const float w3 = conv_w[h * 4 + 3];
    const float cb = conv_b[h];

    const float* gx0 = g_xz + (size_t)h * L_SEQ;
    const float* gx1 = g_xz + ((size_t)EDIM + h) * L_SEQ;
    for (int l = tid; l < L_SEQ; l += NTHR) {
        float a0 = fmaf(w3, gx0[l], cb);
        float a1 = fmaf(w3, gx1[l], cb);
        if (l >= 1) { a0 = fmaf(w2, gx0[l - 1], a0); a1 = fmaf(w2, gx1[l - 1], a1); }
        if (l >= 2) { a0 = fmaf(w1, gx0[l - 2], a0); a1 = fmaf(w1, gx1[l - 2], a1); }
        if (l >= 3) { a0 = fmaf(w0, gx0[l - 3], a0); a1 = fmaf(w0, gx1[l - 3], a1); }
        float v0 = a0 / (1.0f + expf(-a0));
        float v1 = a1 / (1.0f + expf(-a1));
        float2 v = make_float2(v0, v1);
        xs[l]        = v;
        buf0[SKW(l)] = v;
    }
    __syncthreads();

    float2* r1 = fft8192_r8(buf0, buf1, tws, 1.0f, tid, true, false);

    const float2* __restrict__ Hrow = g_Hf + (size_t)h * NFFT;
    for (int i = tid; i < NFFT; i += NTHR) {
        float2 v = r1[SKW(i)];
        r1[SKW(i)] = cmul(v, Hrow[i]);
    }
    __syncthreads();

    float2* other = (r1 == buf0) ? buf1 : buf0;
    float2* r2 = fft8192_r8(r1, other, tws, -1.0f, tid, false, true);

    const float dsk = D_skip[h];
    const float* gz0 = g_xz + ((size_t)DINNER + h) * L_SEQ;
    const float* gz1 = g_xz + ((size_t)EDIM + DINNER + h) * L_SEQ;
    float*       gy0 = g_y  + (size_t)h * L_SEQ;
    float*       gy1 = g_y  + ((size_t)DINNER + h) * L_SEQ;
    const float invn = 1.0f / (float)NFFT;
    for (int l = tid; l < L_SEQ; l += NTHR) {
        float2 xv = xs[l];
        float2 rv = r2[SKW(l)];
        float y0 = fmaf(rv.x, invn, dsk * xv.x);
        float y1 = fmaf(rv.y, invn, dsk * xv.y);
        float z0 = gz0[l];
        float z1 = gz1[l];
        gy0[l] = y0 * (z0 / (1.0f + expf(-z0)));
        gy1[l] = y1 * (z1 / (1.0f + expf(-z1)));
    }
}

// ---------------- launch ----------------
extern "C" void kernel_launch(void* const* d_in, const int* in_sizes, int n_in,
                              void* d_out, int out_size)
{
    (void)in_sizes; (void)n_in; (void)out_size;
    const float* hs     = (const float*)d_in[0];
    const float* W_in   = (const float*)d_in[1];
    const float* conv_w = (const float*)d_in[2];
    const float* conv_b = (const float*)d_in[3];
    const float* k_ssm  = (const float*)d_in[4];
    const float* D_skip = (const float*)d_in[5];
    const float* W_out  = (const float*)d_in[6];
    float* out = (float*)d_out;

    cudaFuncSetAttribute(fftk_kernel,    cudaFuncAttributeMaxDynamicSharedMemorySize, SMEM_FFTK);
    cudaFuncSetAttribute(convfft_kernel, cudaFuncAttributeMaxDynamicSharedMemorySize, SMEM_CONV);

    float* xz = nullptr; cudaGetSymbolAddress((void**)&xz, g_xz);
    float* yt = nullptr; cudaGetSymbolAddress((void**)&yt, g_yt);

    twiddle_kernel<<<NHALF / 512, 512>>>();

    // GEMM1: xz[b][e][l] = sum_d W_in[e][d] * hs[b][l][d]
    gemm_mma<<<dim3(L_SEQ / 128, EDIM / 128, BATCH), 256>>>(
        W_in, hs, xz, DMODEL, DMODEL, L_SEQ, DMODEL,
        0LL, (long long)L_SEQ * DMODEL, (long long)EDIM * L_SEQ);

    fftk_kernel<<<DINNER / 2, NTHR, SMEM_FFTK>>>(k_ssm);
    convfft_kernel<<<DINNER, NTHR, SMEM_CONV>>>(conv_w, conv_b, D_skip);

    transpose_kernel<<<dim3(L_SEQ / 32, DINNER / 32, BATCH), dim3(32, 8)>>>();

    // GEMM2: out[b][l][d] = sum_h y_t[b][l][h] * W_out[d][h]
    gemm_mma<<<dim3(DMODEL / 128, L_SEQ / 128, BATCH), 256>>>(
        yt, W_out, out, DINNER, DINNER, DMODEL, DINNER,
        (long long)L_SEQ * DINNER, 0LL, (long long)L_SEQ * DMODEL);
}

// round 9
// speedup vs baseline: 3.6755x; 1.1370x over previous
#include <cuda_runtime.h>
#include <cuda_fp16.h>
#include <math.h>
#include <stdint.h>

// ---------------- problem constants ----------------
#define L_SEQ   4096
#define DMODEL  1024
#define DINNER  2048
#define EDIM    (2*DINNER)   // 4096
#define BATCH   2
#define NFFT    8192
#define NHALF   (NFFT/2)     // 4096
#define NTHR    1024         // FFT kernel block size

// skewed smem addressing for FFT buffers: linear conflict-free, strided <=2-way
#define SKW(i)  ((i) + ((i) >> 4))
#define SKWN    (NFFT + NFFT/16)     // 8704 float2 per buffer

// single dynamic shared-memory declaration (consistent type across kernels)
extern __shared__ char s4_smem[];

// ---------------- scratch (device globals; allocation-free launch) ----------------
__device__ float  g_xz[(unsigned long long)BATCH * EDIM * L_SEQ];     // [b][e][l]
__device__ float  g_y [(unsigned long long)BATCH * DINNER * L_SEQ];   // [b][h][l]
__device__ float  g_yt[(unsigned long long)BATCH * L_SEQ * DINNER];   // [b][l][h]
__device__ float2 g_Hf[(unsigned long long)DINNER * NFFT];            // kernel spectra
__device__ float2 g_tw[NHALF];                                        // exp(-2*pi*i*k/N)

// ---------------- mma / ldmatrix helpers ----------------
__device__ __forceinline__ void mma_f16(float* d, const uint32_t* a, const uint32_t* b) {
    asm volatile(
        "mma.sync.aligned.m16n8k16.row.col.f32.f16.f16.f32 "
        "{%0,%1,%2,%3}, {%4,%5,%6,%7}, {%8,%9}, {%0,%1,%2,%3};"
        : "+f"(d[0]), "+f"(d[1]), "+f"(d[2]), "+f"(d[3])
        : "r"(a[0]), "r"(a[1]), "r"(a[2]), "r"(a[3]), "r"(b[0]), "r"(b[1]));
}
__device__ __forceinline__ void ldsm_x4(uint32_t* r, uint32_t saddr) {
    asm volatile("ldmatrix.sync.aligned.m8n8.x4.shared.b16 {%0,%1,%2,%3}, [%4];"
                 : "=r"(r[0]), "=r"(r[1]), "=r"(r[2]), "=r"(r[3]) : "r"(saddr));
}

// ================= fp16 mma.sync GEMM, ldmatrix + double buffer =================
// C[m][n] = sum_k A[m*lda+k] * B[n*ldb+k]  (both K-contiguous, NT)
// CTA tile 128x128, 8 warps (2 M x 4 N), warp tile 64x32, mma m16n8k16.
#define GPITCH 40   // halves per smem row (80B = 20 banks: ldmatrix conflict-free)

__global__ void __launch_bounds__(256) gemm_mma(const float* __restrict__ A,
                                                const float* __restrict__ B,
                                                float* __restrict__ C,
                                                int lda, int ldb, int ldc, int K,
                                                long long aBatch, long long bBatch,
                                                long long cBatch)
{
    __shared__ __half As[2][128][GPITCH];
    __shared__ __half Bs[2][128][GPITCH];

    A += (size_t)blockIdx.z * aBatch;
    B += (size_t)blockIdx.z * bBatch;
    C += (size_t)blockIdx.z * cBatch;
    const int m0 = blockIdx.y * 128;
    const int n0 = blockIdx.x * 128;

    const int tid  = threadIdx.x;
    const int wid  = tid >> 5;
    const int lane = tid & 31;
    const int wm   = (wid >> 2) * 64;
    const int wn   = (wid & 3) * 32;
    const int g    = lane >> 2;      // 0..7
    const int t    = lane & 3;       // 0..3

    // ldmatrix source rows/cols (per lane)
    const int aRow = (lane & 15);            // + wm + mi*16
    const int aCol = (lane >> 4) * 8;        // + kk
    const int bRow = (lane & 7) + ((lane >> 4) << 3);   // + wn + ni*8 (ni even pair)
    const int bCol = ((lane >> 3) & 1) * 8;  // + kk

    float acc[4][4][4];
    #pragma unroll
    for (int mi = 0; mi < 4; ++mi)
        #pragma unroll
        for (int ni = 0; ni < 4; ++ni)
            #pragma unroll
            for (int r = 0; r < 4; ++r) acc[mi][ni][r] = 0.f;

    const int nch = K >> 5;          // chunks of 32 k
    const int lrow = tid >> 3;       // 0..31 (row block per phase)
    const int lc4  = tid & 7;        // float4 index within 32 floats

    float4 pa[4], pb[4];
    #pragma unroll
    for (int p = 0; p < 4; ++p) {
        int row = lrow + p * 32;
        pa[p] = *(const float4*)(A + (size_t)(m0 + row) * lda + lc4 * 4);
        pb[p] = *(const float4*)(B + (size_t)(n0 + row) * ldb + lc4 * 4);
    }
    // store chunk 0 -> buf 0
    #pragma unroll
    for (int p = 0; p < 4; ++p) {
        int row = lrow + p * 32;
        __half2 a01 = __floats2half2_rn(pa[p].x, pa[p].y);
        __half2 a23 = __floats2half2_rn(pa[p].z, pa[p].w);
        __half2 b01 = __floats2half2_rn(pb[p].x, pb[p].y);
        __half2 b23 = __floats2half2_rn(pb[p].z, pb[p].w);
        *(uint2*)&As[0][row][lc4 * 4] = make_uint2(*(uint32_t*)&a01, *(uint32_t*)&a23);
        *(uint2*)&Bs[0][row][lc4 * 4] = make_uint2(*(uint32_t*)&b01, *(uint32_t*)&b23);
    }
    __syncthreads();

    for (int c = 0; c < nch; ++c) {
        const int buf = c & 1;

        if (c + 1 < nch) {
            const int k0 = (c + 1) << 5;
            #pragma unroll
            for (int p = 0; p < 4; ++p) {
                int row = lrow + p * 32;
                pa[p] = *(const float4*)(A + (size_t)(m0 + row) * lda + k0 + lc4 * 4);
                pb[p] = *(const float4*)(B + (size_t)(n0 + row) * ldb + k0 + lc4 * 4);
            }
        }

        #pragma unroll
        for (int ks = 0; ks < 2; ++ks) {
            const int kk = ks * 16;
            uint32_t af[4][4], bf[4][4];
            #pragma unroll
            for (int mi = 0; mi < 4; ++mi) {
                uint32_t sa = (uint32_t)__cvta_generic_to_shared(
                    &As[buf][wm + mi * 16 + aRow][kk + aCol]);
                ldsm_x4(af[mi], sa);
            }
            #pragma unroll
            for (int np = 0; np < 2; ++np) {     // ni pairs (0,1) and (2,3)
                uint32_t sb = (uint32_t)__cvta_generic_to_shared(
                    &Bs[buf][wn + np * 16 + bRow][kk + bCol]);
                ldsm_x4(bf[np * 2], sb);         // fills bf[2np][0..1]=ni, [2..3]->ni+1
                bf[np * 2 + 1][0] = bf[np * 2][2];
                bf[np * 2 + 1][1] = bf[np * 2][3];
            }
            #pragma unroll
            for (int mi = 0; mi < 4; ++mi)
                #pragma unroll
                for (int ni = 0; ni < 4; ++ni)
                    mma_f16(acc[mi][ni], af[mi], bf[ni]);
        }

        if (c + 1 < nch) {
            const int nb = (c + 1) & 1;
            #pragma unroll
            for (int p = 0; p < 4; ++p) {
                int row = lrow + p * 32;
                __half2 a01 = __floats2half2_rn(pa[p].x, pa[p].y);
                __half2 a23 = __floats2half2_rn(pa[p].z, pa[p].w);
                __half2 b01 = __floats2half2_rn(pb[p].x, pb[p].y);
                __half2 b23 = __floats2half2_rn(pb[p].z, pb[p].w);
                *(uint2*)&As[nb][row][lc4 * 4] = make_uint2(*(uint32_t*)&a01, *(uint32_t*)&a23);
                *(uint2*)&Bs[nb][row][lc4 * 4] = make_uint2(*(uint32_t*)&b01, *(uint32_t*)&b23);
            }
            __syncthreads();
        }
    }

    #pragma unroll
    for (int mi = 0; mi < 4; ++mi) {
        int r0 = m0 + wm + mi * 16 + g;
        #pragma unroll
        for (int ni = 0; ni < 4; ++ni) {
            int cc = n0 + wn + ni * 8 + t * 2;
            *(float2*)(C + (size_t)r0 * ldc + cc)       = make_float2(acc[mi][ni][0], acc[mi][ni][1]);
            *(float2*)(C + (size_t)(r0 + 8) * ldc + cc) = make_float2(acc[mi][ni][2], acc[mi][ni][3]);
        }
    }
}

// ================= transpose y[b][h][l] -> y_t[b][l][h] =================
__global__ void __launch_bounds__(256) transpose_kernel()
{
    __shared__ float tbuf[32][33];
    const int b  = blockIdx.z;
    const int l0 = blockIdx.x * 32;
    const int h0 = blockIdx.y * 32;
    const int tx = threadIdx.x, ty = threadIdx.y;

    const float* src = g_y + (size_t)b * DINNER * L_SEQ;
    float*       dst = g_yt + (size_t)b * L_SEQ * DINNER;
    #pragma unroll
    for (int i = 0; i < 4; ++i)
        tbuf[ty + i * 8][tx] = src[(size_t)(h0 + ty + i * 8) * L_SEQ + l0 + tx];
    __syncthreads();
    #pragma unroll
    for (int i = 0; i < 4; ++i)
        dst[(size_t)(l0 + ty + i * 8) * DINNER + h0 + tx] = tbuf[tx][ty + i * 8];
}

// ---------------- twiddle table ----------------
__global__ void twiddle_kernel() {
    int k = blockIdx.x * blockDim.x + threadIdx.x;
    if (k < NHALF) {
        float s, c;
        sincospif(2.0f * (float)k / (float)NFFT, &s, &c);
        g_tw[k] = make_float2(c, -s);
    }
}

// ---------------- complex helpers ----------------
__device__ __forceinline__ float2 cmul(float2 a, float2 b) {
    return make_float2(fmaf(a.x, b.x, -a.y * b.y), fmaf(a.x, b.y, a.y * b.x));
}
__device__ __forceinline__ float2 cadd(float2 a, float2 b) { return make_float2(a.x + b.x, a.y + b.y); }
__device__ __forceinline__ float2 csub(float2 a, float2 b) { return make_float2(a.x - b.x, a.y - b.y); }

// ---------------- FFT core: Stockham radix-8 (4 stages) + radix-2, 1024 thr --------
__device__ float2* fft8192_r8(float2* src, float2* dst, const float2* __restrict__ tw,
                              float sgn, int tid, bool padded, bool halfOut)
{
    const float RH = 0.70710678118654752f;

    int s = 1;
    #pragma unroll 1
    for (int st = 0; st < 4; ++st) {
        const int sm1 = s - 1;
        {
            int i  = tid;
            int q  = i & sm1;
            int ps = i - q;

            float2 a0 = src[SKW(i)];
            float2 a1 = src[SKW(i + 1024)];
            float2 a2 = src[SKW(i + 2048)];
            float2 a3 = src[SKW(i + 3072)];

            float2 E0, E1, E2, E3, O0, O1, O2, O3;
            if (padded && st == 0) {
                float2 m2 = make_float2(sgn * a2.y, -sgn * a2.x);
                float2 m3 = make_float2(sgn * a3.y, -sgn * a3.x);
                E0 = cadd(a0, a2); E2 = csub(a0, a2);
                E1 = cadd(a0, m2); E3 = csub(a0, m2);
                O0 = cadd(a1, a3); O2 = csub(a1, a3);
                O1 = cadd(a1, m3); O3 = csub(a1, m3);
            } else {
                float2 a4 = src[SKW(i + 4096)];
                float2 a5 = src[SKW(i + 5120)];
                float2 a6 = src[SKW(i + 6144)];
                float2 a7 = src[SKW(i + 7168)];
                float2 t0 = cadd(a0, a4), t1 = csub(a0, a4);
                float2 t2 = cadd(a2, a6), t3 = csub(a2, a6);
                float2 m3e = make_float2(sgn * t3.y, -sgn * t3.x);
                E0 = cadd(t0, t2); E2 = csub(t0, t2);
                E1 = cadd(t1, m3e); E3 = csub(t1, m3e);
                float2 u0 = cadd(a1, a5), u1 = csub(a1, a5);
                float2 u2 = cadd(a3, a7), u3 = csub(a3, a7);
                float2 m3o = make_float2(sgn * u3.y, -sgn * u3.x);
                O0 = cadd(u0, u2); O2 = csub(u0, u2);
                O1 = cadd(u1, m3o); O3 = csub(u1, m3o);
            }

            float2 W1O = make_float2(RH * (O1.x + sgn * O1.y), RH * (O1.y - sgn * O1.x));
            float2 W2O = make_float2(sgn * O2.y, -sgn * O2.x);
            float2 W3O = make_float2(RH * (sgn * O3.y - O3.x), -RH * (O3.y + sgn * O3.x));

            float2 X0 = cadd(E0, O0),  X4 = csub(E0, O0);
            float2 X1 = cadd(E1, W1O), X5 = csub(E1, W1O);
            float2 X2 = cadd(E2, W2O), X6 = csub(E2, W2O);
            float2 X3 = cadd(E3, W3O), X7 = csub(E3, W3O);

            float2 w1 = tw[ps];     w1.y *= sgn;
            float2 w2 = tw[2 * ps]; w2.y *= sgn;
            float2 w4 = tw[4 * ps]; w4.y *= sgn;
            float2 w3 = cmul(w1, w2);
            float2 w5 = cmul(w1, w4);
            float2 w6 = cmul(w2, w4);
            float2 w7 = cmul(w3, w4);

            int o = q + 8 * ps;
            dst[SKW(o)]         = X0;
            dst[SKW(o + s)]     = cmul(X1, w1);
            dst[SKW(o + 2 * s)] = cmul(X2, w2);
            dst[SKW(o + 3 * s)] = cmul(X3, w3);
            dst[SKW(o + 4 * s)] = cmul(X4, w4);
            dst[SKW(o + 5 * s)] = cmul(X5, w5);
            dst[SKW(o + 6 * s)] = cmul(X6, w6);
            dst[SKW(o + 7 * s)] = cmul(X7, w7);
        }
        __syncthreads();
        float2* t = src; src = dst; dst = t;
        s <<= 3;
    }

    #pragma unroll
    for (int r = 0; r < 4; ++r) {
        int i = tid + r * NTHR;
        float2 a = src[SKW(i)];
        float2 b = src[SKW(i + NHALF)];
        dst[SKW(i)] = cadd(a, b);
        if (!halfOut) dst[SKW(i + NHALF)] = csub(a, b);
    }
    __syncthreads();
    return dst;
}

// ---------------- kernel spectra: two real channels per FFT (Re/Im packing) --------
#define SMEM_FFTK ((2 * SKWN + NHALF) * (int)sizeof(float2))
__global__ void __launch_bounds__(NTHR) fftk_kernel(const float* __restrict__ k_ssm)
{
    float2* buf0 = (float2*)s4_smem;
    float2* buf1 = buf0 + SKWN;
    float2* tws  = buf1 + SKWN;
    const int h0 = blockIdx.x * 2;
    const int tid = threadIdx.x;

    for (int i = tid; i < NHALF; i += NTHR) tws[i] = g_tw[i];
    const float* k0 = k_ssm + (size_t)h0 * L_SEQ;
    const float* k1 = k0 + L_SEQ;
    for (int l = tid; l < L_SEQ; l += NTHR)
        buf0[SKW(l)] = make_float2(k0[l], k1[l]);
    __syncthreads();

    float2* F = fft8192_r8(buf0, buf1, tws, 1.0f, tid, true, false);

    float2* H0 = g_Hf + (size_t)h0 * NFFT;
    float2* H1 = H0 + NFFT;
    for (int k = tid; k < NFFT; k += NTHR) {
        float2 Fk = F[SKW(k)];
        float2 Fn = F[SKW((NFFT - k) & (NFFT - 1))];
        H0[k] = make_float2(0.5f * (Fk.x + Fn.x), 0.5f * (Fk.y - Fn.y));
        float2 Bd = make_float2(Fk.x - Fn.x, Fk.y + Fn.y);
        H1[k] = make_float2(0.5f * Bd.y, -0.5f * Bd.x);
    }
}

// ------- fused: conv4+SiLU -> batch-packed FFT conv -> D_skip -> *SiLU(z) -------
#define SMEM_CONV ((2 * SKWN + NHALF + L_SEQ) * (int)sizeof(float2))
__global__ void __launch_bounds__(NTHR) convfft_kernel(const float* __restrict__ conv_w,
                                                       const float* __restrict__ conv_b,
                                                       const float* __restrict__ D_skip)
{
    float2* buf0 = (float2*)s4_smem;
    float2* buf1 = buf0 + SKWN;
    float2* tws  = buf1 + SKWN;
    float2* xs   = tws + NHALF;

    const int h   = blockIdx.x;
    const int tid = threadIdx.x;

    for (int i = tid; i < NHALF; i += NTHR) tws[i] = g_tw[i];

    const float w0 = conv_w[h * 4 + 0];
    const float w1 = conv_w[h * 4 + 1];
    const float w2 = conv_w[h * 4 + 2];
    const float w3 = conv_w[h * 4 + 3];
    const float cb = conv_b[h];

    const float* gx0 = g_xz + (size_t)h * L_SEQ;
    const float* gx1 = g_xz + ((size_t)EDIM + h) * L_SEQ;
    for (int l = tid; l < L_SEQ; l += NTHR) {
        float a0 = fmaf(w3, gx0[l], cb);
        float a1 = fmaf(w3, gx1[l], cb);
        if (l >= 1) { a0 = fmaf(w2, gx0[l - 1], a0); a1 = fmaf(w2, gx1[l - 1], a1); }
        if (l >= 2) { a0 = fmaf(w1, gx0[l - 2], a0); a1 = fmaf(w1, gx1[l - 2], a1); }
        if (l >= 3) { a0 = fmaf(w0, gx0[l - 3], a0); a1 = fmaf(w0, gx1[l - 3], a1); }
        float v0 = a0 / (1.0f + expf(-a0));
        float v1 = a1 / (1.0f + expf(-a1));
        float2 v = make_float2(v0, v1);
        xs[l]        = v;
        buf0[SKW(l)] = v;
    }
    __syncthreads();

    float2* r1 = fft8192_r8(buf0, buf1, tws, 1.0f, tid, true, false);

    const float2* __restrict__ Hrow = g_Hf + (size_t)h * NFFT;
    for (int i = tid; i < NFFT; i += NTHR) {
        float2 v = r1[SKW(i)];
        r1[SKW(i)] = cmul(v, Hrow[i]);
    }
    __syncthreads();

    float2* other = (r1 == buf0) ? buf1 : buf0;
    float2* r2 = fft8192_r8(r1, other, tws, -1.0f, tid, false, true);

    const float dsk = D_skip[h];
    const float* gz0 = g_xz + ((size_t)DINNER + h) * L_SEQ;
    const float* gz1 = g_xz + ((size_t)EDIM + DINNER + h) * L_SEQ;
    float*       gy0 = g_y  + (size_t)h * L_SEQ;
    float*       gy1 = g_y  + ((size_t)DINNER + h) * L_SEQ;
    const float invn = 1.0f / (float)NFFT;
    for (int l = tid; l < L_SEQ; l += NTHR) {
        float2 xv = xs[l];
        float2 rv = r2[SKW(l)];
        float y0 = fmaf(rv.x, invn, dsk * xv.x);
        float y1 = fmaf(rv.y, invn, dsk * xv.y);
        float z0 = gz0[l];
        float z1 = gz1[l];
        gy0[l] = y0 * (z0 / (1.0f + expf(-z0)));
        gy1[l] = y1 * (z1 / (1.0f + expf(-z1)));
    }
}

// ---------------- launch ----------------
extern "C" void kernel_launch(void* const* d_in, const int* in_sizes, int n_in,
                              void* d_out, int out_size)
{
    (void)in_sizes; (void)n_in; (void)out_size;
    const float* hs     = (const float*)d_in[0];
    const float* W_in   = (const float*)d_in[1];
    const float* conv_w = (const float*)d_in[2];
    const float* conv_b = (const float*)d_in[3];
    const float* k_ssm  = (const float*)d_in[4];
    const float* D_skip = (const float*)d_in[5];
    const float* W_out  = (const float*)d_in[6];
    float* out = (float*)d_out;

    cudaFuncSetAttribute(fftk_kernel,    cudaFuncAttributeMaxDynamicSharedMemorySize, SMEM_FFTK);
    cudaFuncSetAttribute(convfft_kernel, cudaFuncAttributeMaxDynamicSharedMemorySize, SMEM_CONV);

    float* xz = nullptr; cudaGetSymbolAddress((void**)&xz, g_xz);
    float* yt = nullptr; cudaGetSymbolAddress((void**)&yt, g_yt);

    twiddle_kernel<<<NHALF / 512, 512>>>();

    // GEMM1: xz[b][e][l] = sum_d W_in[e][d] * hs[b][l][d]
    gemm_mma<<<dim3(L_SEQ / 128, EDIM / 128, BATCH), 256>>>(
        W_in, hs, xz, DMODEL, DMODEL, L_SEQ, DMODEL,
        0LL, (long long)L_SEQ * DMODEL, (long long)EDIM * L_SEQ);

    fftk_kernel<<<DINNER / 2, NTHR, SMEM_FFTK>>>(k_ssm);
    convfft_kernel<<<DINNER, NTHR, SMEM_CONV>>>(conv_w, conv_b, D_skip);

    transpose_kernel<<<dim3(L_SEQ / 32, DINNER / 32, BATCH), dim3(32, 8)>>>();

    // GEMM2: out[b][l][d] = sum_h y_t[b][l][h] * W_out[d][h]
    gemm_mma<<<dim3(DMODEL / 128, L_SEQ / 128, BATCH), 256>>>(
        yt, W_out, out, DINNER, DINNER, DMODEL, DINNER,
        (long long)L_SEQ * DINNER, 0LL, (long long)L_SEQ * DMODEL);
}

// round 10
// speedup vs baseline: 4.6965x; 1.2778x over previous
#include <cuda_runtime.h>
#include <cuda_fp16.h>
#include <math.h>
#include <stdint.h>

// ---------------- problem constants ----------------
#define L_SEQ   4096
#define DMODEL  1024
#define DINNER  2048
#define EDIM    (2*DINNER)   // 4096
#define BATCH   2
#define NFFT    8192
#define NHALF   (NFFT/2)     // 4096
#define NTHR    1024         // FFT kernel block size

#define SKW(i)  ((i) + ((i) >> 4))
#define SKWN    (NFFT + NFFT/16)     // 8704 float2 per buffer

extern __shared__ char s4_smem[];

// ---------------- scratch (device globals; allocation-free launch) ----------------
__device__ float  g_xz [(unsigned long long)BATCH * EDIM * L_SEQ];     // [b][e][l]
__device__ float  g_y  [(unsigned long long)BATCH * DINNER * L_SEQ];   // [b][h][l]
__device__ __half g_ytH[(unsigned long long)BATCH * L_SEQ * DINNER];   // [b][l][h] fp16
__device__ __half g_hsH [(unsigned long long)BATCH * L_SEQ * DMODEL];
__device__ __half g_WinH[(unsigned long long)EDIM * DMODEL];
__device__ __half g_WoutH[(unsigned long long)DMODEL * DINNER];
__device__ float2 g_Hf[(unsigned long long)DINNER * NFFT];
__device__ float2 g_tw[NHALF];

// ---------------- f32 -> f16 bulk convert ----------------
__global__ void __launch_bounds__(256) f2h_kernel(const float* __restrict__ src,
                                                  __half* __restrict__ dst,
                                                  long long n4)
{
    long long i = ((long long)blockIdx.x * 256 + threadIdx.x);
    if (i < n4) {
        float4 v = *(const float4*)(src + i * 4);
        __half2 h01 = __floats2half2_rn(v.x, v.y);
        __half2 h23 = __floats2half2_rn(v.z, v.w);
        *(uint2*)(dst + i * 4) = make_uint2(*(uint32_t*)&h01, *(uint32_t*)&h23);
    }
}

// ---------------- mma / ldmatrix / cp.async helpers ----------------
__device__ __forceinline__ void mma_f16(float* d, const uint32_t* a, const uint32_t* b) {
    asm volatile(
        "mma.sync.aligned.m16n8k16.row.col.f32.f16.f16.f32 "
        "{%0,%1,%2,%3}, {%4,%5,%6,%7}, {%8,%9}, {%0,%1,%2,%3};"
        : "+f"(d[0]), "+f"(d[1]), "+f"(d[2]), "+f"(d[3])
        : "r"(a[0]), "r"(a[1]), "r"(a[2]), "r"(a[3]), "r"(b[0]), "r"(b[1]));
}
__device__ __forceinline__ void ldsm_x4(uint32_t* r, uint32_t saddr) {
    asm volatile("ldmatrix.sync.aligned.m8n8.x4.shared.b16 {%0,%1,%2,%3}, [%4];"
                 : "=r"(r[0]), "=r"(r[1]), "=r"(r[2]), "=r"(r[3]) : "r"(saddr));
}
__device__ __forceinline__ void cp16(uint32_t saddr, const void* gaddr) {
    asm volatile("cp.async.cg.shared.global [%0], [%1], 16;" :: "r"(saddr), "l"(gaddr));
}
__device__ __forceinline__ void cp_commit() {
    asm volatile("cp.async.commit_group;" ::: "memory");
}
template<int N>
__device__ __forceinline__ void cp_wait() {
    asm volatile("cp.async.wait_group %0;" :: "n"(N) : "memory");
}

// ================= fp16 GEMM: cp.async 3-stage + ldmatrix + mma =================
// C[m][n] = sum_k A[m*lda+k] * B[n*ldb+k]  (half inputs, K-contiguous, NT)
#define GPITCH 40   // halves per smem row (80B: 16B-aligned groups, ldmatrix conflict-free)
#define STAGES 3

__global__ void __launch_bounds__(256) gemm_mma_h(const __half* __restrict__ A,
                                                  const __half* __restrict__ B,
                                                  float* __restrict__ C,
                                                  int lda, int ldb, int ldc, int K,
                                                  long long aBatch, long long bBatch,
                                                  long long cBatch)
{
    __shared__ __half As[STAGES][128][GPITCH];
    __shared__ __half Bs[STAGES][128][GPITCH];

    A += (size_t)blockIdx.z * aBatch;
    B += (size_t)blockIdx.z * bBatch;
    C += (size_t)blockIdx.z * cBatch;
    const int m0 = blockIdx.y * 128;
    const int n0 = blockIdx.x * 128;

    const int tid  = threadIdx.x;
    const int wid  = tid >> 5;
    const int lane = tid & 31;
    const int wm   = (wid >> 2) * 64;
    const int wn   = (wid & 3) * 32;
    const int g    = lane >> 2;
    const int t    = lane & 3;

    const int aRow = (lane & 15);
    const int aCol = (lane >> 4) * 8;
    const int bRow = (lane & 7) + ((lane >> 4) << 3);
    const int bCol = ((lane >> 3) & 1) * 8;

    float acc[4][4][4];
    #pragma unroll
    for (int mi = 0; mi < 4; ++mi)
        #pragma unroll
        for (int ni = 0; ni < 4; ++ni)
            #pragma unroll
            for (int r = 0; r < 4; ++r) acc[mi][ni][r] = 0.f;

    const int nch = K >> 5;

    // cp.async mapping: 128 rows x 32 halves = 512 groups of 16B per matrix
    const int r0a = tid >> 1;               // rows tid/2 and tid/2+... p loop below
    (void)r0a;

    auto issue = [&](int st, int c) {
        const int k0 = c << 5;
        #pragma unroll
        for (int p = 0; p < 2; ++p) {
            int lin = p * 256 + tid;        // 0..511
            int row = lin >> 2;             // 0..127
            int grp = lin & 3;              // 16B group
            uint32_t sa = (uint32_t)__cvta_generic_to_shared(&As[st][row][grp * 8]);
            cp16(sa, A + (size_t)(m0 + row) * lda + k0 + grp * 8);
            uint32_t sb = (uint32_t)__cvta_generic_to_shared(&Bs[st][row][grp * 8]);
            cp16(sb, B + (size_t)(n0 + row) * ldb + k0 + grp * 8);
        }
        cp_commit();
    };

    issue(0, 0);
    issue(1, 1);

    for (int c = 0; c < nch; ++c) {
        cp_wait<STAGES - 2>();
        __syncthreads();

        if (c + STAGES - 1 < nch)
            issue((c + STAGES - 1) % STAGES, c + STAGES - 1);

        const int buf = c % STAGES;
        #pragma unroll
        for (int ks = 0; ks < 2; ++ks) {
            const int kk = ks * 16;
            uint32_t af[4][4], bf[4][4];
            #pragma unroll
            for (int mi = 0; mi < 4; ++mi) {
                uint32_t sa = (uint32_t)__cvta_generic_to_shared(
                    &As[buf][wm + mi * 16 + aRow][kk + aCol]);
                ldsm_x4(af[mi], sa);
            }
            #pragma unroll
            for (int np = 0; np < 2; ++np) {
                uint32_t sb = (uint32_t)__cvta_generic_to_shared(
                    &Bs[buf][wn + np * 16 + bRow][kk + bCol]);
                ldsm_x4(bf[np * 2], sb);
                bf[np * 2 + 1][0] = bf[np * 2][2];
                bf[np * 2 + 1][1] = bf[np * 2][3];
            }
            #pragma unroll
            for (int mi = 0; mi < 4; ++mi)
                #pragma unroll
                for (int ni = 0; ni < 4; ++ni)
                    mma_f16(acc[mi][ni], af[mi], bf[ni]);
        }
    }

    #pragma unroll
    for (int mi = 0; mi < 4; ++mi) {
        int r0 = m0 + wm + mi * 16 + g;
        #pragma unroll
        for (int ni = 0; ni < 4; ++ni) {
            int cc = n0 + wn + ni * 8 + t * 2;
            *(float2*)(C + (size_t)r0 * ldc + cc)       = make_float2(acc[mi][ni][0], acc[mi][ni][1]);
            *(float2*)(C + (size_t)(r0 + 8) * ldc + cc) = make_float2(acc[mi][ni][2], acc[mi][ni][3]);
        }
    }
}

// ================= transpose y[b][h][l] -> y_t[b][l][h] (fp16 out) =================
__global__ void __launch_bounds__(256) transpose_kernel()
{
    __shared__ float tbuf[32][33];
    const int b  = blockIdx.z;
    const int l0 = blockIdx.x * 32;
    const int h0 = blockIdx.y * 32;
    const int tx = threadIdx.x, ty = threadIdx.y;

    const float* src = g_y + (size_t)b * DINNER * L_SEQ;
    __half*      dst = g_ytH + (size_t)b * L_SEQ * DINNER;
    #pragma unroll
    for (int i = 0; i < 4; ++i)
        tbuf[ty + i * 8][tx] = src[(size_t)(h0 + ty + i * 8) * L_SEQ + l0 + tx];
    __syncthreads();
    #pragma unroll
    for (int i = 0; i < 4; ++i)
        dst[(size_t)(l0 + ty + i * 8) * DINNER + h0 + tx] = __float2half_rn(tbuf[tx][ty + i * 8]);
}

// ---------------- twiddle table ----------------
__global__ void twiddle_kernel() {
    int k = blockIdx.x * blockDim.x + threadIdx.x;
    if (k < NHALF) {
        float s, c;
        sincospif(2.0f * (float)k / (float)NFFT, &s, &c);
        g_tw[k] = make_float2(c, -s);
    }
}

// ---------------- complex helpers ----------------
__device__ __forceinline__ float2 cmul(float2 a, float2 b) {
    return make_float2(fmaf(a.x, b.x, -a.y * b.y), fmaf(a.x, b.y, a.y * b.x));
}
__device__ __forceinline__ float2 cadd(float2 a, float2 b) { return make_float2(a.x + b.x, a.y + b.y); }
__device__ __forceinline__ float2 csub(float2 a, float2 b) { return make_float2(a.x - b.x, a.y - b.y); }

// ---------------- FFT core: Stockham radix-8 (4 stages) + radix-2, 1024 thr --------
__device__ float2* fft8192_r8(float2* src, float2* dst, const float2* __restrict__ tw,
                              float sgn, int tid, bool padded, bool halfOut)
{
    const float RH = 0.70710678118654752f;

    int s = 1;
    #pragma unroll 1
    for (int st = 0; st < 4; ++st) {
        const int sm1 = s - 1;
        {
            int i  = tid;
            int q  = i & sm1;
            int ps = i - q;

            float2 a0 = src[SKW(i)];
            float2 a1 = src[SKW(i + 1024)];
            float2 a2 = src[SKW(i + 2048)];
            float2 a3 = src[SKW(i + 3072)];

            float2 E0, E1, E2, E3, O0, O1, O2, O3;
            if (padded && st == 0) {
                float2 m2 = make_float2(sgn * a2.y, -sgn * a2.x);
                float2 m3 = make_float2(sgn * a3.y, -sgn * a3.x);
                E0 = cadd(a0, a2); E2 = csub(a0, a2);
                E1 = cadd(a0, m2); E3 = csub(a0, m2);
                O0 = cadd(a1, a3); O2 = csub(a1, a3);
                O1 = cadd(a1, m3); O3 = csub(a1, m3);
            } else {
                float2 a4 = src[SKW(i + 4096)];
                float2 a5 = src[SKW(i + 5120)];
                float2 a6 = src[SKW(i + 6144)];
                float2 a7 = src[SKW(i + 7168)];
                float2 t0 = cadd(a0, a4), t1 = csub(a0, a4);
                float2 t2 = cadd(a2, a6), t3 = csub(a2, a6);
                float2 m3e = make_float2(sgn * t3.y, -sgn * t3.x);
                E0 = cadd(t0, t2); E2 = csub(t0, t2);
                E1 = cadd(t1, m3e); E3 = csub(t1, m3e);
                float2 u0 = cadd(a1, a5), u1 = csub(a1, a5);
                float2 u2 = cadd(a3, a7), u3 = csub(a3, a7);
                float2 m3o = make_float2(sgn * u3.y, -sgn * u3.x);
                O0 = cadd(u0, u2); O2 = csub(u0, u2);
                O1 = cadd(u1, m3o); O3 = csub(u1, m3o);
            }

            float2 W1O = make_float2(RH * (O1.x + sgn * O1.y), RH * (O1.y - sgn * O1.x));
            float2 W2O = make_float2(sgn * O2.y, -sgn * O2.x);
            float2 W3O = make_float2(RH * (sgn * O3.y - O3.x), -RH * (O3.y + sgn * O3.x));

            float2 X0 = cadd(E0, O0),  X4 = csub(E0, O0);
            float2 X1 = cadd(E1, W1O), X5 = csub(E1, W1O);
            float2 X2 = cadd(E2, W2O), X6 = csub(E2, W2O);
            float2 X3 = cadd(E3, W3O), X7 = csub(E3, W3O);

            float2 w1 = tw[ps];     w1.y *= sgn;
            float2 w2 = tw[2 * ps]; w2.y *= sgn;
            float2 w4 = tw[4 * ps]; w4.y *= sgn;
            float2 w3 = cmul(w1, w2);
            float2 w5 = cmul(w1, w4);
            float2 w6 = cmul(w2, w4);
            float2 w7 = cmul(w3, w4);

            int o = q + 8 * ps;
            dst[SKW(o)]         = X0;
            dst[SKW(o + s)]     = cmul(X1, w1);
            dst[SKW(o + 2 * s)] = cmul(X2, w2);
            dst[SKW(o + 3 * s)] = cmul(X3, w3);
            dst[SKW(o + 4 * s)] = cmul(X4, w4);
            dst[SKW(o + 5 * s)] = cmul(X5, w5);
            dst[SKW(o + 6 * s)] = cmul(X6, w6);
            dst[SKW(o + 7 * s)] = cmul(X7, w7);
        }
        __syncthreads();
        float2* t = src; src = dst; dst = t;
        s <<= 3;
    }

    #pragma unroll
    for (int r = 0; r < 4; ++r) {
        int i = tid + r * NTHR;
        float2 a = src[SKW(i)];
        float2 b = src[SKW(i + NHALF)];
        dst[SKW(i)] = cadd(a, b);
        if (!halfOut) dst[SKW(i + NHALF)] = csub(a, b);
    }
    __syncthreads();
    return dst;
}

// ---------------- kernel spectra: two real channels per FFT ----------------
#define SMEM_FFTK ((2 * SKWN + NHALF) * (int)sizeof(float2))
__global__ void __launch_bounds__(NTHR) fftk_kernel(const float* __restrict__ k_ssm)
{
    float2* buf0 = (float2*)s4_smem;
    float2* buf1 = buf0 + SKWN;
    float2* tws  = buf1 + SKWN;
    const int h0 = blockIdx.x * 2;
    const int tid = threadIdx.x;

    for (int i = tid; i < NHALF; i += NTHR) tws[i] = g_tw[i];
    const float* k0 = k_ssm + (size_t)h0 * L_SEQ;
    const float* k1 = k0 + L_SEQ;
    for (int l = tid; l < L_SEQ; l += NTHR)
        buf0[SKW(l)] = make_float2(k0[l], k1[l]);
    __syncthreads();

    float2* F = fft8192_r8(buf0, buf1, tws, 1.0f, tid, true, false);

    float2* H0 = g_Hf + (size_t)h0 * NFFT;
    float2* H1 = H0 + NFFT;
    for (int k = tid; k < NFFT; k += NTHR) {
        float2 Fk = F[SKW(k)];
        float2 Fn = F[SKW((NFFT - k) & (NFFT - 1))];
        H0[k] = make_float2(0.5f * (Fk.x + Fn.x), 0.5f * (Fk.y - Fn.y));
        float2 Bd = make_float2(Fk.x - Fn.x, Fk.y + Fn.y);
        H1[k] = make_float2(0.5f * Bd.y, -0.5f * Bd.x);
    }
}

// ------- fused: conv4+SiLU -> batch-packed FFT conv -> D_skip -> *SiLU(z) -------
#define SMEM_CONV ((2 * SKWN + NHALF + L_SEQ) * (int)sizeof(float2))
__global__ void __launch_bounds__(NTHR) convfft_kernel(const float* __restrict__ conv_w,
                                                       const float* __restrict__ conv_b,
                                                       const float* __restrict__ D_skip)
{
    float2* buf0 = (float2*)s4_smem;
    float2* buf1 = buf0 + SKWN;
    float2* tws  = buf1 + SKWN;
    float2* xs   = tws + NHALF;

    const int h   = blockIdx.x;
    const int tid = threadIdx.x;

    for (int i = tid; i < NHALF; i += NTHR) tws[i] = g_tw[i];

    const float w0 = conv_w[h * 4 + 0];
    const float w1 = conv_w[h * 4 + 1];
    const float w2 = conv_w[h * 4 + 2];
    const float w3 = conv_w[h * 4 + 3];
    const float cb = conv_b[h];

    const float* gx0 = g_xz + (size_t)h * L_SEQ;
    const float* gx1 = g_xz + ((size_t)EDIM + h) * L_SEQ;
    for (int l = tid; l < L_SEQ; l += NTHR) {
        float a0 = fmaf(w3, gx0[l], cb);
        float a1 = fmaf(w3, gx1[l], cb);
        if (l >= 1) { a0 = fmaf(w2, gx0[l - 1], a0); a1 = fmaf(w2, gx1[l - 1], a1); }
        if (l >= 2) { a0 = fmaf(w1, gx0[l - 2], a0); a1 = fmaf(w1, gx1[l - 2], a1); }
        if (l >= 3) { a0 = fmaf(w0, gx0[l - 3], a0); a1 = fmaf(w0, gx1[l - 3], a1); }
        float v0 = a0 / (1.0f + expf(-a0));
        float v1 = a1 / (1.0f + expf(-a1));
        float2 v = make_float2(v0, v1);
        xs[l]        = v;
        buf0[SKW(l)] = v;
    }
    __syncthreads();

    float2* r1 = fft8192_r8(buf0, buf1, tws, 1.0f, tid, true, false);

    const float2* __restrict__ Hrow = g_Hf + (size_t)h * NFFT;
    for (int i = tid; i < NFFT; i += NTHR) {
        float2 v = r1[SKW(i)];
        r1[SKW(i)] = cmul(v, Hrow[i]);
    }
    __syncthreads();

    float2* other = (r1 == buf0) ? buf1 : buf0;
    float2* r2 = fft8192_r8(r1, other, tws, -1.0f, tid, false, true);

    const float dsk = D_skip[h];
    const float* gz0 = g_xz + ((size_t)DINNER + h) * L_SEQ;
    const float* gz1 = g_xz + ((size_t)EDIM + DINNER + h) * L_SEQ;
    float*       gy0 = g_y  + (size_t)h * L_SEQ;
    float*       gy1 = g_y  + ((size_t)DINNER + h) * L_SEQ;
    const float invn = 1.0f / (float)NFFT;
    for (int l = tid; l < L_SEQ; l += NTHR) {
        float2 xv = xs[l];
        float2 rv = r2[SKW(l)];
        float y0 = fmaf(rv.x, invn, dsk * xv.x);
        float y1 = fmaf(rv.y, invn, dsk * xv.y);
        float z0 = gz0[l];
        float z1 = gz1[l];
        gy0[l] = y0 * (z0 / (1.0f + expf(-z0)));
        gy1[l] = y1 * (z1 / (1.0f + expf(-z1)));
    }
}

// ---------------- launch ----------------
extern "C" void kernel_launch(void* const* d_in, const int* in_sizes, int n_in,
                              void* d_out, int out_size)
{
    (void)in_sizes; (void)n_in; (void)out_size;
    const float* hs     = (const float*)d_in[0];
    const float* W_in   = (const float*)d_in[1];
    const float* conv_w = (const float*)d_in[2];
    const float* conv_b = (const float*)d_in[3];
    const float* k_ssm  = (const float*)d_in[4];
    const float* D_skip = (const float*)d_in[5];
    const float* W_out  = (const float*)d_in[6];
    float* out = (float*)d_out;

    cudaFuncSetAttribute(fftk_kernel,    cudaFuncAttributeMaxDynamicSharedMemorySize, SMEM_FFTK);
    cudaFuncSetAttribute(convfft_kernel, cudaFuncAttributeMaxDynamicSharedMemorySize, SMEM_CONV);

    float*  xz   = nullptr; cudaGetSymbolAddress((void**)&xz, g_xz);
    __half* hsH  = nullptr; cudaGetSymbolAddress((void**)&hsH, g_hsH);
    __half* winH = nullptr; cudaGetSymbolAddress((void**)&winH, g_WinH);
    __half* woutH= nullptr; cudaGetSymbolAddress((void**)&woutH, g_WoutH);
    __half* ytH  = nullptr; cudaGetSymbolAddress((void**)&ytH, g_ytH);

    twiddle_kernel<<<NHALF / 512, 512>>>();

    {
        long long n4;
        n4 = (long long)BATCH * L_SEQ * DMODEL / 4;
        f2h_kernel<<<(unsigned)((n4 + 255) / 256), 256>>>(hs, hsH, n4);
        n4 = (long long)EDIM * DMODEL / 4;
        f2h_kernel<<<(unsigned)((n4 + 255) / 256), 256>>>(W_in, winH, n4);
        n4 = (long long)DMODEL * DINNER / 4;
        f2h_kernel<<<(unsigned)((n4 + 255) / 256), 256>>>(W_out, woutH, n4);
    }

    // GEMM1: xz[b][e][l] = sum_d W_in[e][d] * hs[b][l][d]
    gemm_mma_h<<<dim3(L_SEQ / 128, EDIM / 128, BATCH), 256>>>(
        winH, hsH, xz, DMODEL, DMODEL, L_SEQ, DMODEL,
        0LL, (long long)L_SEQ * DMODEL, (long long)EDIM * L_SEQ);

    fftk_kernel<<<DINNER / 2, NTHR, SMEM_FFTK>>>(k_ssm);
    convfft_kernel<<<DINNER, NTHR, SMEM_CONV>>>(conv_w, conv_b, D_skip);

    transpose_kernel<<<dim3(L_SEQ / 32, DINNER / 32, BATCH), dim3(32, 8)>>>();

    // GEMM2: out[b][l][d] = sum_h y_t[b][l][h] * W_out[d][h]
    gemm_mma_h<<<dim3(DMODEL / 128, L_SEQ / 128, BATCH), 256>>>(
        ytH, woutH, out, DINNER, DINNER, DMODEL, DINNER,
        (long long)L_SEQ * DINNER, 0LL, (long long)L_SEQ * DMODEL);
}

// round 11
// speedup vs baseline: 4.9574x; 1.0556x over previous
#include <cuda_runtime.h>
#include <cuda_fp16.h>
#include <math.h>
#include <stdint.h>

// ---------------- problem constants ----------------
#define L_SEQ   4096
#define DMODEL  1024
#define DINNER  2048
#define EDIM    (2*DINNER)   // 4096
#define BATCH   2
#define NFFT    8192
#define NHALF   (NFFT/2)     // 4096
#define NTHR    1024         // fftk block size

#define SKW(i)  ((i) + ((i) >> 4))
#define SKWN    (NFFT + NFFT/16)       // 8704 float2 (8192 buffer, fftk)
#define SKWN4   (4096 + 4096/16)       // 4352 float2 (4096 buffer, convfft)

extern __shared__ char s4_smem[];

// ---------------- scratch (device globals; allocation-free launch) ----------------
__device__ float  g_xz [(unsigned long long)BATCH * EDIM * L_SEQ];     // [b][e][l]
__device__ float  g_y  [(unsigned long long)BATCH * DINNER * L_SEQ];   // [b][h][l]
__device__ __half g_ytH[(unsigned long long)BATCH * L_SEQ * DINNER];   // [b][l][h] fp16
__device__ __half g_hsH [(unsigned long long)BATCH * L_SEQ * DMODEL];
__device__ __half g_WinH[(unsigned long long)EDIM * DMODEL];
__device__ __half g_WoutH[(unsigned long long)DMODEL * DINNER];
__device__ float2 g_Hf[(unsigned long long)DINNER * NFFT];
__device__ float2 g_tw[NHALF];                                         // e^{-2pi i k/8192}

// ---------------- f32 -> f16 bulk convert ----------------
__global__ void __launch_bounds__(256) f2h_kernel(const float* __restrict__ src,
                                                  __half* __restrict__ dst,
                                                  long long n4)
{
    long long i = ((long long)blockIdx.x * 256 + threadIdx.x);
    if (i < n4) {
        float4 v = *(const float4*)(src + i * 4);
        __half2 h01 = __floats2half2_rn(v.x, v.y);
        __half2 h23 = __floats2half2_rn(v.z, v.w);
        *(uint2*)(dst + i * 4) = make_uint2(*(uint32_t*)&h01, *(uint32_t*)&h23);
    }
}

// ---------------- mma / ldmatrix / cp.async helpers ----------------
__device__ __forceinline__ void mma_f16(float* d, const uint32_t* a, const uint32_t* b) {
    asm volatile(
        "mma.sync.aligned.m16n8k16.row.col.f32.f16.f16.f32 "
        "{%0,%1,%2,%3}, {%4,%5,%6,%7}, {%8,%9}, {%0,%1,%2,%3};"
        : "+f"(d[0]), "+f"(d[1]), "+f"(d[2]), "+f"(d[3])
        : "r"(a[0]), "r"(a[1]), "r"(a[2]), "r"(a[3]), "r"(b[0]), "r"(b[1]));
}
__device__ __forceinline__ void ldsm_x4(uint32_t* r, uint32_t saddr) {
    asm volatile("ldmatrix.sync.aligned.m8n8.x4.shared.b16 {%0,%1,%2,%3}, [%4];"
                 : "=r"(r[0]), "=r"(r[1]), "=r"(r[2]), "=r"(r[3]) : "r"(saddr));
}
__device__ __forceinline__ void cp16(uint32_t saddr, const void* gaddr) {
    asm volatile("cp.async.cg.shared.global [%0], [%1], 16;" :: "r"(saddr), "l"(gaddr));
}
__device__ __forceinline__ void cp_commit() {
    asm volatile("cp.async.commit_group;" ::: "memory");
}
template<int N>
__device__ __forceinline__ void cp_wait() {
    asm volatile("cp.async.wait_group %0;" :: "n"(N) : "memory");
}

// ================= fp16 GEMM: cp.async 3-stage + ldmatrix + mma =================
#define GPITCH 40
#define STAGES 3

__global__ void __launch_bounds__(256) gemm_mma_h(const __half* __restrict__ A,
                                                  const __half* __restrict__ B,
                                                  float* __restrict__ C,
                                                  int lda, int ldb, int ldc, int K,
                                                  long long aBatch, long long bBatch,
                                                  long long cBatch)
{
    __shared__ __half As[STAGES][128][GPITCH];
    __shared__ __half Bs[STAGES][128][GPITCH];

    A += (size_t)blockIdx.z * aBatch;
    B += (size_t)blockIdx.z * bBatch;
    C += (size_t)blockIdx.z * cBatch;
    const int m0 = blockIdx.y * 128;
    const int n0 = blockIdx.x * 128;

    const int tid  = threadIdx.x;
    const int wid  = tid >> 5;
    const int lane = tid & 31;
    const int wm   = (wid >> 2) * 64;
    const int wn   = (wid & 3) * 32;
    const int g    = lane >> 2;
    const int t    = lane & 3;

    const int aRow = (lane & 15);
    const int aCol = (lane >> 4) * 8;
    const int bRow = (lane & 7) + ((lane >> 4) << 3);
    const int bCol = ((lane >> 3) & 1) * 8;

    float acc[4][4][4];
    #pragma unroll
    for (int mi = 0; mi < 4; ++mi)
        #pragma unroll
        for (int ni = 0; ni < 4; ++ni)
            #pragma unroll
            for (int r = 0; r < 4; ++r) acc[mi][ni][r] = 0.f;

    const int nch = K >> 5;

    auto issue = [&](int st, int c) {
        const int k0 = c << 5;
        #pragma unroll
        for (int p = 0; p < 2; ++p) {
            int lin = p * 256 + tid;
            int row = lin >> 2;
            int grp = lin & 3;
            uint32_t sa = (uint32_t)__cvta_generic_to_shared(&As[st][row][grp * 8]);
            cp16(sa, A + (size_t)(m0 + row) * lda + k0 + grp * 8);
            uint32_t sb = (uint32_t)__cvta_generic_to_shared(&Bs[st][row][grp * 8]);
            cp16(sb, B + (size_t)(n0 + row) * ldb + k0 + grp * 8);
        }
        cp_commit();
    };

    issue(0, 0);
    issue(1, 1);

    for (int c = 0; c < nch; ++c) {
        cp_wait<STAGES - 2>();
        __syncthreads();

        if (c + STAGES - 1 < nch)
            issue((c + STAGES - 1) % STAGES, c + STAGES - 1);

        const int buf = c % STAGES;
        #pragma unroll
        for (int ks = 0; ks < 2; ++ks) {
            const int kk = ks * 16;
            uint32_t af[4][4], bf[4][4];
            #pragma unroll
            for (int mi = 0; mi < 4; ++mi) {
                uint32_t sa = (uint32_t)__cvta_generic_to_shared(
                    &As[buf][wm + mi * 16 + aRow][kk + aCol]);
                ldsm_x4(af[mi], sa);
            }
            #pragma unroll
            for (int np = 0; np < 2; ++np) {
                uint32_t sb = (uint32_t)__cvta_generic_to_shared(
                    &Bs[buf][wn + np * 16 + bRow][kk + bCol]);
                ldsm_x4(bf[np * 2], sb);
                bf[np * 2 + 1][0] = bf[np * 2][2];
                bf[np * 2 + 1][1] = bf[np * 2][3];
            }
            #pragma unroll
            for (int mi = 0; mi < 4; ++mi)
                #pragma unroll
                for (int ni = 0; ni < 4; ++ni)
                    mma_f16(acc[mi][ni], af[mi], bf[ni]);
        }
    }

    #pragma unroll
    for (int mi = 0; mi < 4; ++mi) {
        int r0 = m0 + wm + mi * 16 + g;
        #pragma unroll
        for (int ni = 0; ni < 4; ++ni) {
            int cc = n0 + wn + ni * 8 + t * 2;
            *(float2*)(C + (size_t)r0 * ldc + cc)       = make_float2(acc[mi][ni][0], acc[mi][ni][1]);
            *(float2*)(C + (size_t)(r0 + 8) * ldc + cc) = make_float2(acc[mi][ni][2], acc[mi][ni][3]);
        }
    }
}

// ================= transpose y[b][h][l] -> y_t[b][l][h] (fp16 out) =================
__global__ void __launch_bounds__(256) transpose_kernel()
{
    __shared__ float tbuf[32][33];
    const int b  = blockIdx.z;
    const int l0 = blockIdx.x * 32;
    const int h0 = blockIdx.y * 32;
    const int tx = threadIdx.x, ty = threadIdx.y;

    const float* src = g_y + (size_t)b * DINNER * L_SEQ;
    __half*      dst = g_ytH + (size_t)b * L_SEQ * DINNER;
    #pragma unroll
    for (int i = 0; i < 4; ++i)
        tbuf[ty + i * 8][tx] = src[(size_t)(h0 + ty + i * 8) * L_SEQ + l0 + tx];
    __syncthreads();
    #pragma unroll
    for (int i = 0; i < 4; ++i)
        dst[(size_t)(l0 + ty + i * 8) * DINNER + h0 + tx] = __float2half_rn(tbuf[tx][ty + i * 8]);
}

// ---------------- twiddle table ----------------
__global__ void twiddle_kernel() {
    int k = blockIdx.x * blockDim.x + threadIdx.x;
    if (k < NHALF) {
        float s, c;
        sincospif(2.0f * (float)k / (float)NFFT, &s, &c);
        g_tw[k] = make_float2(c, -s);
    }
}

// ---------------- complex helpers ----------------
__device__ __forceinline__ float2 cmul(float2 a, float2 b) {
    return make_float2(fmaf(a.x, b.x, -a.y * b.y), fmaf(a.x, b.y, a.y * b.x));
}
__device__ __forceinline__ float2 cadd(float2 a, float2 b) { return make_float2(a.x + b.x, a.y + b.y); }
__device__ __forceinline__ float2 csub(float2 a, float2 b) { return make_float2(a.x - b.x, a.y - b.y); }

// ---------------- FFT 8192: Stockham radix-8 (4 stages) + radix-2, 1024 thr --------
__device__ float2* fft8192_r8(float2* src, float2* dst, const float2* __restrict__ tw,
                              float sgn, int tid, bool padded, bool halfOut)
{
    const float RH = 0.70710678118654752f;

    int s = 1;
    #pragma unroll 1
    for (int st = 0; st < 4; ++st) {
        const int sm1 = s - 1;
        {
            int i  = tid;
            int q  = i & sm1;
            int ps = i - q;

            float2 a0 = src[SKW(i)];
            float2 a1 = src[SKW(i + 1024)];
            float2 a2 = src[SKW(i + 2048)];
            float2 a3 = src[SKW(i + 3072)];

            float2 E0, E1, E2, E3, O0, O1, O2, O3;
            if (padded && st == 0) {
                float2 m2 = make_float2(sgn * a2.y, -sgn * a2.x);
                float2 m3 = make_float2(sgn * a3.y, -sgn * a3.x);
                E0 = cadd(a0, a2); E2 = csub(a0, a2);
                E1 = cadd(a0, m2); E3 = csub(a0, m2);
                O0 = cadd(a1, a3); O2 = csub(a1, a3);
                O1 = cadd(a1, m3); O3 = csub(a1, m3);
            } else {
                float2 a4 = src[SKW(i + 4096)];
                float2 a5 = src[SKW(i + 5120)];
                float2 a6 = src[SKW(i + 6144)];
                float2 a7 = src[SKW(i + 7168)];
                float2 t0 = cadd(a0, a4), t1 = csub(a0, a4);
                float2 t2 = cadd(a2, a6), t3 = csub(a2, a6);
                float2 m3e = make_float2(sgn * t3.y, -sgn * t3.x);
                E0 = cadd(t0, t2); E2 = csub(t0, t2);
                E1 = cadd(t1, m3e); E3 = csub(t1, m3e);
                float2 u0 = cadd(a1, a5), u1 = csub(a1, a5);
                float2 u2 = cadd(a3, a7), u3 = csub(a3, a7);
                float2 m3o = make_float2(sgn * u3.y, -sgn * u3.x);
                O0 = cadd(u0, u2); O2 = csub(u0, u2);
                O1 = cadd(u1, m3o); O3 = csub(u1, m3o);
            }

            float2 W1O = make_float2(RH * (O1.x + sgn * O1.y), RH * (O1.y - sgn * O1.x));
            float2 W2O = make_float2(sgn * O2.y, -sgn * O2.x);
            float2 W3O = make_float2(RH * (sgn * O3.y - O3.x), -RH * (O3.y + sgn * O3.x));

            float2 X0 = cadd(E0, O0),  X4 = csub(E0, O0);
            float2 X1 = cadd(E1, W1O), X5 = csub(E1, W1O);
            float2 X2 = cadd(E2, W2O), X6 = csub(E2, W2O);
            float2 X3 = cadd(E3, W3O), X7 = csub(E3, W3O);

            float2 w1 = tw[ps];     w1.y *= sgn;
            float2 w2 = tw[2 * ps]; w2.y *= sgn;
            float2 w4 = tw[4 * ps]; w4.y *= sgn;
            float2 w3 = cmul(w1, w2);
            float2 w5 = cmul(w1, w4);
            float2 w6 = cmul(w2, w4);
            float2 w7 = cmul(w3, w4);

            int o = q + 8 * ps;
            dst[SKW(o)]         = X0;
            dst[SKW(o + s)]     = cmul(X1, w1);
            dst[SKW(o + 2 * s)] = cmul(X2, w2);
            dst[SKW(o + 3 * s)] = cmul(X3, w3);
            dst[SKW(o + 4 * s)] = cmul(X4, w4);
            dst[SKW(o + 5 * s)] = cmul(X5, w5);
            dst[SKW(o + 6 * s)] = cmul(X6, w6);
            dst[SKW(o + 7 * s)] = cmul(X7, w7);
        }
        __syncthreads();
        float2* t = src; src = dst; dst = t;
        s <<= 3;
    }

    #pragma unroll
    for (int r = 0; r < 4; ++r) {
        int i = tid + r * NTHR;
        float2 a = src[SKW(i)];
        float2 b = src[SKW(i + NHALF)];
        dst[SKW(i)] = cadd(a, b);
        if (!halfOut) dst[SKW(i + NHALF)] = csub(a, b);
    }
    __syncthreads();
    return dst;
}

// ---------------- FFT 4096: Stockham radix-8, 4 stages, 512 thr --------------------
// tw table: tw4[x] = e^{-2pi i x/4096}, x < 2048.
__device__ float2* fft4096_r8(float2* src, float2* dst, const float2* __restrict__ tw,
                              float sgn, int tid, bool padded, bool halfOut)
{
    const float RH = 0.70710678118654752f;

    int s = 1;
    #pragma unroll 1
    for (int st = 0; st < 4; ++st) {
        const int sm1 = s - 1;
        {
            int i  = tid;                 // 512 butterflies
            int q  = i & sm1;
            int ps = i - q;

            float2 a0 = src[SKW(i)];
            float2 a1 = src[SKW(i + 512)];
            float2 a2 = src[SKW(i + 1024)];
            float2 a3 = src[SKW(i + 1536)];

            float2 E0, E1, E2, E3, O0, O1, O2, O3;
            if (padded && st == 0) {      // inputs >= 2048 are zero
                float2 m2 = make_float2(sgn * a2.y, -sgn * a2.x);
                float2 m3 = make_float2(sgn * a3.y, -sgn * a3.x);
                E0 = cadd(a0, a2); E2 = csub(a0, a2);
                E1 = cadd(a0, m2); E3 = csub(a0, m2);
                O0 = cadd(a1, a3); O2 = csub(a1, a3);
                O1 = cadd(a1, m3); O3 = csub(a1, m3);
            } else {
                float2 a4 = src[SKW(i + 2048)];
                float2 a5 = src[SKW(i + 2560)];
                float2 a6 = src[SKW(i + 3072)];
                float2 a7 = src[SKW(i + 3584)];
                float2 t0 = cadd(a0, a4), t1 = csub(a0, a4);
                float2 t2 = cadd(a2, a6), t3 = csub(a2, a6);
                float2 m3e = make_float2(sgn * t3.y, -sgn * t3.x);
                E0 = cadd(t0, t2); E2 = csub(t0, t2);
                E1 = cadd(t1, m3e); E3 = csub(t1, m3e);
                float2 u0 = cadd(a1, a5), u1 = csub(a1, a5);
                float2 u2 = cadd(a3, a7), u3 = csub(a3, a7);
                float2 m3o = make_float2(sgn * u3.y, -sgn * u3.x);
                O0 = cadd(u0, u2); O2 = csub(u0, u2);
                O1 = cadd(u1, m3o); O3 = csub(u1, m3o);
            }

            float2 W1O = make_float2(RH * (O1.x + sgn * O1.y), RH * (O1.y - sgn * O1.x));
            float2 W2O = make_float2(sgn * O2.y, -sgn * O2.x);
            float2 W3O = make_float2(RH * (sgn * O3.y - O3.x), -RH * (O3.y + sgn * O3.x));

            float2 X0 = cadd(E0, O0),  X4 = csub(E0, O0);
            float2 X1 = cadd(E1, W1O), X5 = csub(E1, W1O);
            float2 X2 = cadd(E2, W2O), X6 = csub(E2, W2O);
            float2 X3 = cadd(E3, W3O), X7 = csub(E3, W3O);

            float2 w1 = tw[ps];     w1.y *= sgn;
            float2 w2 = tw[2 * ps]; w2.y *= sgn;
            float2 w4 = tw[4 * ps]; w4.y *= sgn;
            float2 w3 = cmul(w1, w2);

            int o = q + 8 * ps;
            dst[SKW(o)]         = X0;
            dst[SKW(o + s)]     = cmul(X1, w1);
            dst[SKW(o + 2 * s)] = cmul(X2, w2);
            dst[SKW(o + 3 * s)] = cmul(X3, w3);
            if (!(halfOut && st == 3)) {   // inverse: only outputs < 2048 needed
                float2 w5 = cmul(w1, w4);
                float2 w6 = cmul(w2, w4);
                float2 w7 = cmul(w3, w4);
                dst[SKW(o + 4 * s)] = cmul(X4, w4);
                dst[SKW(o + 5 * s)] = cmul(X5, w5);
                dst[SKW(o + 6 * s)] = cmul(X6, w6);
                dst[SKW(o + 7 * s)] = cmul(X7, w7);
            }
        }
        __syncthreads();
        float2* t = src; src = dst; dst = t;
        s <<= 3;
    }
    return src;   // result buffer after 4 swaps
}

// ---------------- kernel spectra: two real channels per 8192 FFT -------------------
#define SMEM_FFTK ((2 * SKWN + NHALF) * (int)sizeof(float2))
__global__ void __launch_bounds__(NTHR) fftk_kernel(const float* __restrict__ k_ssm)
{
    float2* buf0 = (float2*)s4_smem;
    float2* buf1 = buf0 + SKWN;
    float2* tws  = buf1 + SKWN;
    const int h0 = blockIdx.x * 2;
    const int tid = threadIdx.x;

    for (int i = tid; i < NHALF; i += NTHR) tws[i] = g_tw[i];
    const float* k0 = k_ssm + (size_t)h0 * L_SEQ;
    const float* k1 = k0 + L_SEQ;
    for (int l = tid; l < L_SEQ; l += NTHR)
        buf0[SKW(l)] = make_float2(k0[l], k1[l]);
    __syncthreads();

    float2* F = fft8192_r8(buf0, buf1, tws, 1.0f, tid, true, false);

    float2* H0 = g_Hf + (size_t)h0 * NFFT;
    float2* H1 = H0 + NFFT;
    for (int k = tid; k < NFFT; k += NTHR) {
        float2 Fk = F[SKW(k)];
        float2 Fn = F[SKW((NFFT - k) & (NFFT - 1))];
        H0[k] = make_float2(0.5f * (Fk.x + Fn.x), 0.5f * (Fk.y - Fn.y));
        float2 Bd = make_float2(Fk.x - Fn.x, Fk.y + Fn.y);
        H1[k] = make_float2(0.5f * Bd.y, -0.5f * Bd.x);
    }
}

// ------- fused conv: conv4+SiLU -> rFFT(4096) conv -> D_skip -> *SiLU(z) -------
// One CTA per (b,h). x real (8192 padded) handled via half-size complex FFT:
// z[n] = x[2n] + i x[2n+1]; Z=FFT4096(z); unpack X[k], X[k+4096]; Y=X*H; repack
// Wspec = Ye + i*Yo; w = IFFT4096(Wspec); y[2n]=Re w[n], y[2n+1]=Im w[n].
#define SMEM_CONV4 ((2 * SKWN4 + 2048 + 2048) * (int)sizeof(float2))
__global__ void __launch_bounds__(512, 2) convfft_kernel(const float* __restrict__ conv_w,
                                                         const float* __restrict__ conv_b,
                                                         const float* __restrict__ D_skip)
{
    float2* buf0 = (float2*)s4_smem;
    float2* buf1 = buf0 + SKWN4;
    float2* tws  = buf1 + SKWN4;      // 2048 entries: e^{-2pi i x/4096}
    float2* xs   = tws + 2048;        // conv+silu outputs, pairs (x[2n], x[2n+1])

    const int bh  = blockIdx.x;
    const int h   = bh >> 1;          // adjacent CTAs share channel -> Hrow L2-hot
    const int b   = bh & 1;
    const int tid = threadIdx.x;

    for (int j = tid; j < 2048; j += 512) tws[j] = g_tw[2 * j];

    const float w0 = conv_w[h * 4 + 0];
    const float w1 = conv_w[h * 4 + 1];
    const float w2 = conv_w[h * 4 + 2];
    const float w3 = conv_w[h * 4 + 3];
    const float cb = conv_b[h];

    const float* gx = g_xz + ((size_t)(b * EDIM) + h) * L_SEQ;

    // conv + silu, packed pairs; zero upper half of buffer
    for (int n = tid; n < 2048; n += 512) {
        int l0 = 2 * n, l1 = 2 * n + 1;
        float a0 = fmaf(w3, gx[l0], cb);
        float a1 = fmaf(w3, gx[l1], cb);
        a1 = fmaf(w2, gx[l0], a1);
        if (l0 >= 1) { a0 = fmaf(w2, gx[l0 - 1], a0); a1 = fmaf(w1, gx[l0 - 1], a1); }
        if (l0 >= 2) { a0 = fmaf(w1, gx[l0 - 2], a0); a1 = fmaf(w0, gx[l0 - 2], a1); }
        if (l0 >= 3) { a0 = fmaf(w0, gx[l0 - 3], a0); }
        float v0 = a0 / (1.0f + expf(-a0));
        float v1 = a1 / (1.0f + expf(-a1));
        float2 v = make_float2(v0, v1);
        xs[n]        = v;
        buf0[SKW(n)] = v;
    }
    for (int n = 2048 + tid; n < 4096; n += 512)
        buf0[SKW(n)] = make_float2(0.f, 0.f);
    __syncthreads();

    float2* Z = fft4096_r8(buf0, buf1, tws, 1.0f, tid, true, false);   // -> buf0
    float2* W = (Z == buf0) ? buf1 : buf0;

    // pointwise: unpack -> *H -> repack
    const float2* __restrict__ Hrow = g_Hf + (size_t)h * NFFT;
    for (int k = tid; k < 4096; k += 512) {
        float2 Zk = Z[SKW(k)];
        float2 Zc = Z[SKW((4096 - k) & 4095)];
        Zc.y = -Zc.y;                                  // conj
        float2 t  = g_tw[k];                           // e^{-2pi i k/8192}
        float2 Ze = make_float2(0.5f * (Zk.x + Zc.x), 0.5f * (Zk.y + Zc.y));
        float2 d  = make_float2(Zk.x - Zc.x, Zk.y - Zc.y);
        float2 Zo = make_float2(0.5f * d.y, -0.5f * d.x);   // -i*d/2
        float2 tZo = cmul(t, Zo);
        float2 Xa = cadd(Ze, tZo);                     // X[k]
        float2 Xb = csub(Ze, tZo);                     // X[k+4096]
        float2 Ya = cmul(Xa, Hrow[k]);
        float2 Yb = cmul(Xb, Hrow[k + 4096]);
        float2 Ye = make_float2(0.5f * (Ya.x + Yb.x), 0.5f * (Ya.y + Yb.y));
        float2 u  = make_float2(0.5f * (Ya.x - Yb.x), 0.5f * (Ya.y - Yb.y));
        float2 tc = make_float2(t.x, -t.y);            // e^{+2pi i k/8192}
        float2 Yo = cmul(tc, u);
        W[SKW(k)] = make_float2(Ye.x - Yo.y, Ye.y + Yo.x);   // Ye + i*Yo
    }
    __syncthreads();

    float2* other = (W == buf0) ? buf1 : buf0;
    float2* R = fft4096_r8(W, other, tws, -1.0f, tid, false, true);    // first 2048 valid

    const float dsk = D_skip[h];
    const float* gz = g_xz + ((size_t)(b * EDIM) + DINNER + h) * L_SEQ;
    float*       gy = g_y  + ((size_t)(b * DINNER) + h) * L_SEQ;
    const float invn = 1.0f / 4096.0f;
    for (int n = tid; n < 2048; n += 512) {
        float2 wv = R[SKW(n)];
        float2 xv = xs[n];
        float2 zv = *(const float2*)(gz + 2 * n);
        float y0 = fmaf(wv.x, invn, dsk * xv.x);
        float y1 = fmaf(wv.y, invn, dsk * xv.y);
        float s0 = zv.x / (1.0f + expf(-zv.x));
        float s1 = zv.y / (1.0f + expf(-zv.y));
        *(float2*)(gy + 2 * n) = make_float2(y0 * s0, y1 * s1);
    }
}

// ---------------- launch ----------------
extern "C" void kernel_launch(void* const* d_in, const int* in_sizes, int n_in,
                              void* d_out, int out_size)
{
    (void)in_sizes; (void)n_in; (void)out_size;
    const float* hs     = (const float*)d_in[0];
    const float* W_in   = (const float*)d_in[1];
    const float* conv_w = (const float*)d_in[2];
    const float* conv_b = (const float*)d_in[3];
    const float* k_ssm  = (const float*)d_in[4];
    const float* D_skip = (const float*)d_in[5];
    const float* W_out  = (const float*)d_in[6];
    float* out = (float*)d_out;

    cudaFuncSetAttribute(fftk_kernel,    cudaFuncAttributeMaxDynamicSharedMemorySize, SMEM_FFTK);
    cudaFuncSetAttribute(convfft_kernel, cudaFuncAttributeMaxDynamicSharedMemorySize, SMEM_CONV4);

    float*  xz   = nullptr; cudaGetSymbolAddress((void**)&xz, g_xz);
    __half* hsH  = nullptr; cudaGetSymbolAddress((void**)&hsH, g_hsH);
    __half* winH = nullptr; cudaGetSymbolAddress((void**)&winH, g_WinH);
    __half* woutH= nullptr; cudaGetSymbolAddress((void**)&woutH, g_WoutH);
    __half* ytH  = nullptr; cudaGetSymbolAddress((void**)&ytH, g_ytH);

    twiddle_kernel<<<NHALF / 512, 512>>>();

    {
        long long n4;
        n4 = (long long)BATCH * L_SEQ * DMODEL / 4;
        f2h_kernel<<<(unsigned)((n4 + 255) / 256), 256>>>(hs, hsH, n4);
        n4 = (long long)EDIM * DMODEL / 4;
        f2h_kernel<<<(unsigned)((n4 + 255) / 256), 256>>>(W_in, winH, n4);
        n4 = (long long)DMODEL * DINNER / 4;
        f2h_kernel<<<(unsigned)((n4 + 255) / 256), 256>>>(W_out, woutH, n4);
    }

    // GEMM1: xz[b][e][l] = sum_d W_in[e][d] * hs[b][l][d]
    gemm_mma_h<<<dim3(L_SEQ / 128, EDIM / 128, BATCH), 256>>>(
        winH, hsH, xz, DMODEL, DMODEL, L_SEQ, DMODEL,
        0LL, (long long)L_SEQ * DMODEL, (long long)EDIM * L_SEQ);

    fftk_kernel<<<DINNER / 2, NTHR, SMEM_FFTK>>>(k_ssm);
    convfft_kernel<<<BATCH * DINNER, 512, SMEM_CONV4>>>(conv_w, conv_b, D_skip);

    transpose_kernel<<<dim3(L_SEQ / 32, DINNER / 32, BATCH), dim3(32, 8)>>>();

    // GEMM2: out[b][l][d] = sum_h y_t[b][l][h] * W_out[d][h]
    gemm_mma_h<<<dim3(DMODEL / 128, L_SEQ / 128, BATCH), 256>>>(
        ytH, woutH, out, DINNER, DINNER, DMODEL, DINNER,
        (long long)L_SEQ * DINNER, 0LL, (long long)L_SEQ * DMODEL);
}

// round 12
// speedup vs baseline: 5.1440x; 1.0376x over previous
#include <cuda_runtime.h>
#include <cuda_fp16.h>
#include <math.h>
#include <stdint.h>

// ---------------- problem constants ----------------
#define L_SEQ   4096
#define DMODEL  1024
#define DINNER  2048
#define EDIM    (2*DINNER)   // 4096
#define BATCH   2
#define NFFT    8192
#define NHALF   (NFFT/2)     // 4096
#define NTHR    1024         // fftk block size

#define SKW(i)  ((i) + ((i) >> 4))
#define SKWN    (NFFT + NFFT/16)       // 8704 float2 (8192 buffer, fftk)
#define SKWN4   (4096 + 4096/16)       // 4352 float2 (4096 buffer, convfft)

extern __shared__ char s4_smem[];

// ---------------- scratch (device globals; allocation-free launch) ----------------
__device__ float  g_xz [(unsigned long long)BATCH * EDIM * L_SEQ];     // [b][e][l]
__device__ __half g_yH [(unsigned long long)BATCH * DINNER * L_SEQ];   // [b][h][l] fp16
__device__ __half g_hsH [(unsigned long long)BATCH * L_SEQ * DMODEL];
__device__ __half g_WinH[(unsigned long long)EDIM * DMODEL];
__device__ __half g_WoutH[(unsigned long long)DMODEL * DINNER];
__device__ float2 g_Hf[(unsigned long long)DINNER * NFFT];
__device__ float2 g_tw[NHALF];                                         // e^{-2pi i k/8192}

// ---------------- f32 -> f16 bulk convert ----------------
__global__ void __launch_bounds__(256) f2h_kernel(const float* __restrict__ src,
                                                  __half* __restrict__ dst,
                                                  long long n4)
{
    long long i = ((long long)blockIdx.x * 256 + threadIdx.x);
    if (i < n4) {
        float4 v = *(const float4*)(src + i * 4);
        __half2 h01 = __floats2half2_rn(v.x, v.y);
        __half2 h23 = __floats2half2_rn(v.z, v.w);
        *(uint2*)(dst + i * 4) = make_uint2(*(uint32_t*)&h01, *(uint32_t*)&h23);
    }
}

// ---------------- mma / ldmatrix / cp.async helpers ----------------
__device__ __forceinline__ void mma_f16(float* d, const uint32_t* a, const uint32_t* b) {
    asm volatile(
        "mma.sync.aligned.m16n8k16.row.col.f32.f16.f16.f32 "
        "{%0,%1,%2,%3}, {%4,%5,%6,%7}, {%8,%9}, {%0,%1,%2,%3};"
        : "+f"(d[0]), "+f"(d[1]), "+f"(d[2]), "+f"(d[3])
        : "r"(a[0]), "r"(a[1]), "r"(a[2]), "r"(a[3]), "r"(b[0]), "r"(b[1]));
}
__device__ __forceinline__ void ldsm_x4(uint32_t* r, uint32_t saddr) {
    asm volatile("ldmatrix.sync.aligned.m8n8.x4.shared.b16 {%0,%1,%2,%3}, [%4];"
                 : "=r"(r[0]), "=r"(r[1]), "=r"(r[2]), "=r"(r[3]) : "r"(saddr));
}
__device__ __forceinline__ void ldsm_x4_t(uint32_t* r, uint32_t saddr) {
    asm volatile("ldmatrix.sync.aligned.m8n8.x4.trans.shared.b16 {%0,%1,%2,%3}, [%4];"
                 : "=r"(r[0]), "=r"(r[1]), "=r"(r[2]), "=r"(r[3]) : "r"(saddr));
}
__device__ __forceinline__ void cp16(uint32_t saddr, const void* gaddr) {
    asm volatile("cp.async.cg.shared.global [%0], [%1], 16;" :: "r"(saddr), "l"(gaddr));
}
__device__ __forceinline__ void cp_commit() {
    asm volatile("cp.async.commit_group;" ::: "memory");
}
template<int N>
__device__ __forceinline__ void cp_wait() {
    asm volatile("cp.async.wait_group %0;" :: "n"(N) : "memory");
}

#define GPITCH 40
#define APITCH 136
#define STAGES 3

// ================= GEMM1 (NT): C[m][n] = sum_k A[m][k] * B[n][k], fp16 in, f32 out ==
__global__ void __launch_bounds__(256) gemm_mma_h(const __half* __restrict__ A,
                                                  const __half* __restrict__ B,
                                                  float* __restrict__ C,
                                                  int lda, int ldb, int ldc, int K,
                                                  long long aBatch, long long bBatch,
                                                  long long cBatch)
{
    __shared__ __half As[STAGES][128][GPITCH];
    __shared__ __half Bs[STAGES][128][GPITCH];

    A += (size_t)blockIdx.z * aBatch;
    B += (size_t)blockIdx.z * bBatch;
    C += (size_t)blockIdx.z * cBatch;
    const int m0 = blockIdx.y * 128;
    const int n0 = blockIdx.x * 128;

    const int tid  = threadIdx.x;
    const int wid  = tid >> 5;
    const int lane = tid & 31;
    const int wm   = (wid >> 2) * 64;
    const int wn   = (wid & 3) * 32;
    const int g    = lane >> 2;
    const int t    = lane & 3;

    const int aRow = (lane & 15);
    const int aCol = (lane >> 4) * 8;
    const int bRow = (lane & 7) + ((lane >> 4) << 3);
    const int bCol = ((lane >> 3) & 1) * 8;

    float acc[4][4][4];
    #pragma unroll
    for (int mi = 0; mi < 4; ++mi)
        #pragma unroll
        for (int ni = 0; ni < 4; ++ni)
            #pragma unroll
            for (int r = 0; r < 4; ++r) acc[mi][ni][r] = 0.f;

    const int nch = K >> 5;

    auto issue = [&](int st, int c) {
        const int k0 = c << 5;
        #pragma unroll
        for (int p = 0; p < 2; ++p) {
            int lin = p * 256 + tid;
            int row = lin >> 2;
            int grp = lin & 3;
            uint32_t sa = (uint32_t)__cvta_generic_to_shared(&As[st][row][grp * 8]);
            cp16(sa, A + (size_t)(m0 + row) * lda + k0 + grp * 8);
            uint32_t sb = (uint32_t)__cvta_generic_to_shared(&Bs[st][row][grp * 8]);
            cp16(sb, B + (size_t)(n0 + row) * ldb + k0 + grp * 8);
        }
        cp_commit();
    };

    issue(0, 0);
    issue(1, 1);

    for (int c = 0; c < nch; ++c) {
        cp_wait<STAGES - 2>();
        __syncthreads();

        if (c + STAGES - 1 < nch)
            issue((c + STAGES - 1) % STAGES, c + STAGES - 1);

        const int buf = c % STAGES;
        #pragma unroll
        for (int ks = 0; ks < 2; ++ks) {
            const int kk = ks * 16;
            uint32_t af[4][4], bf[4][4];
            #pragma unroll
            for (int mi = 0; mi < 4; ++mi) {
                uint32_t sa = (uint32_t)__cvta_generic_to_shared(
                    &As[buf][wm + mi * 16 + aRow][kk + aCol]);
                ldsm_x4(af[mi], sa);
            }
            #pragma unroll
            for (int np = 0; np < 2; ++np) {
                uint32_t sb = (uint32_t)__cvta_generic_to_shared(
                    &Bs[buf][wn + np * 16 + bRow][kk + bCol]);
                ldsm_x4(bf[np * 2], sb);
                bf[np * 2 + 1][0] = bf[np * 2][2];
                bf[np * 2 + 1][1] = bf[np * 2][3];
            }
            #pragma unroll
            for (int mi = 0; mi < 4; ++mi)
                #pragma unroll
                for (int ni = 0; ni < 4; ++ni)
                    mma_f16(acc[mi][ni], af[mi], bf[ni]);
        }
    }

    #pragma unroll
    for (int mi = 0; mi < 4; ++mi) {
        int r0 = m0 + wm + mi * 16 + g;
        #pragma unroll
        for (int ni = 0; ni < 4; ++ni) {
            int cc = n0 + wn + ni * 8 + t * 2;
            *(float2*)(C + (size_t)r0 * ldc + cc)       = make_float2(acc[mi][ni][0], acc[mi][ni][1]);
            *(float2*)(C + (size_t)(r0 + 8) * ldc + cc) = make_float2(acc[mi][ni][2], acc[mi][ni][3]);
        }
    }
}

// ================= GEMM2 (NN): out[b][l][d] = sum_h y[b][h][l] * W_out[d][h] =======
// A-source y is [k=h][m=l] (K-major): A tiles 32(k) x 128(m), fragments via
// ldmatrix.trans. B = W_out [n=d][k=h] K-contiguous, as in GEMM1. Epilogue coalesced.
__global__ void __launch_bounds__(256) gemm2_nn(const __half* __restrict__ Y,
                                                const __half* __restrict__ W,
                                                float* __restrict__ C)
{
    __shared__ __half As[STAGES][32][APITCH];    // [k][m], pitch 136 halves
    __shared__ __half Bs[STAGES][128][GPITCH];

    Y += (size_t)blockIdx.z * DINNER * L_SEQ;
    C += (size_t)blockIdx.z * L_SEQ * DMODEL;
    const int m0 = blockIdx.y * 128;             // l
    const int n0 = blockIdx.x * 128;             // d

    const int tid  = threadIdx.x;
    const int wid  = tid >> 5;
    const int lane = tid & 31;
    const int wm   = (wid >> 2) * 64;
    const int wn   = (wid & 3) * 32;
    const int g    = lane >> 2;
    const int t    = lane & 3;

    // trans-A lane mapping: a0=(m0-7,k0-7) a1=(m8-15,k0-7) a2=(m0-7,k8-15) a3=(m8-15,k8-15)
    const int kOff = (lane & 7) + ((lane >> 4) << 3);
    const int mOff = ((lane >> 3) & 1) * 8;
    const int bRow = (lane & 7) + ((lane >> 4) << 3);
    const int bCol = ((lane >> 3) & 1) * 8;

    float acc[4][4][4];
    #pragma unroll
    for (int mi = 0; mi < 4; ++mi)
        #pragma unroll
        for (int ni = 0; ni < 4; ++ni)
            #pragma unroll
            for (int r = 0; r < 4; ++r) acc[mi][ni][r] = 0.f;

    const int nch = DINNER >> 5;

    auto issue = [&](int st, int c) {
        const int k0 = c << 5;
        #pragma unroll
        for (int p = 0; p < 2; ++p) {
            int lin = p * 256 + tid;             // 0..511
            // A: 32 rows x 16 groups of 16B
            int arow = lin >> 4;
            int agrp = lin & 15;
            uint32_t sa = (uint32_t)__cvta_generic_to_shared(&As[st][arow][agrp * 8]);
            cp16(sa, Y + (size_t)(k0 + arow) * L_SEQ + m0 + agrp * 8);
            // B: 128 rows x 4 groups of 16B
            int brow = lin >> 2;
            int bgrp = lin & 3;
            uint32_t sb = (uint32_t)__cvta_generic_to_shared(&Bs[st][brow][bgrp * 8]);
            cp16(sb, W + (size_t)(n0 + brow) * DINNER + k0 + bgrp * 8);
        }
        cp_commit();
    };

    issue(0, 0);
    issue(1, 1);

    for (int c = 0; c < nch; ++c) {
        cp_wait<STAGES - 2>();
        __syncthreads();

        if (c + STAGES - 1 < nch)
            issue((c + STAGES - 1) % STAGES, c + STAGES - 1);

        const int buf = c % STAGES;
        #pragma unroll
        for (int ks = 0; ks < 2; ++ks) {
            const int kk = ks * 16;
            uint32_t af[4][4], bf[4][4];
            #pragma unroll
            for (int mi = 0; mi < 4; ++mi) {
                uint32_t sa = (uint32_t)__cvta_generic_to_shared(
                    &As[buf][kk + kOff][wm + mi * 16 + mOff]);
                ldsm_x4_t(af[mi], sa);
            }
            #pragma unroll
            for (int np = 0; np < 2; ++np) {
                uint32_t sb = (uint32_t)__cvta_generic_to_shared(
                    &Bs[buf][wn + np * 16 + bRow][kk + bCol]);
                ldsm_x4(bf[np * 2], sb);
                bf[np * 2 + 1][0] = bf[np * 2][2];
                bf[np * 2 + 1][1] = bf[np * 2][3];
            }
            #pragma unroll
            for (int mi = 0; mi < 4; ++mi)
                #pragma unroll
                for (int ni = 0; ni < 4; ++ni)
                    mma_f16(acc[mi][ni], af[mi], bf[ni]);
        }
    }

    #pragma unroll
    for (int mi = 0; mi < 4; ++mi) {
        int r0 = m0 + wm + mi * 16 + g;
        #pragma unroll
        for (int ni = 0; ni < 4; ++ni) {
            int cc = n0 + wn + ni * 8 + t * 2;
            *(float2*)(C + (size_t)r0 * DMODEL + cc)       = make_float2(acc[mi][ni][0], acc[mi][ni][1]);
            *(float2*)(C + (size_t)(r0 + 8) * DMODEL + cc) = make_float2(acc[mi][ni][2], acc[mi][ni][3]);
        }
    }
}

// ---------------- twiddle table ----------------
__global__ void twiddle_kernel() {
    int k = blockIdx.x * blockDim.x + threadIdx.x;
    if (k < NHALF) {
        float s, c;
        sincospif(2.0f * (float)k / (float)NFFT, &s, &c);
        g_tw[k] = make_float2(c, -s);
    }
}

// ---------------- complex helpers ----------------
__device__ __forceinline__ float2 cmul(float2 a, float2 b) {
    return make_float2(fmaf(a.x, b.x, -a.y * b.y), fmaf(a.x, b.y, a.y * b.x));
}
__device__ __forceinline__ float2 cadd(float2 a, float2 b) { return make_float2(a.x + b.x, a.y + b.y); }
__device__ __forceinline__ float2 csub(float2 a, float2 b) { return make_float2(a.x - b.x, a.y - b.y); }

// ---------------- FFT 8192: Stockham radix-8 (4 stages) + radix-2, 1024 thr --------
__device__ float2* fft8192_r8(float2* src, float2* dst, const float2* __restrict__ tw,
                              float sgn, int tid, bool padded, bool halfOut)
{
    const float RH = 0.70710678118654752f;

    int s = 1;
    #pragma unroll 1
    for (int st = 0; st < 4; ++st) {
        const int sm1 = s - 1;
        {
            int i  = tid;
            int q  = i & sm1;
            int ps = i - q;

            float2 a0 = src[SKW(i)];
            float2 a1 = src[SKW(i + 1024)];
            float2 a2 = src[SKW(i + 2048)];
            float2 a3 = src[SKW(i + 3072)];

            float2 E0, E1, E2, E3, O0, O1, O2, O3;
            if (padded && st == 0) {
                float2 m2 = make_float2(sgn * a2.y, -sgn * a2.x);
                float2 m3 = make_float2(sgn * a3.y, -sgn * a3.x);
                E0 = cadd(a0, a2); E2 = csub(a0, a2);
                E1 = cadd(a0, m2); E3 = csub(a0, m2);
                O0 = cadd(a1, a3); O2 = csub(a1, a3);
                O1 = cadd(a1, m3); O3 = csub(a1, m3);
            } else {
                float2 a4 = src[SKW(i + 4096)];
                float2 a5 = src[SKW(i + 5120)];
                float2 a6 = src[SKW(i + 6144)];
                float2 a7 = src[SKW(i + 7168)];
                float2 t0 = cadd(a0, a4), t1 = csub(a0, a4);
                float2 t2 = cadd(a2, a6), t3 = csub(a2, a6);
                float2 m3e = make_float2(sgn * t3.y, -sgn * t3.x);
                E0 = cadd(t0, t2); E2 = csub(t0, t2);
                E1 = cadd(t1, m3e); E3 = csub(t1, m3e);
                float2 u0 = cadd(a1, a5), u1 = csub(a1, a5);
                float2 u2 = cadd(a3, a7), u3 = csub(a3, a7);
                float2 m3o = make_float2(sgn * u3.y, -sgn * u3.x);
                O0 = cadd(u0, u2); O2 = csub(u0, u2);
                O1 = cadd(u1, m3o); O3 = csub(u1, m3o);
            }

            float2 W1O = make_float2(RH * (O1.x + sgn * O1.y), RH * (O1.y - sgn * O1.x));
            float2 W2O = make_float2(sgn * O2.y, -sgn * O2.x);
            float2 W3O = make_float2(RH * (sgn * O3.y - O3.x), -RH * (O3.y + sgn * O3.x));

            float2 X0 = cadd(E0, O0),  X4 = csub(E0, O0);
            float2 X1 = cadd(E1, W1O), X5 = csub(E1, W1O);
            float2 X2 = cadd(E2, W2O), X6 = csub(E2, W2O);
            float2 X3 = cadd(E3, W3O), X7 = csub(E3, W3O);

            float2 w1 = tw[ps];     w1.y *= sgn;
            float2 w2 = tw[2 * ps]; w2.y *= sgn;
            float2 w4 = tw[4 * ps]; w4.y *= sgn;
            float2 w3 = cmul(w1, w2);
            float2 w5 = cmul(w1, w4);
            float2 w6 = cmul(w2, w4);
            float2 w7 = cmul(w3, w4);

            int o = q + 8 * ps;
            dst[SKW(o)]         = X0;
            dst[SKW(o + s)]     = cmul(X1, w1);
            dst[SKW(o + 2 * s)] = cmul(X2, w2);
            dst[SKW(o + 3 * s)] = cmul(X3, w3);
            dst[SKW(o + 4 * s)] = cmul(X4, w4);
            dst[SKW(o + 5 * s)] = cmul(X5, w5);
            dst[SKW(o + 6 * s)] = cmul(X6, w6);
            dst[SKW(o + 7 * s)] = cmul(X7, w7);
        }
        __syncthreads();
        float2* t = src; src = dst; dst = t;
        s <<= 3;
    }

    #pragma unroll
    for (int r = 0; r < 4; ++r) {
        int i = tid + r * NTHR;
        float2 a = src[SKW(i)];
        float2 b = src[SKW(i + NHALF)];
        dst[SKW(i)] = cadd(a, b);
        if (!halfOut) dst[SKW(i + NHALF)] = csub(a, b);
    }
    __syncthreads();
    return dst;
}

// ---------------- FFT 4096: Stockham radix-8, 4 stages, 512 thr --------------------
__device__ float2* fft4096_r8(float2* src, float2* dst, const float2* __restrict__ tw,
                              float sgn, int tid, bool padded, bool halfOut)
{
    const float RH = 0.70710678118654752f;

    int s = 1;
    #pragma unroll 1
    for (int st = 0; st < 4; ++st) {
        const int sm1 = s - 1;
        {
            int i  = tid;
            int q  = i & sm1;
            int ps = i - q;

            float2 a0 = src[SKW(i)];
            float2 a1 = src[SKW(i + 512)];
            float2 a2 = src[SKW(i + 1024)];
            float2 a3 = src[SKW(i + 1536)];

            float2 E0, E1, E2, E3, O0, O1, O2, O3;
            if (padded && st == 0) {
                float2 m2 = make_float2(sgn * a2.y, -sgn * a2.x);
                float2 m3 = make_float2(sgn * a3.y, -sgn * a3.x);
                E0 = cadd(a0, a2); E2 = csub(a0, a2);
                E1 = cadd(a0, m2); E3 = csub(a0, m2);
                O0 = cadd(a1, a3); O2 = csub(a1, a3);
                O1 = cadd(a1, m3); O3 = csub(a1, m3);
            } else {
                float2 a4 = src[SKW(i + 2048)];
                float2 a5 = src[SKW(i + 2560)];
                float2 a6 = src[SKW(i + 3072)];
                float2 a7 = src[SKW(i + 3584)];
                float2 t0 = cadd(a0, a4), t1 = csub(a0, a4);
                float2 t2 = cadd(a2, a6), t3 = csub(a2, a6);
                float2 m3e = make_float2(sgn * t3.y, -sgn * t3.x);
                E0 = cadd(t0, t2); E2 = csub(t0, t2);
                E1 = cadd(t1, m3e); E3 = csub(t1, m3e);
                float2 u0 = cadd(a1, a5), u1 = csub(a1, a5);
                float2 u2 = cadd(a3, a7), u3 = csub(a3, a7);
                float2 m3o = make_float2(sgn * u3.y, -sgn * u3.x);
                O0 = cadd(u0, u2); O2 = csub(u0, u2);
                O1 = cadd(u1, m3o); O3 = csub(u1, m3o);
            }

            float2 W1O = make_float2(RH * (O1.x + sgn * O1.y), RH * (O1.y - sgn * O1.x));
            float2 W2O = make_float2(sgn * O2.y, -sgn * O2.x);
            float2 W3O = make_float2(RH * (sgn * O3.y - O3.x), -RH * (O3.y + sgn * O3.x));

            float2 X0 = cadd(E0, O0),  X4 = csub(E0, O0);
            float2 X1 = cadd(E1, W1O), X5 = csub(E1, W1O);
            float2 X2 = cadd(E2, W2O), X6 = csub(E2, W2O);
            float2 X3 = cadd(E3, W3O), X7 = csub(E3, W3O);

            float2 w1 = tw[ps];     w1.y *= sgn;
            float2 w2 = tw[2 * ps]; w2.y *= sgn;
            float2 w4 = tw[4 * ps]; w4.y *= sgn;
            float2 w3 = cmul(w1, w2);

            int o = q + 8 * ps;
            dst[SKW(o)]         = X0;
            dst[SKW(o + s)]     = cmul(X1, w1);
            dst[SKW(o + 2 * s)] = cmul(X2, w2);
            dst[SKW(o + 3 * s)] = cmul(X3, w3);
            if (!(halfOut && st == 3)) {
                float2 w5 = cmul(w1, w4);
                float2 w6 = cmul(w2, w4);
                float2 w7 = cmul(w3, w4);
                dst[SKW(o + 4 * s)] = cmul(X4, w4);
                dst[SKW(o + 5 * s)] = cmul(X5, w5);
                dst[SKW(o + 6 * s)] = cmul(X6, w6);
                dst[SKW(o + 7 * s)] = cmul(X7, w7);
            }
        }
        __syncthreads();
        float2* t = src; src = dst; dst = t;
        s <<= 3;
    }
    return src;
}

// ---------------- kernel spectra: two real channels per 8192 FFT -------------------
#define SMEM_FFTK ((2 * SKWN + NHALF) * (int)sizeof(float2))
__global__ void __launch_bounds__(NTHR) fftk_kernel(const float* __restrict__ k_ssm)
{
    float2* buf0 = (float2*)s4_smem;
    float2* buf1 = buf0 + SKWN;
    float2* tws  = buf1 + SKWN;
    const int h0 = blockIdx.x * 2;
    const int tid = threadIdx.x;

    for (int i = tid; i < NHALF; i += NTHR) tws[i] = g_tw[i];
    const float* k0 = k_ssm + (size_t)h0 * L_SEQ;
    const float* k1 = k0 + L_SEQ;
    for (int l = tid; l < L_SEQ; l += NTHR)
        buf0[SKW(l)] = make_float2(k0[l], k1[l]);
    __syncthreads();

    float2* F = fft8192_r8(buf0, buf1, tws, 1.0f, tid, true, false);

    float2* H0 = g_Hf + (size_t)h0 * NFFT;
    float2* H1 = H0 + NFFT;
    for (int k = tid; k < NFFT; k += NTHR) {
        float2 Fk = F[SKW(k)];
        float2 Fn = F[SKW((NFFT - k) & (NFFT - 1))];
        H0[k] = make_float2(0.5f * (Fk.x + Fn.x), 0.5f * (Fk.y - Fn.y));
        float2 Bd = make_float2(Fk.x - Fn.x, Fk.y + Fn.y);
        H1[k] = make_float2(0.5f * Bd.y, -0.5f * Bd.x);
    }
}

// ------- fused conv: conv4+SiLU -> rFFT(4096) conv -> D_skip -> *SiLU(z) -------
// One CTA per (b,h); output y written fp16 [b][h][l].
#define SMEM_CONV4 ((2 * SKWN4 + 2048 + 2048) * (int)sizeof(float2))
__global__ void __launch_bounds__(512, 2) convfft_kernel(const float* __restrict__ conv_w,
                                                         const float* __restrict__ conv_b,
                                                         const float* __restrict__ D_skip)
{
    float2* buf0 = (float2*)s4_smem;
    float2* buf1 = buf0 + SKWN4;
    float2* tws  = buf1 + SKWN4;      // 2048 entries: e^{-2pi i x/4096}
    float2* xs   = tws + 2048;

    const int bh  = blockIdx.x;
    const int h   = bh >> 1;
    const int b   = bh & 1;
    const int tid = threadIdx.x;

    for (int j = tid; j < 2048; j += 512) tws[j] = g_tw[2 * j];

    const float w0 = conv_w[h * 4 + 0];
    const float w1 = conv_w[h * 4 + 1];
    const float w2 = conv_w[h * 4 + 2];
    const float w3 = conv_w[h * 4 + 3];
    const float cb = conv_b[h];

    const float* gx = g_xz + ((size_t)(b * EDIM) + h) * L_SEQ;

    for (int n = tid; n < 2048; n += 512) {
        int l0 = 2 * n, l1 = 2 * n + 1;
        float a0 = fmaf(w3, gx[l0], cb);
        float a1 = fmaf(w3, gx[l1], cb);
        a1 = fmaf(w2, gx[l0], a1);
        if (l0 >= 1) { a0 = fmaf(w2, gx[l0 - 1], a0); a1 = fmaf(w1, gx[l0 - 1], a1); }
        if (l0 >= 2) { a0 = fmaf(w1, gx[l0 - 2], a0); a1 = fmaf(w0, gx[l0 - 2], a1); }
        if (l0 >= 3) { a0 = fmaf(w0, gx[l0 - 3], a0); }
        float v0 = a0 / (1.0f + expf(-a0));
        float v1 = a1 / (1.0f + expf(-a1));
        float2 v = make_float2(v0, v1);
        xs[n]        = v;
        buf0[SKW(n)] = v;
    }
    for (int n = 2048 + tid; n < 4096; n += 512)
        buf0[SKW(n)] = make_float2(0.f, 0.f);
    __syncthreads();

    float2* Z = fft4096_r8(buf0, buf1, tws, 1.0f, tid, true, false);
    float2* W = (Z == buf0) ? buf1 : buf0;

    const float2* __restrict__ Hrow = g_Hf + (size_t)h * NFFT;
    for (int k = tid; k < 4096; k += 512) {
        float2 Zk = Z[SKW(k)];
        float2 Zc = Z[SKW((4096 - k) & 4095)];
        Zc.y = -Zc.y;
        float2 t  = g_tw[k];
        float2 Ze = make_float2(0.5f * (Zk.x + Zc.x), 0.5f * (Zk.y + Zc.y));
        float2 d  = make_float2(Zk.x - Zc.x, Zk.y - Zc.y);
        float2 Zo = make_float2(0.5f * d.y, -0.5f * d.x);
        float2 tZo = cmul(t, Zo);
        float2 Xa = cadd(Ze, tZo);
        float2 Xb = csub(Ze, tZo);
        float2 Ya = cmul(Xa, Hrow[k]);
        float2 Yb = cmul(Xb, Hrow[k + 4096]);
        float2 Ye = make_float2(0.5f * (Ya.x + Yb.x), 0.5f * (Ya.y + Yb.y));
        float2 u  = make_float2(0.5f * (Ya.x - Yb.x), 0.5f * (Ya.y - Yb.y));
        float2 tc = make_float2(t.x, -t.y);
        float2 Yo = cmul(tc, u);
        W[SKW(k)] = make_float2(Ye.x - Yo.y, Ye.y + Yo.x);
    }
    __syncthreads();

    float2* other = (W == buf0) ? buf1 : buf0;
    float2* R = fft4096_r8(W, other, tws, -1.0f, tid, false, true);

    const float dsk = D_skip[h];
    const float* gz = g_xz + ((size_t)(b * EDIM) + DINNER + h) * L_SEQ;
    __half*      gy = g_yH + ((size_t)(b * DINNER) + h) * L_SEQ;
    const float invn = 1.0f / 4096.0f;
    for (int n = tid; n < 2048; n += 512) {
        float2 wv = R[SKW(n)];
        float2 xv = xs[n];
        float2 zv = *(const float2*)(gz + 2 * n);
        float y0 = fmaf(wv.x, invn, dsk * xv.x);
        float y1 = fmaf(wv.y, invn, dsk * xv.y);
        float s0 = zv.x / (1.0f + expf(-zv.x));
        float s1 = zv.y / (1.0f + expf(-zv.y));
        *(__half2*)(gy + 2 * n) = __floats2half2_rn(y0 * s0, y1 * s1);
    }
}

// ---------------- launch ----------------
extern "C" void kernel_launch(void* const* d_in, const int* in_sizes, int n_in,
                              void* d_out, int out_size)
{
    (void)in_sizes; (void)n_in; (void)out_size;
    const float* hs     = (const float*)d_in[0];
    const float* W_in   = (const float*)d_in[1];
    const float* conv_w = (const float*)d_in[2];
    const float* conv_b = (const float*)d_in[3];
    const float* k_ssm  = (const float*)d_in[4];
    const float* D_skip = (const float*)d_in[5];
    const float* W_out  = (const float*)d_in[6];
    float* out = (float*)d_out;

    cudaFuncSetAttribute(fftk_kernel,    cudaFuncAttributeMaxDynamicSharedMemorySize, SMEM_FFTK);
    cudaFuncSetAttribute(convfft_kernel, cudaFuncAttributeMaxDynamicSharedMemorySize, SMEM_CONV4);

    float*  xz   = nullptr; cudaGetSymbolAddress((void**)&xz, g_xz);
    __half* hsH  = nullptr; cudaGetSymbolAddress((void**)&hsH, g_hsH);
    __half* winH = nullptr; cudaGetSymbolAddress((void**)&winH, g_WinH);
    __half* woutH= nullptr; cudaGetSymbolAddress((void**)&woutH, g_WoutH);
    __half* yH   = nullptr; cudaGetSymbolAddress((void**)&yH, g_yH);

    twiddle_kernel<<<NHALF / 512, 512>>>();

    {
        long long n4;
        n4 = (long long)BATCH * L_SEQ * DMODEL / 4;
        f2h_kernel<<<(unsigned)((n4 + 255) / 256), 256>>>(hs, hsH, n4);
        n4 = (long long)EDIM * DMODEL / 4;
        f2h_kernel<<<(unsigned)((n4 + 255) / 256), 256>>>(W_in, winH, n4);
        n4 = (long long)DMODEL * DINNER / 4;
        f2h_kernel<<<(unsigned)((n4 + 255) / 256), 256>>>(W_out, woutH, n4);
    }

    // GEMM1: xz[b][e][l] = sum_d W_in[e][d] * hs[b][l][d]
    gemm_mma_h<<<dim3(L_SEQ / 128, EDIM / 128, BATCH), 256>>>(
        winH, hsH, xz, DMODEL, DMODEL, L_SEQ, DMODEL,
        0LL, (long long)L_SEQ * DMODEL, (long long)EDIM * L_SEQ);

    fftk_kernel<<<DINNER / 2, NTHR, SMEM_FFTK>>>(k_ssm);
    convfft_kernel<<<BATCH * DINNER, 512, SMEM_CONV4>>>(conv_w, conv_b, D_skip);

    // GEMM2 (NN): out[b][l][d] = sum_h y[b][h][l] * W_out[d][h]
    gemm2_nn<<<dim3(DMODEL / 128, L_SEQ / 128, BATCH), 256>>>(yH, woutH, out);
}

// round 13
// speedup vs baseline: 5.2887x; 1.0281x over previous
#include <cuda_runtime.h>
#include <cuda_fp16.h>
#include <math.h>
#include <stdint.h>

// ---------------- problem constants ----------------
#define L_SEQ   4096
#define DMODEL  1024
#define DINNER  2048
#define EDIM    (2*DINNER)   // 4096
#define BATCH   2
#define NFFT    8192
#define NHALF   (NFFT/2)     // 4096
#define NTHR    1024         // fftk block size

#define SKW(i)  ((i) + ((i) >> 4))
#define SKWN    (NFFT + NFFT/16)       // 8704 float2 (8192 buffer, fftk)
#define SKWN4   (4096 + 4096/16)       // 4352 float2 (4096 buffer, convfft)

extern __shared__ char s4_smem[];

// ---------------- scratch (device globals; allocation-free launch) ----------------
__device__ __half g_xzH[(unsigned long long)BATCH * EDIM * L_SEQ];     // [b][e][l] fp16
__device__ __half g_yH [(unsigned long long)BATCH * DINNER * L_SEQ];   // [b][h][l] fp16
__device__ __half g_hsH [(unsigned long long)BATCH * L_SEQ * DMODEL];
__device__ __half g_WinH[(unsigned long long)EDIM * DMODEL];
__device__ __half g_WoutH[(unsigned long long)DMODEL * DINNER];
__device__ float2 g_Hf[(unsigned long long)DINNER * NFFT];
__device__ float2 g_tw[NHALF];                                         // e^{-2pi i k/8192}

// ---------------- f32 -> f16 bulk convert ----------------
__global__ void __launch_bounds__(256) f2h_kernel(const float* __restrict__ src,
                                                  __half* __restrict__ dst,
                                                  long long n4)
{
    long long i = ((long long)blockIdx.x * 256 + threadIdx.x);
    if (i < n4) {
        float4 v = *(const float4*)(src + i * 4);
        __half2 h01 = __floats2half2_rn(v.x, v.y);
        __half2 h23 = __floats2half2_rn(v.z, v.w);
        *(uint2*)(dst + i * 4) = make_uint2(*(uint32_t*)&h01, *(uint32_t*)&h23);
    }
}

// ---------------- mma / ldmatrix / cp.async helpers ----------------
__device__ __forceinline__ void mma_f16(float* d, const uint32_t* a, const uint32_t* b) {
    asm volatile(
        "mma.sync.aligned.m16n8k16.row.col.f32.f16.f16.f32 "
        "{%0,%1,%2,%3}, {%4,%5,%6,%7}, {%8,%9}, {%0,%1,%2,%3};"
        : "+f"(d[0]), "+f"(d[1]), "+f"(d[2]), "+f"(d[3])
        : "r"(a[0]), "r"(a[1]), "r"(a[2]), "r"(a[3]), "r"(b[0]), "r"(b[1]));
}
__device__ __forceinline__ void ldsm_x4(uint32_t* r, uint32_t saddr) {
    asm volatile("ldmatrix.sync.aligned.m8n8.x4.shared.b16 {%0,%1,%2,%3}, [%4];"
                 : "=r"(r[0]), "=r"(r[1]), "=r"(r[2]), "=r"(r[3]) : "r"(saddr));
}
__device__ __forceinline__ void ldsm_x4_t(uint32_t* r, uint32_t saddr) {
    asm volatile("ldmatrix.sync.aligned.m8n8.x4.trans.shared.b16 {%0,%1,%2,%3}, [%4];"
                 : "=r"(r[0]), "=r"(r[1]), "=r"(r[2]), "=r"(r[3]) : "r"(saddr));
}
__device__ __forceinline__ void cp16(uint32_t saddr, const void* gaddr) {
    asm volatile("cp.async.cg.shared.global [%0], [%1], 16;" :: "r"(saddr), "l"(gaddr));
}
__device__ __forceinline__ void cp_commit() {
    asm volatile("cp.async.commit_group;" ::: "memory");
}
template<int N>
__device__ __forceinline__ void cp_wait() {
    asm volatile("cp.async.wait_group %0;" :: "n"(N) : "memory");
}

#define GPITCH 40
#define APITCH 136
#define STAGES 3

// ============ GEMM1 (NT): xzH[m][n] = sum_k W_in[m][k] * hs[n][k], fp16 out ========
__global__ void __launch_bounds__(256) gemm_mma_h(const __half* __restrict__ A,
                                                  const __half* __restrict__ B,
                                                  __half* __restrict__ C,
                                                  int lda, int ldb, int ldc, int K,
                                                  long long aBatch, long long bBatch,
                                                  long long cBatch)
{
    __shared__ __half As[STAGES][128][GPITCH];
    __shared__ __half Bs[STAGES][128][GPITCH];

    A += (size_t)blockIdx.z * aBatch;
    B += (size_t)blockIdx.z * bBatch;
    C += (size_t)blockIdx.z * cBatch;
    const int m0 = blockIdx.y * 128;
    const int n0 = blockIdx.x * 128;

    const int tid  = threadIdx.x;
    const int wid  = tid >> 5;
    const int lane = tid & 31;
    const int wm   = (wid >> 2) * 64;
    const int wn   = (wid & 3) * 32;
    const int g    = lane >> 2;
    const int t    = lane & 3;

    const int aRow = (lane & 15);
    const int aCol = (lane >> 4) * 8;
    const int bRow = (lane & 7) + ((lane >> 4) << 3);
    const int bCol = ((lane >> 3) & 1) * 8;

    float acc[4][4][4];
    #pragma unroll
    for (int mi = 0; mi < 4; ++mi)
        #pragma unroll
        for (int ni = 0; ni < 4; ++ni)
            #pragma unroll
            for (int r = 0; r < 4; ++r) acc[mi][ni][r] = 0.f;

    const int nch = K >> 5;

    auto issue = [&](int st, int c) {
        const int k0 = c << 5;
        #pragma unroll
        for (int p = 0; p < 2; ++p) {
            int lin = p * 256 + tid;
            int row = lin >> 2;
            int grp = lin & 3;
            uint32_t sa = (uint32_t)__cvta_generic_to_shared(&As[st][row][grp * 8]);
            cp16(sa, A + (size_t)(m0 + row) * lda + k0 + grp * 8);
            uint32_t sb = (uint32_t)__cvta_generic_to_shared(&Bs[st][row][grp * 8]);
            cp16(sb, B + (size_t)(n0 + row) * ldb + k0 + grp * 8);
        }
        cp_commit();
    };

    issue(0, 0);
    issue(1, 1);

    for (int c = 0; c < nch; ++c) {
        cp_wait<STAGES - 2>();
        __syncthreads();

        if (c + STAGES - 1 < nch)
            issue((c + STAGES - 1) % STAGES, c + STAGES - 1);

        const int buf = c % STAGES;
        #pragma unroll
        for (int ks = 0; ks < 2; ++ks) {
            const int kk = ks * 16;
            uint32_t af[4][4], bf[4][4];
            #pragma unroll
            for (int mi = 0; mi < 4; ++mi) {
                uint32_t sa = (uint32_t)__cvta_generic_to_shared(
                    &As[buf][wm + mi * 16 + aRow][kk + aCol]);
                ldsm_x4(af[mi], sa);
            }
            #pragma unroll
            for (int np = 0; np < 2; ++np) {
                uint32_t sb = (uint32_t)__cvta_generic_to_shared(
                    &Bs[buf][wn + np * 16 + bRow][kk + bCol]);
                ldsm_x4(bf[np * 2], sb);
                bf[np * 2 + 1][0] = bf[np * 2][2];
                bf[np * 2 + 1][1] = bf[np * 2][3];
            }
            #pragma unroll
            for (int mi = 0; mi < 4; ++mi)
                #pragma unroll
                for (int ni = 0; ni < 4; ++ni)
                    mma_f16(acc[mi][ni], af[mi], bf[ni]);
        }
    }

    #pragma unroll
    for (int mi = 0; mi < 4; ++mi) {
        int r0 = m0 + wm + mi * 16 + g;
        #pragma unroll
        for (int ni = 0; ni < 4; ++ni) {
            int cc = n0 + wn + ni * 8 + t * 2;
            *(__half2*)(C + (size_t)r0 * ldc + cc) =
                __floats2half2_rn(acc[mi][ni][0], acc[mi][ni][1]);
            *(__half2*)(C + (size_t)(r0 + 8) * ldc + cc) =
                __floats2half2_rn(acc[mi][ni][2], acc[mi][ni][3]);
        }
    }
}

// ================= GEMM2 (NN): out[b][l][d] = sum_h y[b][h][l] * W_out[d][h] =======
__global__ void __launch_bounds__(256) gemm2_nn(const __half* __restrict__ Y,
                                                const __half* __restrict__ W,
                                                float* __restrict__ C)
{
    __shared__ __half As[STAGES][32][APITCH];
    __shared__ __half Bs[STAGES][128][GPITCH];

    Y += (size_t)blockIdx.z * DINNER * L_SEQ;
    C += (size_t)blockIdx.z * L_SEQ * DMODEL;
    const int m0 = blockIdx.y * 128;
    const int n0 = blockIdx.x * 128;

    const int tid  = threadIdx.x;
    const int wid  = tid >> 5;
    const int lane = tid & 31;
    const int wm   = (wid >> 2) * 64;
    const int wn   = (wid & 3) * 32;
    const int g    = lane >> 2;
    const int t    = lane & 3;

    const int kOff = (lane & 7) + ((lane >> 4) << 3);
    const int mOff = ((lane >> 3) & 1) * 8;
    const int bRow = (lane & 7) + ((lane >> 4) << 3);
    const int bCol = ((lane >> 3) & 1) * 8;

    float acc[4][4][4];
    #pragma unroll
    for (int mi = 0; mi < 4; ++mi)
        #pragma unroll
        for (int ni = 0; ni < 4; ++ni)
            #pragma unroll
            for (int r = 0; r < 4; ++r) acc[mi][ni][r] = 0.f;

    const int nch = DINNER >> 5;

    auto issue = [&](int st, int c) {
        const int k0 = c << 5;
        #pragma unroll
        for (int p = 0; p < 2; ++p) {
            int lin = p * 256 + tid;
            int arow = lin >> 4;
            int agrp = lin & 15;
            uint32_t sa = (uint32_t)__cvta_generic_to_shared(&As[st][arow][agrp * 8]);
            cp16(sa, Y + (size_t)(k0 + arow) * L_SEQ + m0 + agrp * 8);
            int brow = lin >> 2;
            int bgrp = lin & 3;
            uint32_t sb = (uint32_t)__cvta_generic_to_shared(&Bs[st][brow][bgrp * 8]);
            cp16(sb, W + (size_t)(n0 + brow) * DINNER + k0 + bgrp * 8);
        }
        cp_commit();
    };

    issue(0, 0);
    issue(1, 1);

    for (int c = 0; c < nch; ++c) {
        cp_wait<STAGES - 2>();
        __syncthreads();

        if (c + STAGES - 1 < nch)
            issue((c + STAGES - 1) % STAGES, c + STAGES - 1);

        const int buf = c % STAGES;
        #pragma unroll
        for (int ks = 0; ks < 2; ++ks) {
            const int kk = ks * 16;
            uint32_t af[4][4], bf[4][4];
            #pragma unroll
            for (int mi = 0; mi < 4; ++mi) {
                uint32_t sa = (uint32_t)__cvta_generic_to_shared(
                    &As[buf][kk + kOff][wm + mi * 16 + mOff]);
                ldsm_x4_t(af[mi], sa);
            }
            #pragma unroll
            for (int np = 0; np < 2; ++np) {
                uint32_t sb = (uint32_t)__cvta_generic_to_shared(
                    &Bs[buf][wn + np * 16 + bRow][kk + bCol]);
                ldsm_x4(bf[np * 2], sb);
                bf[np * 2 + 1][0] = bf[np * 2][2];
                bf[np * 2 + 1][1] = bf[np * 2][3];
            }
            #pragma unroll
            for (int mi = 0; mi < 4; ++mi)
                #pragma unroll
                for (int ni = 0; ni < 4; ++ni)
                    mma_f16(acc[mi][ni], af[mi], bf[ni]);
        }
    }

    #pragma unroll
    for (int mi = 0; mi < 4; ++mi) {
        int r0 = m0 + wm + mi * 16 + g;
        #pragma unroll
        for (int ni = 0; ni < 4; ++ni) {
            int cc = n0 + wn + ni * 8 + t * 2;
            *(float2*)(C + (size_t)r0 * DMODEL + cc)       = make_float2(acc[mi][ni][0], acc[mi][ni][1]);
            *(float2*)(C + (size_t)(r0 + 8) * DMODEL + cc) = make_float2(acc[mi][ni][2], acc[mi][ni][3]);
        }
    }
}

// ---------------- twiddle table ----------------
__global__ void twiddle_kernel() {
    int k = blockIdx.x * blockDim.x + threadIdx.x;
    if (k < NHALF) {
        float s, c;
        sincospif(2.0f * (float)k / (float)NFFT, &s, &c);
        g_tw[k] = make_float2(c, -s);
    }
}

// ---------------- complex helpers ----------------
__device__ __forceinline__ float2 cmul(float2 a, float2 b) {
    return make_float2(fmaf(a.x, b.x, -a.y * b.y), fmaf(a.x, b.y, a.y * b.x));
}
__device__ __forceinline__ float2 cadd(float2 a, float2 b) { return make_float2(a.x + b.x, a.y + b.y); }
__device__ __forceinline__ float2 csub(float2 a, float2 b) { return make_float2(a.x - b.x, a.y - b.y); }

// ---------------- FFT 8192: Stockham radix-8 (4 stages) + radix-2, 1024 thr --------
__device__ float2* fft8192_r8(float2* src, float2* dst, const float2* __restrict__ tw,
                              float sgn, int tid, bool padded, bool halfOut)
{
    const float RH = 0.70710678118654752f;

    int s = 1;
    #pragma unroll 1
    for (int st = 0; st < 4; ++st) {
        const int sm1 = s - 1;
        {
            int i  = tid;
            int q  = i & sm1;
            int ps = i - q;

            float2 a0 = src[SKW(i)];
            float2 a1 = src[SKW(i + 1024)];
            float2 a2 = src[SKW(i + 2048)];
            float2 a3 = src[SKW(i + 3072)];

            float2 E0, E1, E2, E3, O0, O1, O2, O3;
            if (padded && st == 0) {
                float2 m2 = make_float2(sgn * a2.y, -sgn * a2.x);
                float2 m3 = make_float2(sgn * a3.y, -sgn * a3.x);
                E0 = cadd(a0, a2); E2 = csub(a0, a2);
                E1 = cadd(a0, m2); E3 = csub(a0, m2);
                O0 = cadd(a1, a3); O2 = csub(a1, a3);
                O1 = cadd(a1, m3); O3 = csub(a1, m3);
            } else {
                float2 a4 = src[SKW(i + 4096)];
                float2 a5 = src[SKW(i + 5120)];
                float2 a6 = src[SKW(i + 6144)];
                float2 a7 = src[SKW(i + 7168)];
                float2 t0 = cadd(a0, a4), t1 = csub(a0, a4);
                float2 t2 = cadd(a2, a6), t3 = csub(a2, a6);
                float2 m3e = make_float2(sgn * t3.y, -sgn * t3.x);
                E0 = cadd(t0, t2); E2 = csub(t0, t2);
                E1 = cadd(t1, m3e); E3 = csub(t1, m3e);
                float2 u0 = cadd(a1, a5), u1 = csub(a1, a5);
                float2 u2 = cadd(a3, a7), u3 = csub(a3, a7);
                float2 m3o = make_float2(sgn * u3.y, -sgn * u3.x);
                O0 = cadd(u0, u2); O2 = csub(u0, u2);
                O1 = cadd(u1, m3o); O3 = csub(u1, m3o);
            }

            float2 W1O = make_float2(RH * (O1.x + sgn * O1.y), RH * (O1.y - sgn * O1.x));
            float2 W2O = make_float2(sgn * O2.y, -sgn * O2.x);
            float2 W3O = make_float2(RH * (sgn * O3.y - O3.x), -RH * (O3.y + sgn * O3.x));

            float2 X0 = cadd(E0, O0),  X4 = csub(E0, O0);
            float2 X1 = cadd(E1, W1O), X5 = csub(E1, W1O);
            float2 X2 = cadd(E2, W2O), X6 = csub(E2, W2O);
            float2 X3 = cadd(E3, W3O), X7 = csub(E3, W3O);

            float2 w1 = tw[ps];     w1.y *= sgn;
            float2 w2 = tw[2 * ps]; w2.y *= sgn;
            float2 w4 = tw[4 * ps]; w4.y *= sgn;
            float2 w3 = cmul(w1, w2);
            float2 w5 = cmul(w1, w4);
            float2 w6 = cmul(w2, w4);
            float2 w7 = cmul(w3, w4);

            int o = q + 8 * ps;
            dst[SKW(o)]         = X0;
            dst[SKW(o + s)]     = cmul(X1, w1);
            dst[SKW(o + 2 * s)] = cmul(X2, w2);
            dst[SKW(o + 3 * s)] = cmul(X3, w3);
            dst[SKW(o + 4 * s)] = cmul(X4, w4);
            dst[SKW(o + 5 * s)] = cmul(X5, w5);
            dst[SKW(o + 6 * s)] = cmul(X6, w6);
            dst[SKW(o + 7 * s)] = cmul(X7, w7);
        }
        __syncthreads();
        float2* t = src; src = dst; dst = t;
        s <<= 3;
    }

    #pragma unroll
    for (int r = 0; r < 4; ++r) {
        int i = tid + r * NTHR;
        float2 a = src[SKW(i)];
        float2 b = src[SKW(i + NHALF)];
        dst[SKW(i)] = cadd(a, b);
        if (!halfOut) dst[SKW(i + NHALF)] = csub(a, b);
    }
    __syncthreads();
    return dst;
}

// ---------------- FFT 4096: Stockham radix-8, 4 stages, 512 thr --------------------
__device__ float2* fft4096_r8(float2* src, float2* dst, const float2* __restrict__ tw,
                              float sgn, int tid, bool padded, bool halfOut)
{
    const float RH = 0.70710678118654752f;

    int s = 1;
    #pragma unroll 1
    for (int st = 0; st < 4; ++st) {
        const int sm1 = s - 1;
        {
            int i  = tid;
            int q  = i & sm1;
            int ps = i - q;

            float2 a0 = src[SKW(i)];
            float2 a1 = src[SKW(i + 512)];
            float2 a2 = src[SKW(i + 1024)];
            float2 a3 = src[SKW(i + 1536)];

            float2 E0, E1, E2, E3, O0, O1, O2, O3;
            if (padded && st == 0) {
                float2 m2 = make_float2(sgn * a2.y, -sgn * a2.x);
                float2 m3 = make_float2(sgn * a3.y, -sgn * a3.x);
                E0 = cadd(a0, a2); E2 = csub(a0, a2);
                E1 = cadd(a0, m2); E3 = csub(a0, m2);
                O0 = cadd(a1, a3); O2 = csub(a1, a3);
                O1 = cadd(a1, m3); O3 = csub(a1, m3);
            } else {
                float2 a4 = src[SKW(i + 2048)];
                float2 a5 = src[SKW(i + 2560)];
                float2 a6 = src[SKW(i + 3072)];
                float2 a7 = src[SKW(i + 3584)];
                float2 t0 = cadd(a0, a4), t1 = csub(a0, a4);
                float2 t2 = cadd(a2, a6), t3 = csub(a2, a6);
                float2 m3e = make_float2(sgn * t3.y, -sgn * t3.x);
                E0 = cadd(t0, t2); E2 = csub(t0, t2);
                E1 = cadd(t1, m3e); E3 = csub(t1, m3e);
                float2 u0 = cadd(a1, a5), u1 = csub(a1, a5);
                float2 u2 = cadd(a3, a7), u3 = csub(a3, a7);
                float2 m3o = make_float2(sgn * u3.y, -sgn * u3.x);
                O0 = cadd(u0, u2); O2 = csub(u0, u2);
                O1 = cadd(u1, m3o); O3 = csub(u1, m3o);
            }

            float2 W1O = make_float2(RH * (O1.x + sgn * O1.y), RH * (O1.y - sgn * O1.x));
            float2 W2O = make_float2(sgn * O2.y, -sgn * O2.x);
            float2 W3O = make_float2(RH * (sgn * O3.y - O3.x), -RH * (O3.y + sgn * O3.x));

            float2 X0 = cadd(E0, O0),  X4 = csub(E0, O0);
            float2 X1 = cadd(E1, W1O), X5 = csub(E1, W1O);
            float2 X2 = cadd(E2, W2O), X6 = csub(E2, W2O);
            float2 X3 = cadd(E3, W3O), X7 = csub(E3, W3O);

            float2 w1 = tw[ps];     w1.y *= sgn;
            float2 w2 = tw[2 * ps]; w2.y *= sgn;
            float2 w4 = tw[4 * ps]; w4.y *= sgn;
            float2 w3 = cmul(w1, w2);

            int o = q + 8 * ps;
            dst[SKW(o)]         = X0;
            dst[SKW(o + s)]     = cmul(X1, w1);
            dst[SKW(o + 2 * s)] = cmul(X2, w2);
            dst[SKW(o + 3 * s)] = cmul(X3, w3);
            if (!(halfOut && st == 3)) {
                float2 w5 = cmul(w1, w4);
                float2 w6 = cmul(w2, w4);
                float2 w7 = cmul(w3, w4);
                dst[SKW(o + 4 * s)] = cmul(X4, w4);
                dst[SKW(o + 5 * s)] = cmul(X5, w5);
                dst[SKW(o + 6 * s)] = cmul(X6, w6);
                dst[SKW(o + 7 * s)] = cmul(X7, w7);
            }
        }
        __syncthreads();
        float2* t = src; src = dst; dst = t;
        s <<= 3;
    }
    return src;
}

// ---------------- kernel spectra: two real channels per 8192 FFT -------------------
#define SMEM_FFTK ((2 * SKWN + NHALF) * (int)sizeof(float2))
__global__ void __launch_bounds__(NTHR) fftk_kernel(const float* __restrict__ k_ssm)
{
    float2* buf0 = (float2*)s4_smem;
    float2* buf1 = buf0 + SKWN;
    float2* tws  = buf1 + SKWN;
    const int h0 = blockIdx.x * 2;
    const int tid = threadIdx.x;

    for (int i = tid; i < NHALF; i += NTHR) tws[i] = g_tw[i];
    const float* k0 = k_ssm + (size_t)h0 * L_SEQ;
    const float* k1 = k0 + L_SEQ;
    for (int l = tid; l < L_SEQ; l += NTHR)
        buf0[SKW(l)] = make_float2(k0[l], k1[l]);
    __syncthreads();

    float2* F = fft8192_r8(buf0, buf1, tws, 1.0f, tid, true, false);

    float2* H0 = g_Hf + (size_t)h0 * NFFT;
    float2* H1 = H0 + NFFT;
    for (int k = tid; k < NFFT; k += NTHR) {
        float2 Fk = F[SKW(k)];
        float2 Fn = F[SKW((NFFT - k) & (NFFT - 1))];
        H0[k] = make_float2(0.5f * (Fk.x + Fn.x), 0.5f * (Fk.y - Fn.y));
        float2 Bd = make_float2(Fk.x - Fn.x, Fk.y + Fn.y);
        H1[k] = make_float2(0.5f * Bd.y, -0.5f * Bd.x);
    }
}

// ------- fused conv: conv4+SiLU -> rFFT(4096) conv -> D_skip -> *SiLU(z) -------
#define SMEM_CONV4 ((2 * SKWN4 + 2048 + 2048) * (int)sizeof(float2))
__global__ void __launch_bounds__(512, 2) convfft_kernel(const float* __restrict__ conv_w,
                                                         const float* __restrict__ conv_b,
                                                         const float* __restrict__ D_skip)
{
    float2* buf0 = (float2*)s4_smem;
    float2* buf1 = buf0 + SKWN4;
    float2* tws  = buf1 + SKWN4;      // 2048 entries: e^{-2pi i x/4096}
    float2* xs   = tws + 2048;

    const int bh  = blockIdx.x;
    const int h   = bh >> 1;
    const int b   = bh & 1;
    const int tid = threadIdx.x;

    for (int j = tid; j < 2048; j += 512) tws[j] = g_tw[2 * j];

    const float w0 = conv_w[h * 4 + 0];
    const float w1 = conv_w[h * 4 + 1];
    const float w2 = conv_w[h * 4 + 2];
    const float w3 = conv_w[h * 4 + 3];
    const float cb = conv_b[h];

    const __half* gx = g_xzH + ((size_t)(b * EDIM) + h) * L_SEQ;

    for (int n = tid; n < 2048; n += 512) {
        int l0 = 2 * n;
        float x0  = __half2float(gx[l0]);
        float x1  = __half2float(gx[l0 + 1]);
        float a0 = fmaf(w3, x0, cb);
        float a1 = fmaf(w3, x1, cb);
        a1 = fmaf(w2, x0, a1);
        if (l0 >= 1) {
            float xm1 = __half2float(gx[l0 - 1]);
            a0 = fmaf(w2, xm1, a0); a1 = fmaf(w1, xm1, a1);
        }
        if (l0 >= 2) {
            float xm2 = __half2float(gx[l0 - 2]);
            a0 = fmaf(w1, xm2, a0); a1 = fmaf(w0, xm2, a1);
        }
        if (l0 >= 3) {
            float xm3 = __half2float(gx[l0 - 3]);
            a0 = fmaf(w0, xm3, a0);
        }
        float v0 = a0 / (1.0f + expf(-a0));
        float v1 = a1 / (1.0f + expf(-a1));
        float2 v = make_float2(v0, v1);
        xs[n]        = v;
        buf0[SKW(n)] = v;
    }
    for (int n = 2048 + tid; n < 4096; n += 512)
        buf0[SKW(n)] = make_float2(0.f, 0.f);
    __syncthreads();

    float2* Z = fft4096_r8(buf0, buf1, tws, 1.0f, tid, true, false);
    float2* W = (Z == buf0) ? buf1 : buf0;

    const float2* __restrict__ Hrow = g_Hf + (size_t)h * NFFT;
    for (int k = tid; k < 4096; k += 512) {
        float2 Zk = Z[SKW(k)];
        float2 Zc = Z[SKW((4096 - k) & 4095)];
        Zc.y = -Zc.y;
        float2 t  = g_tw[k];
        float2 Ze = make_float2(0.5f * (Zk.x + Zc.x), 0.5f * (Zk.y + Zc.y));
        float2 d  = make_float2(Zk.x - Zc.x, Zk.y - Zc.y);
        float2 Zo = make_float2(0.5f * d.y, -0.5f * d.x);
        float2 tZo = cmul(t, Zo);
        float2 Xa = cadd(Ze, tZo);
        float2 Xb = csub(Ze, tZo);
        float2 Ya = cmul(Xa, Hrow[k]);
        float2 Yb = cmul(Xb, Hrow[k + 4096]);
        float2 Ye = make_float2(0.5f * (Ya.x + Yb.x), 0.5f * (Ya.y + Yb.y));
        float2 u  = make_float2(0.5f * (Ya.x - Yb.x), 0.5f * (Ya.y - Yb.y));
        float2 tc = make_float2(t.x, -t.y);
        float2 Yo = cmul(tc, u);
        W[SKW(k)] = make_float2(Ye.x - Yo.y, Ye.y + Yo.x);
    }
    __syncthreads();

    float2* other = (W == buf0) ? buf1 : buf0;
    float2* R = fft4096_r8(W, other, tws, -1.0f, tid, false, true);

    const float dsk = D_skip[h];
    const __half* gz = g_xzH + ((size_t)(b * EDIM) + DINNER + h) * L_SEQ;
    __half*       gy = g_yH + ((size_t)(b * DINNER) + h) * L_SEQ;
    const float invn = 1.0f / 4096.0f;
    for (int n = tid; n < 2048; n += 512) {
        float2 wv = R[SKW(n)];
        float2 xv = xs[n];
        __half2 zh = *(const __half2*)(gz + 2 * n);
        float z0 = __half2float(__low2half(zh));
        float z1 = __half2float(__high2half(zh));
        float y0 = fmaf(wv.x, invn, dsk * xv.x);
        float y1 = fmaf(wv.y, invn, dsk * xv.y);
        float s0 = z0 / (1.0f + expf(-z0));
        float s1 = z1 / (1.0f + expf(-z1));
        *(__half2*)(gy + 2 * n) = __floats2half2_rn(y0 * s0, y1 * s1);
    }
}

// ---------------- launch ----------------
extern "C" void kernel_launch(void* const* d_in, const int* in_sizes, int n_in,
                              void* d_out, int out_size)
{
    (void)in_sizes; (void)n_in; (void)out_size;
    const float* hs     = (const float*)d_in[0];
    const float* W_in   = (const float*)d_in[1];
    const float* conv_w = (const float*)d_in[2];
    const float* conv_b = (const float*)d_in[3];
    const float* k_ssm  = (const float*)d_in[4];
    const float* D_skip = (const float*)d_in[5];
    const float* W_out  = (const float*)d_in[6];
    float* out = (float*)d_out;

    cudaFuncSetAttribute(fftk_kernel,    cudaFuncAttributeMaxDynamicSharedMemorySize, SMEM_FFTK);
    cudaFuncSetAttribute(convfft_kernel, cudaFuncAttributeMaxDynamicSharedMemorySize, SMEM_CONV4);

    __half* xzH  = nullptr; cudaGetSymbolAddress((void**)&xzH, g_xzH);
    __half* hsH  = nullptr; cudaGetSymbolAddress((void**)&hsH, g_hsH);
    __half* winH = nullptr; cudaGetSymbolAddress((void**)&winH, g_WinH);
    __half* woutH= nullptr; cudaGetSymbolAddress((void**)&woutH, g_WoutH);
    __half* yH   = nullptr; cudaGetSymbolAddress((void**)&yH, g_yH);

    // fork a side stream for the fftk chain (independent of GEMM1)
    cudaStream_t sB;
    cudaStreamCreateWithFlags(&sB, cudaStreamNonBlocking);
    cudaEvent_t eFork, eJoin;
    cudaEventCreateWithFlags(&eFork, cudaEventDisableTiming);
    cudaEventCreateWithFlags(&eJoin, cudaEventDisableTiming);

    cudaEventRecord(eFork, 0);
    cudaStreamWaitEvent(sB, eFork, 0);

    // ---- stream B: twiddle -> f2h(W_out) -> fftk ----
    twiddle_kernel<<<NHALF / 512, 512, 0, sB>>>();
    {
        long long n4 = (long long)DMODEL * DINNER / 4;
        f2h_kernel<<<(unsigned)((n4 + 255) / 256), 256, 0, sB>>>(W_out, woutH, n4);
    }
    fftk_kernel<<<DINNER / 2, NTHR, SMEM_FFTK, sB>>>(k_ssm);
    cudaEventRecord(eJoin, sB);

    // ---- main stream: f2h(hs, W_in) -> GEMM1 ----
    {
        long long n4;
        n4 = (long long)BATCH * L_SEQ * DMODEL / 4;
        f2h_kernel<<<(unsigned)((n4 + 255) / 256), 256>>>(hs, hsH, n4);
        n4 = (long long)EDIM * DMODEL / 4;
        f2h_kernel<<<(unsigned)((n4 + 255) / 256), 256>>>(W_in, winH, n4);
    }
    gemm_mma_h<<<dim3(L_SEQ / 128, EDIM / 128, BATCH), 256>>>(
        winH, hsH, xzH, DMODEL, DMODEL, L_SEQ, DMODEL,
        0LL, (long long)L_SEQ * DMODEL, (long long)EDIM * L_SEQ);

    // join, then the dependent tail
    cudaStreamWaitEvent(0, eJoin, 0);
    convfft_kernel<<<BATCH * DINNER, 512, SMEM_CONV4>>>(conv_w, conv_b, D_skip);
    gemm2_nn<<<dim3(DMODEL / 128, L_SEQ / 128, BATCH), 256>>>(yH, woutH, out);
    // stream/events intentionally not destroyed: they may be referenced by an
    // in-progress stream capture; a handful of handles leak per call (host-side
    // only, no device memory).
}